// round 1
// baseline (speedup 1.0000x reference)
#include <cuda_runtime.h>
#include <math.h>

#define BATCH 4
#define CCH 128
#define HDIM 256
#define WDIM 256
#define NTOK 64
#define NPIX (BATCH*HDIM*WDIM)   /* 262144 */
#define NWIN (NPIX/NTOK)         /* 4096 */

// ---------------- device scratch (allocation-free rule: __device__ globals) ----------------
__device__ float g_Wc[CCH*CCH];
__device__ float g_bc[CCH];
__device__ float g_y [NPIX*CCH];   // LN1 out, window-token layout [win][tok][c]
__device__ float g_att[NPIX*CCH];  // remsa out, window-token layout
__device__ float g_x1[NPIX*CCH];   // x + merged attn, channels-last pixel layout
__device__ float g_y2[NPIX*CCH];   // LN2 out, channels-last
__device__ float g_z [NPIX*CCH];   // lpw out, channels-last

// ---------------- shared GEMM helpers ----------------
// W staged as interleaved float4: sWt[kk*129 + c] = row c, k-chunk kk (k = kk*4..kk*4+3)
__device__ __forceinline__ void stage_w(const float* __restrict__ W, int rowstride4,
                                        float4* __restrict__ sWt, int tid) {
    const float4* W4 = (const float4*)W;
    #pragma unroll
    for (int idx = tid; idx < 4096; idx += 256) {
        int c = idx >> 5, kk = idx & 31;
        sWt[kk*129 + c] = W4[c*rowstride4 + kk];
    }
}

// 64x128 output tile, K=128. A in smem [64][strideA], thread computes 8 rows x 4 cols
// (cols c = cg + 32*j). Accumulates into acc.
__device__ __forceinline__ void gemm_tile(const float* __restrict__ sA, int strideA,
                                          const float4* __restrict__ sWt,
                                          float acc[8][4], int pg, int cg) {
    #pragma unroll 4
    for (int kk = 0; kk < 32; ++kk) {
        float4 w0 = sWt[kk*129 + cg];
        float4 w1 = sWt[kk*129 + cg + 32];
        float4 w2 = sWt[kk*129 + cg + 64];
        float4 w3 = sWt[kk*129 + cg + 96];
        #pragma unroll
        for (int r = 0; r < 8; ++r) {
            float4 a = *(const float4*)(sA + (pg*8 + r)*strideA + kk*4);
            acc[r][0] += a.x*w0.x + a.y*w0.y + a.z*w0.z + a.w*w0.w;
            acc[r][1] += a.x*w1.x + a.y*w1.y + a.z*w1.z + a.w*w1.w;
            acc[r][2] += a.x*w2.x + a.y*w2.y + a.z*w2.z + a.w*w2.w;
            acc[r][3] += a.x*w3.x + a.y*w3.y + a.z*w3.z + a.w*w3.w;
        }
    }
}

// ---------------- K0: fuse convp + pw1 into one 128x128 weight ----------------
__global__ void k_fuse(const float* __restrict__ convp_w, const float* __restrict__ convp_b,
                       const float* __restrict__ pw1_w,   const float* __restrict__ pw1_b) {
    int gid = blockIdx.x*256 + threadIdx.x;      // 64 blocks * 256 = 16384
    int o = gid >> 7, i = gid & 127;
    float s = 0.f;
    for (int c = 0; c < CCH; ++c) s += pw1_w[o*CCH + c] * convp_w[c*CCH + i];
    g_Wc[o*CCH + i] = s;
    if (gid < CCH) {
        float b = pw1_b[gid];
        for (int c = 0; c < CCH; ++c) b += pw1_w[gid*CCH + c] * convp_b[c];
        g_bc[gid] = b;
    }
}

// ---------------- LN1: NCHW -> layernorm -> window-token layout ----------------
__global__ void k_ln1(const float* __restrict__ x, const float* __restrict__ w,
                      const float* __restrict__ b) {
    __shared__ float s[64*129];
    __shared__ float s_mu[64], s_rs[64];
    int tid = threadIdx.x, bid = blockIdx.x;
    int w0 = (bid & 3) * 64;
    int h  = (bid >> 2) & 255;
    int bb = bid >> 10;
    const float* xb = x + (size_t)bb*CCH*65536 + h*256 + w0;
    for (int idx = tid; idx < 8192; idx += 256) {
        int c = idx >> 6, p = idx & 63;
        s[p*129 + c] = xb[c*65536 + p];                 // coalesced over p
    }
    __syncthreads();
    int p = tid >> 2, q = tid & 3;
    float sm = 0.f, sq = 0.f;
    #pragma unroll
    for (int i = 0; i < 32; ++i) { float v = s[p*129 + q*32 + i]; sm += v; sq += v*v; }
    sm += __shfl_xor_sync(0xffffffffu, sm, 1); sq += __shfl_xor_sync(0xffffffffu, sq, 1);
    sm += __shfl_xor_sync(0xffffffffu, sm, 2); sq += __shfl_xor_sync(0xffffffffu, sq, 2);
    if (q == 0) {
        float mu = sm * (1.f/128.f);
        float var = sq * (1.f/128.f) - mu*mu;
        s_mu[p] = mu; s_rs[p] = rsqrtf(var + 1e-5f);
    }
    __syncthreads();
    for (int idx = tid; idx < 8192; idx += 256) {
        int pp = idx >> 7, c = idx & 127;
        int wc = w0 + pp;
        int win = (bb*32 + (h >> 3))*32 + (wc >> 3);
        int n   = (h & 7)*8 + (wc & 7);
        float v = (s[pp*129 + c] - s_mu[pp]) * s_rs[pp] * w[c] + b[c];
        g_y[(size_t)win*8192 + n*128 + c] = v;          // contiguous per pixel
    }
}

// ---------------- ReMSA: one CTA per 8x8 window ----------------
__global__ void k_remsa(const float* __restrict__ qkv_w, const float* __restrict__ qkv_b,
                        const float* __restrict__ pos_bias,
                        const float* __restrict__ out_w, const float* __restrict__ out_b,
                        const float* __restrict__ tok_w, const float* __restrict__ tok_b,
                        const float* __restrict__ dw1_w, const float* __restrict__ dw1_b) {
    extern __shared__ __align__(16) float smem[];
    float*  s_y   = smem;                         // 64*132   (LN1 tile, later ao)
    float*  s_big = smem + 64*132;                // 64*516   (qkv cols 0..383 | xc1 384..511)
    float4* s_Wt  = (float4*)(smem + 64*132 + 64*516); // 32*129 float4
    int tid = threadIdx.x;
    int win = blockIdx.x;
    const float* yb = g_y + (size_t)win*8192;
    for (int idx = tid; idx < 8192; idx += 256)
        s_y[(idx >> 7)*132 + (idx & 127)] = yb[idx];
    __syncthreads();
    int pg = tid >> 5, cg = tid & 31;

    // Phase A: [qkv_w ; Wc] GEMM (64 x 512)
    for (int chunk = 0; chunk < 4; ++chunk) {
        const float* Wsrc = (chunk < 3) ? (qkv_w + chunk*128*128) : g_Wc;
        stage_w(Wsrc, 32, s_Wt, tid);
        __syncthreads();
        float acc[8][4] = {{0.f}};
        gemm_tile(s_y, 132, s_Wt, acc, pg, cg);
        const float* bsrc = (chunk < 3) ? (qkv_b + chunk*128) : g_bc;
        #pragma unroll
        for (int r = 0; r < 8; ++r)
            #pragma unroll
            for (int j = 0; j < 4; ++j) {
                int c = cg + 32*j;
                s_big[(pg*8 + r)*516 + chunk*128 + c] = acc[r][j] + bsrc[c];
            }
        __syncthreads();
    }

    // Phase B: head-mixing attention, 4 threads per token, 2 heads each
    {
        int n = tid >> 2, q4 = tid & 3;
        const float* base = s_big + n*516;
        const float* pb = pos_bias + n*64;
        #pragma unroll
        for (int hh = 0; hh < 2; ++hh) {
            int hI = q4*2 + hh;
            const float* qp = base + hI*48;
            float sc[8]; float mx = -1e30f;
            #pragma unroll
            for (int g = 0; g < 8; ++g) {
                const float* kp = base + g*48 + 16;
                float sd = 0.f;
                #pragma unroll
                for (int d = 0; d < 16; ++d) sd += qp[d]*kp[d];
                sc[g] = sd*0.25f + pb[hI*8 + g];
                mx = fmaxf(mx, sc[g]);
            }
            float ssum = 0.f;
            #pragma unroll
            for (int g = 0; g < 8; ++g) { sc[g] = expf(sc[g] - mx); ssum += sc[g]; }
            float inv = 1.f / ssum;
            float ao[16];
            #pragma unroll
            for (int d = 0; d < 16; ++d) ao[d] = 0.f;
            #pragma unroll
            for (int g = 0; g < 8; ++g) {
                float a = sc[g]*inv;
                const float* vp = base + g*48 + 32;
                #pragma unroll
                for (int d = 0; d < 16; ++d) ao[d] += a*vp[d];
            }
            #pragma unroll
            for (int d = 0; d < 16; ++d) s_y[n*132 + hI*16 + d] = ao[d];
        }
    }
    __syncthreads();

    // Phase C: token-dim depthwise conv (window-local, zero pad)
    for (int idx = tid; idx < 8192; idx += 256) {
        int n = idx >> 7, c = idx & 127;
        float a0 = (n > 0)  ? s_big[(n-1)*516 + 384 + c] : 0.f;
        float a1 =            s_big[ n   *516 + 384 + c];
        float a2 = (n < 63) ? s_big[(n+1)*516 + 384 + c] : 0.f;
        float d = a0*dw1_w[c*3] + a1*dw1_w[c*3+1] + a2*dw1_w[c*3+2] + dw1_b[c];
        s_big[n*516 + c] = d;   // disjoint columns, no race
    }
    __syncthreads();

    // Phase D: ao @ out_w^T + d1 @ tok_w^T + biases
    float acc[8][4] = {{0.f}};
    stage_w(out_w, 32, s_Wt, tid);
    __syncthreads();
    gemm_tile(s_y, 132, s_Wt, acc, pg, cg);
    __syncthreads();
    stage_w(tok_w, 32, s_Wt, tid);
    __syncthreads();
    gemm_tile(s_big, 516, s_Wt, acc, pg, cg);
    float* ob = g_att + (size_t)win*8192;
    #pragma unroll
    for (int r = 0; r < 8; ++r)
        #pragma unroll
        for (int j = 0; j < 4; ++j) {
            int c = cg + 32*j;
            ob[(pg*8 + r)*128 + c] = acc[r][j] + out_b[c] + tok_b[c];
        }
}

// ---------------- LN2: x1 = x + merge(att); emit x1 & LN(x1) channels-last ----------------
__global__ void k_ln2(const float* __restrict__ x, const float* __restrict__ w,
                      const float* __restrict__ b) {
    __shared__ float s[64*129];
    __shared__ float s_mu[64], s_rs[64];
    int tid = threadIdx.x, bid = blockIdx.x;
    int w0 = (bid & 3) * 64;
    int h  = (bid >> 2) & 255;
    int bb = bid >> 10;
    const float* xb = x + (size_t)bb*CCH*65536 + h*256 + w0;
    for (int idx = tid; idx < 8192; idx += 256) {
        int c = idx >> 6, p = idx & 63;
        s[p*129 + c] = xb[c*65536 + p];
    }
    __syncthreads();
    for (int idx = tid; idx < 8192; idx += 256) {
        int pp = idx >> 7, c = idx & 127;
        int wc = w0 + pp;
        int win = (bb*32 + (h >> 3))*32 + (wc >> 3);
        int n   = (h & 7)*8 + (wc & 7);
        float v = s[pp*129 + c] + g_att[(size_t)win*8192 + n*128 + c];
        s[pp*129 + c] = v;
        g_x1[((size_t)(bb*65536 + h*256 + wc))*128 + c] = v;
    }
    __syncthreads();
    int p = tid >> 2, q = tid & 3;
    float sm = 0.f, sq = 0.f;
    #pragma unroll
    for (int i = 0; i < 32; ++i) { float v = s[p*129 + q*32 + i]; sm += v; sq += v*v; }
    sm += __shfl_xor_sync(0xffffffffu, sm, 1); sq += __shfl_xor_sync(0xffffffffu, sq, 1);
    sm += __shfl_xor_sync(0xffffffffu, sm, 2); sq += __shfl_xor_sync(0xffffffffu, sq, 2);
    if (q == 0) {
        float mu = sm * (1.f/128.f);
        float var = sq * (1.f/128.f) - mu*mu;
        s_mu[p] = mu; s_rs[p] = rsqrtf(var + 1e-5f);
    }
    __syncthreads();
    for (int idx = tid; idx < 8192; idx += 256) {
        int pp = idx >> 7, c = idx & 127;
        int wc = w0 + pp;
        float v = (s[pp*129 + c] - s_mu[pp]) * s_rs[pp] * w[c] + b[c];
        g_y2[((size_t)(bb*65536 + h*256 + wc))*128 + c] = v;
    }
}

// ---------------- lpw: per-pixel 128x128 GEMM (no bias) ----------------
__global__ void k_lpw(const float* __restrict__ lpw_w) {
    extern __shared__ __align__(16) float smem[];
    float*  s_A  = smem;                          // 64*132
    float4* s_Wt = (float4*)(smem + 64*132);
    int tid = threadIdx.x;
    size_t pixbase = (size_t)blockIdx.x * 64;
    for (int idx = tid; idx < 8192; idx += 256)
        s_A[(idx >> 7)*132 + (idx & 127)] = g_y2[pixbase*128 + idx];
    stage_w(lpw_w, 32, s_Wt, tid);
    __syncthreads();
    int pg = tid >> 5, cg = tid & 31;
    float acc[8][4] = {{0.f}};
    gemm_tile(s_A, 132, s_Wt, acc, pg, cg);
    #pragma unroll
    for (int r = 0; r < 8; ++r)
        #pragma unroll
        for (int j = 0; j < 4; ++j)
            g_z[(pixbase + pg*8 + r)*128 + cg + 32*j] = acc[r][j];
}

// ---------------- LeFF: 3x3 dw + fc1 + GELU + fc2 + residual + NCHW out ----------------
__global__ void k_leff(const float* __restrict__ ldw_w, const float* __restrict__ ldw_b,
                       const float* __restrict__ fc1_w, const float* __restrict__ fc1_b,
                       const float* __restrict__ fc2_w, const float* __restrict__ fc2_b,
                       float* __restrict__ out) {
    extern __shared__ __align__(16) float smem[];
    float*  s_d  = smem;                          // 64*132
    float*  s_t  = smem + 64*132;                 // 64*132
    float4* s_Wt = (float4*)(smem + 2*64*132);
    int tid = threadIdx.x, bid = blockIdx.x;
    int w0 = (bid & 3) * 64;
    int h  = (bid >> 2) & 255;
    int bb = bid >> 10;

    // 3x3 depthwise over g_z (channels-last), zero padding
    for (int idx = tid; idx < 8192; idx += 256) {
        int p = idx >> 7, c = idx & 127;
        int xx0 = w0 + p;
        float acc = ldw_b[c];
        #pragma unroll
        for (int dy = 0; dy < 3; ++dy) {
            int yy = h + dy - 1;
            if (yy < 0 || yy > 255) continue;
            #pragma unroll
            for (int dx = 0; dx < 3; ++dx) {
                int xx = xx0 + dx - 1;
                if (xx < 0 || xx > 255) continue;
                acc += g_z[((size_t)(bb*65536 + yy*256 + xx))*128 + c] * ldw_w[c*9 + dy*3 + dx];
            }
        }
        s_d[p*132 + c] = acc;
    }
    __syncthreads();

    int pg = tid >> 5, cg = tid & 31;
    float oacc[8][4] = {{0.f}};
    for (int jc = 0; jc < 4; ++jc) {
        stage_w(fc1_w + jc*128*128, 32, s_Wt, tid);
        __syncthreads();
        float tacc[8][4] = {{0.f}};
        gemm_tile(s_d, 132, s_Wt, tacc, pg, cg);
        #pragma unroll
        for (int r = 0; r < 8; ++r)
            #pragma unroll
            for (int j = 0; j < 4; ++j) {
                int c = cg + 32*j;
                float v = tacc[r][j] + fc1_b[jc*128 + c];
                v = v * normcdff(v);                       // exact GELU
                s_t[(pg*8 + r)*132 + c] = v;
            }
        __syncthreads();
        stage_w(fc2_w + jc*128, 128, s_Wt, tid);           // fc2 row stride = 512 floats
        __syncthreads();
        gemm_tile(s_t, 132, s_Wt, oacc, pg, cg);
        __syncthreads();
    }

    // epilogue: + fc2_b + residual x1, stage, transpose-write NCHW
    size_t pixb = (size_t)(bb*65536 + h*256 + w0);
    #pragma unroll
    for (int r = 0; r < 8; ++r)
        #pragma unroll
        for (int j = 0; j < 4; ++j) {
            int c = cg + 32*j, p = pg*8 + r;
            s_d[p*132 + c] = oacc[r][j] + fc2_b[c] + g_x1[(pixb + p)*128 + c];
        }
    __syncthreads();
    for (int idx = tid; idx < 8192; idx += 256) {
        int c = idx >> 6, p = idx & 63;
        out[((size_t)(bb*128 + c)*256 + h)*256 + w0 + p] = s_d[p*132 + c];
    }
}

// ---------------- launch ----------------
extern "C" void kernel_launch(void* const* d_in, const int* in_sizes, int n_in,
                              void* d_out, int out_size) {
    const float* x        = (const float*)d_in[0];
    const float* norm1_w  = (const float*)d_in[1];
    const float* norm1_b  = (const float*)d_in[2];
    const float* qkv_w    = (const float*)d_in[3];
    const float* qkv_b    = (const float*)d_in[4];
    const float* pos_bias = (const float*)d_in[5];
    const float* out_w    = (const float*)d_in[6];
    const float* out_b    = (const float*)d_in[7];
    const float* convp_w  = (const float*)d_in[8];
    const float* convp_b  = (const float*)d_in[9];
    const float* pw1_w    = (const float*)d_in[10];
    const float* pw1_b    = (const float*)d_in[11];
    const float* dw1_w    = (const float*)d_in[12];
    const float* dw1_b    = (const float*)d_in[13];
    const float* tok_w    = (const float*)d_in[14];
    const float* tok_b    = (const float*)d_in[15];
    const float* norm2_w  = (const float*)d_in[16];
    const float* norm2_b  = (const float*)d_in[17];
    const float* lpw_w    = (const float*)d_in[18];
    const float* ldw_w    = (const float*)d_in[19];
    const float* ldw_b    = (const float*)d_in[20];
    const float* fc1_w    = (const float*)d_in[21];
    const float* fc1_b    = (const float*)d_in[22];
    const float* fc2_w    = (const float*)d_in[23];
    const float* fc2_b    = (const float*)d_in[24];
    float* out = (float*)d_out;

    const int SM_REMSA = (64*132 + 64*516)*4 + 32*129*16;   // 231936
    const int SM_LPW   = (64*132)*4 + 32*129*16;            //  99840
    const int SM_LEFF  = (2*64*132)*4 + 32*129*16;          // 133632
    cudaFuncSetAttribute(k_remsa, cudaFuncAttributeMaxDynamicSharedMemorySize, SM_REMSA);
    cudaFuncSetAttribute(k_lpw,   cudaFuncAttributeMaxDynamicSharedMemorySize, SM_LPW);
    cudaFuncSetAttribute(k_leff,  cudaFuncAttributeMaxDynamicSharedMemorySize, SM_LEFF);

    k_fuse <<<64,   256>>>(convp_w, convp_b, pw1_w, pw1_b);
    k_ln1  <<<4096, 256>>>(x, norm1_w, norm1_b);
    k_remsa<<<4096, 256, SM_REMSA>>>(qkv_w, qkv_b, pos_bias, out_w, out_b,
                                     tok_w, tok_b, dw1_w, dw1_b);
    k_ln2  <<<4096, 256>>>(x, norm2_w, norm2_b);
    k_lpw  <<<4096, 256, SM_LPW>>>(lpw_w);
    k_leff <<<4096, 256, SM_LEFF>>>(ldw_w, ldw_b, fc1_w, fc1_b, fc2_w, fc2_b, out);
}

// round 3
// speedup vs baseline: 1.6673x; 1.6673x over previous
#include <cuda_runtime.h>
#include <cstdint>
#include <math.h>

#define BATCH 4
#define CCH 128
#define NPIX (BATCH*256*256)     /* 262144 */
#define NWIN (NPIX/64)           /* 4096 */

// ---------------- device scratch ----------------
__device__ float g_Wc[CCH*CCH];
__device__ float g_bc[CCH];
__device__ float g_y [NPIX*CCH];   // LN1 out (tf32-rounded), window-token layout
__device__ float g_att[NPIX*CCH];  // remsa out, window-token layout
__device__ float g_x1[NPIX*CCH];   // x + merged attn, channels-last (fp32)
__device__ float g_y2[NPIX*CCH];   // LN2 out (tf32-rounded), channels-last
__device__ float g_z [NPIX*CCH];   // lpw out, channels-last (fp32)

// ---------------- tf32 helpers ----------------
__device__ __forceinline__ float tf32r(float x) {
    uint32_t r; asm("cvt.rna.tf32.f32 %0, %1;" : "=r"(r) : "f"(x));
    return __uint_as_float(r);
}

__device__ __forceinline__ void mma8(float* c, uint32_t a0, uint32_t a1, uint32_t a2,
                                     uint32_t a3, uint32_t b0, uint32_t b1) {
    asm volatile(
        "mma.sync.aligned.m16n8k8.row.col.f32.tf32.tf32.f32 "
        "{%0,%1,%2,%3},{%4,%5,%6,%7},{%8,%9},{%0,%1,%2,%3};"
        : "+f"(c[0]), "+f"(c[1]), "+f"(c[2]), "+f"(c[3])
        : "r"(a0), "r"(a1), "r"(a2), "r"(a3), "r"(b0), "r"(b1));
}

// Stage 128x128 weight, tf32-rounded, XOR-swizzled: sW[c*128 + (k ^ ((c&7)<<2))]
__device__ __forceinline__ void stage_w(const float* __restrict__ W, int rowstride,
                                        float* __restrict__ sW, int tid) {
    #pragma unroll
    for (int idx = tid; idx < 16384; idx += 256) {
        int c = idx >> 7, k = idx & 127;
        sW[c*128 + (k ^ ((c & 7) << 2))] = tf32r(W[c*rowstride + k]);
    }
}

// 64x128 (rows x cols) GEMM tile, K=128. 8 warps, each 32x32.
// sA: fp32(tf32-rounded) [64][strideA]; sW swizzled. Accumulates.
__device__ __forceinline__ void mma_gemm(const float* __restrict__ sA, int strideA,
                                         const float* __restrict__ sW,
                                         float acc[2][4][4], int warp, int lane) {
    int g = lane >> 2, tg = lane & 3;
    int rb = (warp & 1) * 32 + g;
    int cb = (warp >> 1) * 32 + g;
    int kx = g << 2;
    #pragma unroll
    for (int kt = 0; kt < 16; ++kt) {
        int k0 = kt * 8;
        uint32_t a[2][4];
        #pragma unroll
        for (int mt = 0; mt < 2; ++mt) {
            const float* ar = sA + (rb + mt*16)*strideA + k0 + tg;
            a[mt][0] = __float_as_uint(ar[0]);
            a[mt][1] = __float_as_uint(ar[8*strideA]);
            a[mt][2] = __float_as_uint(ar[4]);
            a[mt][3] = __float_as_uint(ar[8*strideA + 4]);
        }
        #pragma unroll
        for (int nt = 0; nt < 4; ++nt) {
            const float* wr = sW + (cb + nt*8)*128;
            uint32_t b0 = __float_as_uint(wr[(k0 | tg) ^ kx]);
            uint32_t b1 = __float_as_uint(wr[(k0 | tg | 4) ^ kx]);
            #pragma unroll
            for (int mt = 0; mt < 2; ++mt)
                mma8(acc[mt][nt], a[mt][0], a[mt][1], a[mt][2], a[mt][3], b0, b1);
        }
    }
}

// ---------------- K0: fuse convp + pw1 ----------------
__global__ void k_fuse(const float* __restrict__ convp_w, const float* __restrict__ convp_b,
                       const float* __restrict__ pw1_w,   const float* __restrict__ pw1_b) {
    int gid = blockIdx.x*256 + threadIdx.x;
    int o = gid >> 7, i = gid & 127;
    float s = 0.f;
    for (int c = 0; c < CCH; ++c) s += pw1_w[o*CCH + c] * convp_w[c*CCH + i];
    g_Wc[o*CCH + i] = s;
    if (gid < CCH) {
        float b = pw1_b[gid];
        for (int c = 0; c < CCH; ++c) b += pw1_w[gid*CCH + c] * convp_b[c];
        g_bc[gid] = b;
    }
}

// ---------------- LN1 ----------------
__global__ void k_ln1(const float* __restrict__ x, const float* __restrict__ w,
                      const float* __restrict__ b) {
    __shared__ float s[64*129];
    __shared__ float s_mu[64], s_rs[64];
    int tid = threadIdx.x, bid = blockIdx.x;
    int w0 = (bid & 3) * 64;
    int h  = (bid >> 2) & 255;
    int bb = bid >> 10;
    const float* xb = x + (size_t)bb*CCH*65536 + h*256 + w0;
    for (int idx = tid; idx < 8192; idx += 256) {
        int c = idx >> 6, p = idx & 63;
        s[p*129 + c] = xb[c*65536 + p];
    }
    __syncthreads();
    int p = tid >> 2, q = tid & 3;
    float sm = 0.f, sq = 0.f;
    #pragma unroll
    for (int i = 0; i < 32; ++i) { float v = s[p*129 + q*32 + i]; sm += v; sq += v*v; }
    sm += __shfl_xor_sync(0xffffffffu, sm, 1); sq += __shfl_xor_sync(0xffffffffu, sq, 1);
    sm += __shfl_xor_sync(0xffffffffu, sm, 2); sq += __shfl_xor_sync(0xffffffffu, sq, 2);
    if (q == 0) {
        float mu = sm * (1.f/128.f);
        float var = sq * (1.f/128.f) - mu*mu;
        s_mu[p] = mu; s_rs[p] = rsqrtf(var + 1e-5f);
    }
    __syncthreads();
    for (int idx = tid; idx < 8192; idx += 256) {
        int pp = idx >> 7, c = idx & 127;
        int wc = w0 + pp;
        int win = (bb*32 + (h >> 3))*32 + (wc >> 3);
        int n   = (h & 7)*8 + (wc & 7);
        float v = (s[pp*129 + c] - s_mu[pp]) * s_rs[pp] * w[c] + b[c];
        g_y[(size_t)win*8192 + n*128 + c] = tf32r(v);
    }
}

// ---------------- ReMSA ----------------
__global__ void k_remsa(const float* __restrict__ qkv_w, const float* __restrict__ qkv_b,
                        const float* __restrict__ pos_bias,
                        const float* __restrict__ out_w, const float* __restrict__ out_b,
                        const float* __restrict__ tok_w, const float* __restrict__ tok_b,
                        const float* __restrict__ dw1_w, const float* __restrict__ dw1_b) {
    extern __shared__ __align__(16) float smem[];
    float* s_y   = smem;                       // 64*132
    float* s_big = smem + 64*132;              // 64*516
    float* s_W   = smem + 64*132 + 64*516;     // 128*128 swizzled
    int tid = threadIdx.x, warp = tid >> 5, lane = tid & 31;
    int win = blockIdx.x;
    const float* yb = g_y + (size_t)win*8192;
    for (int idx = tid; idx < 8192; idx += 256)
        s_y[(idx >> 7)*132 + (idx & 127)] = yb[idx];

    int g = lane >> 2, tg = lane & 3;
    int rbase = (warp & 1) * 32 + g;
    int cbase = (warp >> 1) * 32;

    // Phase A: [qkv_w ; Wc] GEMM (64 x 512)
    for (int chunk = 0; chunk < 4; ++chunk) {
        const float* Wsrc = (chunk < 3) ? (qkv_w + chunk*128*128) : g_Wc;
        __syncthreads();
        stage_w(Wsrc, 128, s_W, tid);
        __syncthreads();
        float acc[2][4][4] = {};
        mma_gemm(s_y, 132, s_W, acc, warp, lane);
        const float* bsrc = (chunk < 3) ? (qkv_b + chunk*128) : g_bc;
        #pragma unroll
        for (int mt = 0; mt < 2; ++mt)
            #pragma unroll
            for (int nt = 0; nt < 4; ++nt) {
                int r0 = rbase + mt*16;
                int c0 = cbase + nt*8 + 2*tg;
                float b0 = bsrc[c0], b1 = bsrc[c0+1];
                *(float2*)&s_big[ r0   *516 + chunk*128 + c0] =
                    make_float2(acc[mt][nt][0] + b0, acc[mt][nt][1] + b1);
                *(float2*)&s_big[(r0+8)*516 + chunk*128 + c0] =
                    make_float2(acc[mt][nt][2] + b0, acc[mt][nt][3] + b1);
            }
    }
    __syncthreads();

    // Phase B: head-mixing attention (4 threads/token, 2 heads each)
    {
        int n = tid >> 2, q4 = tid & 3;
        const float* base = s_big + n*516;
        const float* pb = pos_bias + n*64;
        #pragma unroll
        for (int hh = 0; hh < 2; ++hh) {
            int hI = q4*2 + hh;
            const float* qp = base + hI*48;
            float sc[8]; float mx = -1e30f;
            #pragma unroll
            for (int gg = 0; gg < 8; ++gg) {
                const float* kp = base + gg*48 + 16;
                float sd = 0.f;
                #pragma unroll
                for (int d = 0; d < 16; ++d) sd += qp[d]*kp[d];
                sc[gg] = sd*0.25f + pb[hI*8 + gg];
                mx = fmaxf(mx, sc[gg]);
            }
            float ssum = 0.f;
            #pragma unroll
            for (int gg = 0; gg < 8; ++gg) { sc[gg] = expf(sc[gg] - mx); ssum += sc[gg]; }
            float inv = 1.f / ssum;
            float ao[16];
            #pragma unroll
            for (int d = 0; d < 16; ++d) ao[d] = 0.f;
            #pragma unroll
            for (int gg = 0; gg < 8; ++gg) {
                float a = sc[gg]*inv;
                const float* vp = base + gg*48 + 32;
                #pragma unroll
                for (int d = 0; d < 16; ++d) ao[d] += a*vp[d];
            }
            #pragma unroll
            for (int d = 0; d < 16; ++d) s_y[n*132 + hI*16 + d] = tf32r(ao[d]);
        }
    }
    __syncthreads();

    // Phase C: token-dim depthwise conv on xc (cols 384..511), write to cols 0..127
    for (int idx = tid; idx < 8192; idx += 256) {
        int n = idx >> 7, c = idx & 127;
        float a0 = (n > 0)  ? s_big[(n-1)*516 + 384 + c] : 0.f;
        float a1 =            s_big[ n   *516 + 384 + c];
        float a2 = (n < 63) ? s_big[(n+1)*516 + 384 + c] : 0.f;
        float d = a0*dw1_w[c*3] + a1*dw1_w[c*3+1] + a2*dw1_w[c*3+2] + dw1_b[c];
        s_big[n*516 + c] = tf32r(d);
    }
    __syncthreads();

    // Phase D: ao @ out_w^T + d1 @ tok_w^T
    float acc[2][4][4] = {};
    stage_w(out_w, 128, s_W, tid);
    __syncthreads();
    mma_gemm(s_y, 132, s_W, acc, warp, lane);
    __syncthreads();
    stage_w(tok_w, 128, s_W, tid);
    __syncthreads();
    mma_gemm(s_big, 516, s_W, acc, warp, lane);
    float* ob = g_att + (size_t)win*8192;
    #pragma unroll
    for (int mt = 0; mt < 2; ++mt)
        #pragma unroll
        for (int nt = 0; nt < 4; ++nt) {
            int r0 = rbase + mt*16;
            int c0 = cbase + nt*8 + 2*tg;
            float b0 = out_b[c0] + tok_b[c0], b1 = out_b[c0+1] + tok_b[c0+1];
            *(float2*)&ob[ r0   *128 + c0] =
                make_float2(acc[mt][nt][0] + b0, acc[mt][nt][1] + b1);
            *(float2*)&ob[(r0+8)*128 + c0] =
                make_float2(acc[mt][nt][2] + b0, acc[mt][nt][3] + b1);
        }
}

// ---------------- LN2 ----------------
__global__ void k_ln2(const float* __restrict__ x, const float* __restrict__ w,
                      const float* __restrict__ b) {
    __shared__ float s[64*129];
    __shared__ float s_mu[64], s_rs[64];
    int tid = threadIdx.x, bid = blockIdx.x;
    int w0 = (bid & 3) * 64;
    int h  = (bid >> 2) & 255;
    int bb = bid >> 10;
    const float* xb = x + (size_t)bb*CCH*65536 + h*256 + w0;
    for (int idx = tid; idx < 8192; idx += 256) {
        int c = idx >> 6, p = idx & 63;
        s[p*129 + c] = xb[c*65536 + p];
    }
    __syncthreads();
    for (int idx = tid; idx < 8192; idx += 256) {
        int pp = idx >> 7, c = idx & 127;
        int wc = w0 + pp;
        int win = (bb*32 + (h >> 3))*32 + (wc >> 3);
        int n   = (h & 7)*8 + (wc & 7);
        float v = s[pp*129 + c] + g_att[(size_t)win*8192 + n*128 + c];
        s[pp*129 + c] = v;
        g_x1[((size_t)(bb*65536 + h*256 + wc))*128 + c] = v;
    }
    __syncthreads();
    int p = tid >> 2, q = tid & 3;
    float sm = 0.f, sq = 0.f;
    #pragma unroll
    for (int i = 0; i < 32; ++i) { float v = s[p*129 + q*32 + i]; sm += v; sq += v*v; }
    sm += __shfl_xor_sync(0xffffffffu, sm, 1); sq += __shfl_xor_sync(0xffffffffu, sq, 1);
    sm += __shfl_xor_sync(0xffffffffu, sm, 2); sq += __shfl_xor_sync(0xffffffffu, sq, 2);
    if (q == 0) {
        float mu = sm * (1.f/128.f);
        float var = sq * (1.f/128.f) - mu*mu;
        s_mu[p] = mu; s_rs[p] = rsqrtf(var + 1e-5f);
    }
    __syncthreads();
    for (int idx = tid; idx < 8192; idx += 256) {
        int pp = idx >> 7, c = idx & 127;
        int wc = w0 + pp;
        float v = (s[pp*129 + c] - s_mu[pp]) * s_rs[pp] * w[c] + b[c];
        g_y2[((size_t)(bb*65536 + h*256 + wc))*128 + c] = tf32r(v);
    }
}

// ---------------- lpw ----------------
__global__ void k_lpw(const float* __restrict__ lpw_w) {
    extern __shared__ __align__(16) float smem[];
    float* s_A = smem;                         // 64*132
    float* s_W = smem + 64*132;
    int tid = threadIdx.x, warp = tid >> 5, lane = tid & 31;
    size_t pixbase = (size_t)blockIdx.x * 64;
    for (int idx = tid; idx < 8192; idx += 256)
        s_A[(idx >> 7)*132 + (idx & 127)] = g_y2[pixbase*128 + idx];
    stage_w(lpw_w, 128, s_W, tid);
    __syncthreads();
    float acc[2][4][4] = {};
    mma_gemm(s_A, 132, s_W, acc, warp, lane);
    int g = lane >> 2, tg = lane & 3;
    int rbase = (warp & 1) * 32 + g;
    int cbase = (warp >> 1) * 32;
    float* ob = g_z + pixbase*128;
    #pragma unroll
    for (int mt = 0; mt < 2; ++mt)
        #pragma unroll
        for (int nt = 0; nt < 4; ++nt) {
            int r0 = rbase + mt*16;
            int c0 = cbase + nt*8 + 2*tg;
            *(float2*)&ob[ r0   *128 + c0] = make_float2(acc[mt][nt][0], acc[mt][nt][1]);
            *(float2*)&ob[(r0+8)*128 + c0] = make_float2(acc[mt][nt][2], acc[mt][nt][3]);
        }
}

// ---------------- LeFF ----------------
__global__ void k_leff(const float* __restrict__ ldw_w, const float* __restrict__ ldw_b,
                       const float* __restrict__ fc1_w, const float* __restrict__ fc1_b,
                       const float* __restrict__ fc2_w, const float* __restrict__ fc2_b,
                       float* __restrict__ out) {
    extern __shared__ __align__(16) float smem[];
    float* s_d = smem;                         // 64*132
    float* s_t = smem + 64*132;                // 64*132
    float* s_W = smem + 2*64*132;
    int tid = threadIdx.x, warp = tid >> 5, lane = tid & 31, bid = blockIdx.x;
    int w0 = (bid & 3) * 64;
    int h  = (bid >> 2) & 255;
    int bb = bid >> 10;

    // 3x3 depthwise over g_z (channels-last), zero padding
    for (int idx = tid; idx < 8192; idx += 256) {
        int p = idx >> 7, c = idx & 127;
        int xx0 = w0 + p;
        float acc = ldw_b[c];
        #pragma unroll
        for (int dy = 0; dy < 3; ++dy) {
            int yy = h + dy - 1;
            if (yy < 0 || yy > 255) continue;
            #pragma unroll
            for (int dx = 0; dx < 3; ++dx) {
                int xx = xx0 + dx - 1;
                if (xx < 0 || xx > 255) continue;
                acc += g_z[((size_t)(bb*65536 + yy*256 + xx))*128 + c] * ldw_w[c*9 + dy*3 + dx];
            }
        }
        s_d[p*132 + c] = tf32r(acc);
    }

    int g = lane >> 2, tg = lane & 3;
    int rbase = (warp & 1) * 32 + g;
    int cbase = (warp >> 1) * 32;
    float oacc[2][4][4] = {};
    for (int jc = 0; jc < 4; ++jc) {
        __syncthreads();
        stage_w(fc1_w + jc*128*128, 128, s_W, tid);
        __syncthreads();
        float tacc[2][4][4] = {};
        mma_gemm(s_d, 132, s_W, tacc, warp, lane);
        #pragma unroll
        for (int mt = 0; mt < 2; ++mt)
            #pragma unroll
            for (int nt = 0; nt < 4; ++nt) {
                int r0 = rbase + mt*16;
                int c0 = cbase + nt*8 + 2*tg;
                #pragma unroll
                for (int q = 0; q < 4; ++q) {
                    float v = tacc[mt][nt][q] + fc1_b[jc*128 + c0 + (q & 1)];
                    v = v * normcdff(v);
                    s_t[(r0 + (q >> 1)*8)*132 + c0 + (q & 1)] = tf32r(v);
                }
            }
        __syncthreads();
        stage_w(fc2_w + jc*128, 512, s_W, tid);
        __syncthreads();
        mma_gemm(s_t, 132, s_W, oacc, warp, lane);
    }
    __syncthreads();

    // epilogue: + fc2_b + residual x1, stage, transpose-write NCHW
    size_t pixb = (size_t)(bb*65536 + h*256 + w0);
    #pragma unroll
    for (int mt = 0; mt < 2; ++mt)
        #pragma unroll
        for (int nt = 0; nt < 4; ++nt) {
            int r0 = rbase + mt*16;
            int c0 = cbase + nt*8 + 2*tg;
            #pragma unroll
            for (int q = 0; q < 4; ++q) {
                int r = r0 + (q >> 1)*8, c = c0 + (q & 1);
                s_d[r*132 + c] = oacc[mt][nt][q] + fc2_b[c] + g_x1[(pixb + r)*128 + c];
            }
        }
    __syncthreads();
    for (int idx = tid; idx < 8192; idx += 256) {
        int c = idx >> 6, p = idx & 63;
        out[((size_t)(bb*128 + c)*256 + h)*256 + w0 + p] = s_d[p*132 + c];
    }
}

// ---------------- launch ----------------
extern "C" void kernel_launch(void* const* d_in, const int* in_sizes, int n_in,
                              void* d_out, int out_size) {
    const float* x        = (const float*)d_in[0];
    const float* norm1_w  = (const float*)d_in[1];
    const float* norm1_b  = (const float*)d_in[2];
    const float* qkv_w    = (const float*)d_in[3];
    const float* qkv_b    = (const float*)d_in[4];
    const float* pos_bias = (const float*)d_in[5];
    const float* out_w    = (const float*)d_in[6];
    const float* out_b    = (const float*)d_in[7];
    const float* convp_w  = (const float*)d_in[8];
    const float* convp_b  = (const float*)d_in[9];
    const float* pw1_w    = (const float*)d_in[10];
    const float* pw1_b    = (const float*)d_in[11];
    const float* dw1_w    = (const float*)d_in[12];
    const float* dw1_b    = (const float*)d_in[13];
    const float* tok_w    = (const float*)d_in[14];
    const float* tok_b    = (const float*)d_in[15];
    const float* norm2_w  = (const float*)d_in[16];
    const float* norm2_b  = (const float*)d_in[17];
    const float* lpw_w    = (const float*)d_in[18];
    const float* ldw_w    = (const float*)d_in[19];
    const float* ldw_b    = (const float*)d_in[20];
    const float* fc1_w    = (const float*)d_in[21];
    const float* fc1_b    = (const float*)d_in[22];
    const float* fc2_w    = (const float*)d_in[23];
    const float* fc2_b    = (const float*)d_in[24];
    float* out = (float*)d_out;

    const int SM_REMSA = (64*132 + 64*516 + 128*128)*4;   // 231424
    const int SM_LPW   = (64*132 + 128*128)*4;            //  99328
    const int SM_LEFF  = (2*64*132 + 128*128)*4;          // 133120
    cudaFuncSetAttribute(k_remsa, cudaFuncAttributeMaxDynamicSharedMemorySize, SM_REMSA);
    cudaFuncSetAttribute(k_lpw,   cudaFuncAttributeMaxDynamicSharedMemorySize, SM_LPW);
    cudaFuncSetAttribute(k_leff,  cudaFuncAttributeMaxDynamicSharedMemorySize, SM_LEFF);

    k_fuse <<<64,   256>>>(convp_w, convp_b, pw1_w, pw1_b);
    k_ln1  <<<4096, 256>>>(x, norm1_w, norm1_b);
    k_remsa<<<4096, 256, SM_REMSA>>>(qkv_w, qkv_b, pos_bias, out_w, out_b,
                                     tok_w, tok_b, dw1_w, dw1_b);
    k_ln2  <<<4096, 256>>>(x, norm2_w, norm2_b);
    k_lpw  <<<4096, 256, SM_LPW>>>(lpw_w);
    k_leff <<<4096, 256, SM_LEFF>>>(ldw_w, ldw_b, fc1_w, fc1_b, fc2_w, fc2_b, out);
}

// round 4
// speedup vs baseline: 2.4508x; 1.4700x over previous
#include <cuda_runtime.h>
#include <cuda_bf16.h>
#include <cstdint>
#include <math.h>

#define BATCH 4
#define CCH 128
#define NPIX (BATCH*256*256)     /* 262144 */
#define NWIN (NPIX/64)           /* 4096 */

// ---------------- device scratch ----------------
__device__ float g_Wc[CCH*CCH];
__device__ float g_bc[CCH];
__device__ __nv_bfloat16 g_y[NPIX*CCH];   // LN1 out, window-token layout [win][n][c]
__device__ float g_att[NPIX*CCH];         // remsa out fp32, window-token layout
__device__ float g_x1[NPIX*CCH];          // x + merged attn, channels-last fp32
__device__ __nv_bfloat16 g_z[NPIX*CCH];   // lpw out, channels-last bf16

// ---------------- bf16 helpers ----------------
__device__ __forceinline__ uint32_t bf2(float a, float b) {
    __nv_bfloat162 t = __floats2bfloat162_rn(a, b);
    return *reinterpret_cast<uint32_t*>(&t);
}

__device__ __forceinline__ void mma16(float* c, const uint32_t* a, const uint32_t* b) {
    asm volatile(
        "mma.sync.aligned.m16n8k16.row.col.f32.bf16.bf16.f32 "
        "{%0,%1,%2,%3},{%4,%5,%6,%7},{%8,%9},{%0,%1,%2,%3};"
        : "+f"(c[0]), "+f"(c[1]), "+f"(c[2]), "+f"(c[3])
        : "r"(a[0]), "r"(a[1]), "r"(a[2]), "r"(a[3]), "r"(b[0]), "r"(b[1]));
}

// Stage 128x128 fp32 weight -> bf16 smem [128][136] (row-major, padded)
__device__ __forceinline__ void stage_wb(const float* __restrict__ W, int rowstride,
                                         __nv_bfloat16* __restrict__ sW, int tid) {
    #pragma unroll
    for (int idx = tid; idx < 4096; idx += 256) {
        int c = idx >> 5, kk = idx & 31;
        float4 w = *(const float4*)(W + c*rowstride + kk*4);
        uint2 p;
        p.x = bf2(w.x, w.y);
        p.y = bf2(w.z, w.w);
        *(uint2*)(sW + c*136 + kk*4) = p;
    }
}

// 64x128 GEMM tile, K=128, bf16 inputs, fp32 accum. 8 warps, each 32x32.
__device__ __forceinline__ void mma_gemm_bf(const __nv_bfloat16* __restrict__ sA, int strideA,
                                            const __nv_bfloat16* __restrict__ sW,
                                            float acc[2][4][4], int warp, int lane) {
    int g = lane >> 2, tg = lane & 3;
    int rb = (warp & 1) * 32 + g;
    int cb = (warp >> 1) * 32 + g;
    #pragma unroll
    for (int kt = 0; kt < 8; ++kt) {
        int k0 = kt * 16;
        uint32_t a[2][4];
        #pragma unroll
        for (int mt = 0; mt < 2; ++mt) {
            const __nv_bfloat16* ar = sA + (rb + mt*16)*strideA + k0 + 2*tg;
            a[mt][0] = *(const uint32_t*)(ar);
            a[mt][1] = *(const uint32_t*)(ar + 8*strideA);
            a[mt][2] = *(const uint32_t*)(ar + 8);
            a[mt][3] = *(const uint32_t*)(ar + 8*strideA + 8);
        }
        #pragma unroll
        for (int nt = 0; nt < 4; ++nt) {
            const __nv_bfloat16* wr = sW + (cb + nt*8)*136 + k0 + 2*tg;
            uint32_t b[2];
            b[0] = *(const uint32_t*)(wr);
            b[1] = *(const uint32_t*)(wr + 8);
            #pragma unroll
            for (int mt = 0; mt < 2; ++mt)
                mma16(acc[mt][nt], a[mt], b);
        }
    }
}

// ---------------- K0: fuse convp + pw1 ----------------
__global__ void k_fuse(const float* __restrict__ convp_w, const float* __restrict__ convp_b,
                       const float* __restrict__ pw1_w,   const float* __restrict__ pw1_b) {
    int gid = blockIdx.x*256 + threadIdx.x;
    int o = gid >> 7, i = gid & 127;
    float s = 0.f;
    for (int c = 0; c < CCH; ++c) s += pw1_w[o*CCH + c] * convp_w[c*CCH + i];
    g_Wc[o*CCH + i] = s;
    if (gid < CCH) {
        float b = pw1_b[gid];
        for (int c = 0; c < CCH; ++c) b += pw1_w[gid*CCH + c] * convp_b[c];
        g_bc[gid] = b;
    }
}

// ---------------- LN1: NCHW -> layernorm -> bf16 window-token layout ----------------
__global__ void k_ln1(const float* __restrict__ x, const float* __restrict__ w,
                      const float* __restrict__ b) {
    __shared__ float s[64*129];
    __shared__ float s_mu[64], s_rs[64];
    int tid = threadIdx.x, bid = blockIdx.x;
    int w0 = (bid & 3) * 64;
    int h  = (bid >> 2) & 255;
    int bb = bid >> 10;
    const float* xb = x + (size_t)bb*CCH*65536 + h*256 + w0;
    for (int idx = tid; idx < 8192; idx += 256) {
        int c = idx >> 6, p = idx & 63;
        s[p*129 + c] = xb[c*65536 + p];
    }
    __syncthreads();
    int p = tid >> 2, q = tid & 3;
    float sm = 0.f, sq = 0.f;
    #pragma unroll
    for (int i = 0; i < 32; ++i) { float v = s[p*129 + q*32 + i]; sm += v; sq += v*v; }
    sm += __shfl_xor_sync(0xffffffffu, sm, 1); sq += __shfl_xor_sync(0xffffffffu, sq, 1);
    sm += __shfl_xor_sync(0xffffffffu, sm, 2); sq += __shfl_xor_sync(0xffffffffu, sq, 2);
    if (q == 0) {
        float mu = sm * (1.f/128.f);
        float var = sq * (1.f/128.f) - mu*mu;
        s_mu[p] = mu; s_rs[p] = rsqrtf(var + 1e-5f);
    }
    __syncthreads();
    uint32_t* yw = (uint32_t*)g_y;
    for (int idx = tid; idx < 4096; idx += 256) {
        int pp = idx >> 6, cw = idx & 63;
        int c0 = cw*2;
        int wc = w0 + pp;
        int win = (bb*32 + (h >> 3))*32 + (wc >> 3);
        int n   = (h & 7)*8 + (wc & 7);
        float mu = s_mu[pp], rs = s_rs[pp];
        float v0 = (s[pp*129 + c0]   - mu) * rs * w[c0]   + b[c0];
        float v1 = (s[pp*129 + c0+1] - mu) * rs * w[c0+1] + b[c0+1];
        yw[(size_t)win*4096 + n*64 + cw] = bf2(v0, v1);
    }
}

// ---------------- ReMSA: one CTA per 8x8 window ----------------
__global__ void k_remsa(const float* __restrict__ qkv_w, const float* __restrict__ qkv_b,
                        const float* __restrict__ pos_bias,
                        const float* __restrict__ out_w, const float* __restrict__ out_b,
                        const float* __restrict__ tok_w, const float* __restrict__ tok_b,
                        const float* __restrict__ dw1_w, const float* __restrict__ dw1_b) {
    extern __shared__ __align__(16) char smem[];
    float* s_big = (float*)smem;                                    // 64*516 fp32
    __nv_bfloat16* s_y = (__nv_bfloat16*)(smem + 132096);           // 64*136 (LN1 tile / ao)
    __nv_bfloat16* s_c = (__nv_bfloat16*)(smem + 132096 + 17408);   // 64*136 (dwconv out)
    __nv_bfloat16* s_W = (__nv_bfloat16*)(smem + 132096 + 34816);   // 128*136 weights
    int tid = threadIdx.x, warp = tid >> 5, lane = tid & 31;
    int win = blockIdx.x;

    const uint32_t* yw = (const uint32_t*)g_y + (size_t)win*4096;
    uint32_t* s_yw = (uint32_t*)s_y;
    for (int idx = tid; idx < 4096; idx += 256) {
        int n = idx >> 6, cw = idx & 63;
        s_yw[n*68 + cw] = yw[idx];
    }

    int g = lane >> 2, tg = lane & 3;
    int rbase = (warp & 1) * 32 + g;
    int cbase = (warp >> 1) * 32;

    // Phase A: [qkv_w ; Wc] GEMM (64 x 512), outputs fp32 into s_big
    for (int chunk = 0; chunk < 4; ++chunk) {
        const float* Wsrc = (chunk < 3) ? (qkv_w + chunk*128*128) : g_Wc;
        __syncthreads();
        stage_wb(Wsrc, 128, s_W, tid);
        __syncthreads();
        float acc[2][4][4] = {};
        mma_gemm_bf(s_y, 136, s_W, acc, warp, lane);
        const float* bsrc = (chunk < 3) ? (qkv_b + chunk*128) : g_bc;
        #pragma unroll
        for (int mt = 0; mt < 2; ++mt)
            #pragma unroll
            for (int nt = 0; nt < 4; ++nt) {
                int r0 = rbase + mt*16;
                int c0 = cbase + nt*8 + 2*tg;
                float b0 = bsrc[c0], b1 = bsrc[c0+1];
                *(float2*)&s_big[ r0   *516 + chunk*128 + c0] =
                    make_float2(acc[mt][nt][0] + b0, acc[mt][nt][1] + b1);
                *(float2*)&s_big[(r0+8)*516 + chunk*128 + c0] =
                    make_float2(acc[mt][nt][2] + b0, acc[mt][nt][3] + b1);
            }
    }
    __syncthreads();

    // Phase B: head-mixing attention (4 threads/token, 2 heads each); ao -> s_y (bf16)
    {
        int n = tid >> 2, q4 = tid & 3;
        const float* base = s_big + n*516;
        const float* pb = pos_bias + n*64;
        uint32_t* aw = (uint32_t*)s_y;
        #pragma unroll
        for (int hh = 0; hh < 2; ++hh) {
            int hI = q4*2 + hh;
            const float* qp = base + hI*48;
            float sc[8]; float mx = -1e30f;
            #pragma unroll
            for (int gg = 0; gg < 8; ++gg) {
                const float* kp = base + gg*48 + 16;
                float sd = 0.f;
                #pragma unroll
                for (int d = 0; d < 16; ++d) sd += qp[d]*kp[d];
                sc[gg] = sd*0.25f + pb[hI*8 + gg];
                mx = fmaxf(mx, sc[gg]);
            }
            float ssum = 0.f;
            #pragma unroll
            for (int gg = 0; gg < 8; ++gg) { sc[gg] = expf(sc[gg] - mx); ssum += sc[gg]; }
            float inv = 1.f / ssum;
            float ao[16];
            #pragma unroll
            for (int d = 0; d < 16; ++d) ao[d] = 0.f;
            #pragma unroll
            for (int gg = 0; gg < 8; ++gg) {
                float a = sc[gg]*inv;
                const float* vp = base + gg*48 + 32;
                #pragma unroll
                for (int d = 0; d < 16; ++d) ao[d] += a*vp[d];
            }
            #pragma unroll
            for (int d = 0; d < 16; d += 2)
                aw[n*68 + hI*8 + (d >> 1)] = bf2(ao[d], ao[d+1]);
        }
    }

    // Phase C: token-dim depthwise conv on xc (s_big cols 384..511) -> s_c (bf16)
    {
        uint32_t* cw32 = (uint32_t*)s_c;
        for (int idx = tid; idx < 4096; idx += 256) {
            int n = idx >> 6, cw = idx & 63;
            int c0 = cw*2;
            const float* col = s_big + 384;
            float a0, a1, a2, b0, b1, b2;
            a1 = col[n*516 + c0];     b1 = col[n*516 + c0 + 1];
            a0 = (n > 0)  ? col[(n-1)*516 + c0]     : 0.f;
            b0 = (n > 0)  ? col[(n-1)*516 + c0 + 1] : 0.f;
            a2 = (n < 63) ? col[(n+1)*516 + c0]     : 0.f;
            b2 = (n < 63) ? col[(n+1)*516 + c0 + 1] : 0.f;
            float d0 = a0*dw1_w[c0*3] + a1*dw1_w[c0*3+1] + a2*dw1_w[c0*3+2] + dw1_b[c0];
            float d1 = b0*dw1_w[c0*3+3] + b1*dw1_w[c0*3+4] + b2*dw1_w[c0*3+5] + dw1_b[c0+1];
            cw32[n*68 + cw] = bf2(d0, d1);
        }
    }
    __syncthreads();

    // Phase D: ao @ out_w^T + d1 @ tok_w^T
    float acc[2][4][4] = {};
    stage_wb(out_w, 128, s_W, tid);
    __syncthreads();
    mma_gemm_bf(s_y, 136, s_W, acc, warp, lane);
    __syncthreads();
    stage_wb(tok_w, 128, s_W, tid);
    __syncthreads();
    mma_gemm_bf(s_c, 136, s_W, acc, warp, lane);
    float* ob = g_att + (size_t)win*8192;
    #pragma unroll
    for (int mt = 0; mt < 2; ++mt)
        #pragma unroll
        for (int nt = 0; nt < 4; ++nt) {
            int r0 = rbase + mt*16;
            int c0 = cbase + nt*8 + 2*tg;
            float b0 = out_b[c0] + tok_b[c0], b1 = out_b[c0+1] + tok_b[c0+1];
            *(float2*)&ob[ r0   *128 + c0] =
                make_float2(acc[mt][nt][0] + b0, acc[mt][nt][1] + b1);
            *(float2*)&ob[(r0+8)*128 + c0] =
                make_float2(acc[mt][nt][2] + b0, acc[mt][nt][3] + b1);
        }
}

// ---------------- LN2 + lpw fused: x1 = x + merge(att); z = LN(x1) @ lpw^T ----------------
__global__ void k_ln2z(const float* __restrict__ x, const float* __restrict__ w,
                       const float* __restrict__ b, const float* __restrict__ lpw_w) {
    extern __shared__ __align__(16) char smem[];
    float* s = (float*)smem;                                      // 64*129 fp32
    __nv_bfloat16* s_A = (__nv_bfloat16*)(smem + 33024);          // 64*136
    __nv_bfloat16* s_W = (__nv_bfloat16*)(smem + 33024 + 17408);  // 128*136
    __shared__ float s_mu[64], s_rs[64];
    int tid = threadIdx.x, bid = blockIdx.x;
    int warp = tid >> 5, lane = tid & 31;
    int w0 = (bid & 3) * 64;
    int h  = (bid >> 2) & 255;
    int bb = bid >> 10;
    const float* xb = x + (size_t)bb*CCH*65536 + h*256 + w0;
    for (int idx = tid; idx < 8192; idx += 256) {
        int c = idx >> 6, p = idx & 63;
        s[p*129 + c] = xb[c*65536 + p];
    }
    __syncthreads();
    for (int idx = tid; idx < 8192; idx += 256) {
        int pp = idx >> 7, c = idx & 127;
        int wc = w0 + pp;
        int win = (bb*32 + (h >> 3))*32 + (wc >> 3);
        int n   = (h & 7)*8 + (wc & 7);
        float v = s[pp*129 + c] + g_att[(size_t)win*8192 + n*128 + c];
        s[pp*129 + c] = v;
        g_x1[((size_t)(bb*65536 + h*256 + wc))*128 + c] = v;
    }
    __syncthreads();
    int p = tid >> 2, q = tid & 3;
    float sm = 0.f, sq = 0.f;
    #pragma unroll
    for (int i = 0; i < 32; ++i) { float v = s[p*129 + q*32 + i]; sm += v; sq += v*v; }
    sm += __shfl_xor_sync(0xffffffffu, sm, 1); sq += __shfl_xor_sync(0xffffffffu, sq, 1);
    sm += __shfl_xor_sync(0xffffffffu, sm, 2); sq += __shfl_xor_sync(0xffffffffu, sq, 2);
    if (q == 0) {
        float mu = sm * (1.f/128.f);
        float var = sq * (1.f/128.f) - mu*mu;
        s_mu[p] = mu; s_rs[p] = rsqrtf(var + 1e-5f);
    }
    __syncthreads();
    uint32_t* aw = (uint32_t*)s_A;
    for (int idx = tid; idx < 4096; idx += 256) {
        int pp = idx >> 6, cw = idx & 63;
        int c0 = cw*2;
        float mu = s_mu[pp], rs = s_rs[pp];
        float v0 = (s[pp*129 + c0]   - mu) * rs * w[c0]   + b[c0];
        float v1 = (s[pp*129 + c0+1] - mu) * rs * w[c0+1] + b[c0+1];
        aw[pp*68 + cw] = bf2(v0, v1);
    }
    stage_wb(lpw_w, 128, s_W, tid);
    __syncthreads();
    float acc[2][4][4] = {};
    mma_gemm_bf(s_A, 136, s_W, acc, warp, lane);
    int g = lane >> 2, tg = lane & 3;
    int rbase = (warp & 1) * 32 + g;
    int cbase = (warp >> 1) * 32;
    size_t pixb = (size_t)(bb*65536 + h*256 + w0);
    uint32_t* zw = (uint32_t*)g_z;
    #pragma unroll
    for (int mt = 0; mt < 2; ++mt)
        #pragma unroll
        for (int nt = 0; nt < 4; ++nt) {
            int r0 = rbase + mt*16;
            int c0 = cbase + nt*8 + 2*tg;
            zw[(pixb + r0)  *64 + (c0 >> 1)] = bf2(acc[mt][nt][0], acc[mt][nt][1]);
            zw[(pixb + r0+8)*64 + (c0 >> 1)] = bf2(acc[mt][nt][2], acc[mt][nt][3]);
        }
}

// ---------------- LeFF: 3x3 dw + fc1 + GELU + fc2 + residual + NCHW out ----------------
__global__ void k_leff(const float* __restrict__ ldw_w, const float* __restrict__ ldw_b,
                       const float* __restrict__ fc1_w, const float* __restrict__ fc1_b,
                       const float* __restrict__ fc2_w, const float* __restrict__ fc2_b,
                       float* __restrict__ out) {
    extern __shared__ __align__(16) char smem[];
    __nv_bfloat16* s_d = (__nv_bfloat16*)smem;                   // 64*136
    __nv_bfloat16* s_t = (__nv_bfloat16*)(smem + 17408);         // 64*136
    __nv_bfloat16* s_W = (__nv_bfloat16*)(smem + 34816);         // 128*136
    float* s_f = (float*)(smem + 34816);                         // aliases s_W, 64*129 fp32
    int tid = threadIdx.x, warp = tid >> 5, lane = tid & 31, bid = blockIdx.x;
    int w0 = (bid & 3) * 64;
    int h  = (bid >> 2) & 255;
    int bb = bid >> 10;

    // 3x3 depthwise over g_z (bf16 channels-last), zero padding; pairs of channels
    {
        const uint32_t* zw = (const uint32_t*)g_z;
        uint32_t* dw = (uint32_t*)s_d;
        for (int idx = tid; idx < 4096; idx += 256) {
            int p = idx >> 6, cw = idx & 63;
            int c0 = cw*2;
            int xx0 = w0 + p;
            float accA = ldw_b[c0], accB = ldw_b[c0+1];
            #pragma unroll
            for (int dy = 0; dy < 3; ++dy) {
                int yy = h + dy - 1;
                if (yy < 0 || yy > 255) continue;
                #pragma unroll
                for (int dx = 0; dx < 3; ++dx) {
                    int xx = xx0 + dx - 1;
                    if (xx < 0 || xx > 255) continue;
                    uint32_t word = zw[((size_t)(bb*65536 + yy*256 + xx))*64 + cw];
                    __nv_bfloat162 t = *reinterpret_cast<__nv_bfloat162*>(&word);
                    accA += __bfloat162float(t.x) * ldw_w[c0*9     + dy*3 + dx];
                    accB += __bfloat162float(t.y) * ldw_w[(c0+1)*9 + dy*3 + dx];
                }
            }
            dw[p*68 + cw] = bf2(accA, accB);
        }
    }

    int g = lane >> 2, tg = lane & 3;
    int rbase = (warp & 1) * 32 + g;
    int cbase = (warp >> 1) * 32;
    float oacc[2][4][4] = {};
    for (int jc = 0; jc < 4; ++jc) {
        __syncthreads();
        stage_wb(fc1_w + jc*128*128, 128, s_W, tid);
        __syncthreads();
        float tacc[2][4][4] = {};
        mma_gemm_bf(s_d, 136, s_W, tacc, warp, lane);
        uint32_t* tw = (uint32_t*)s_t;
        #pragma unroll
        for (int mt = 0; mt < 2; ++mt)
            #pragma unroll
            for (int nt = 0; nt < 4; ++nt) {
                int r0 = rbase + mt*16;
                int c0 = cbase + nt*8 + 2*tg;
                float b0 = fc1_b[jc*128 + c0], b1 = fc1_b[jc*128 + c0 + 1];
                float v0 = tacc[mt][nt][0] + b0; v0 = v0 * normcdff(v0);
                float v1 = tacc[mt][nt][1] + b1; v1 = v1 * normcdff(v1);
                float v2 = tacc[mt][nt][2] + b0; v2 = v2 * normcdff(v2);
                float v3 = tacc[mt][nt][3] + b1; v3 = v3 * normcdff(v3);
                tw[ r0   *68 + (c0 >> 1)] = bf2(v0, v1);
                tw[(r0+8)*68 + (c0 >> 1)] = bf2(v2, v3);
            }
        __syncthreads();
        stage_wb(fc2_w + jc*128, 512, s_W, tid);
        __syncthreads();
        mma_gemm_bf(s_t, 136, s_W, oacc, warp, lane);
    }
    __syncthreads();   // done reading s_W before aliasing as s_f

    // epilogue: + fc2_b + residual x1 (fp32), stage fp32, transpose-write NCHW
    size_t pixb = (size_t)(bb*65536 + h*256 + w0);
    #pragma unroll
    for (int mt = 0; mt < 2; ++mt)
        #pragma unroll
        for (int nt = 0; nt < 4; ++nt) {
            int r0 = rbase + mt*16;
            int c0 = cbase + nt*8 + 2*tg;
            float b0 = fc2_b[c0], b1 = fc2_b[c0+1];
            float2 x0 = *(const float2*)&g_x1[(pixb + r0)  *128 + c0];
            float2 x1 = *(const float2*)&g_x1[(pixb + r0+8)*128 + c0];
            s_f[ r0   *129 + c0]     = oacc[mt][nt][0] + b0 + x0.x;
            s_f[ r0   *129 + c0 + 1] = oacc[mt][nt][1] + b1 + x0.y;
            s_f[(r0+8)*129 + c0]     = oacc[mt][nt][2] + b0 + x1.x;
            s_f[(r0+8)*129 + c0 + 1] = oacc[mt][nt][3] + b1 + x1.y;
        }
    __syncthreads();
    for (int idx = tid; idx < 8192; idx += 256) {
        int c = idx >> 6, p = idx & 63;
        out[((size_t)(bb*128 + c)*256 + h)*256 + w0 + p] = s_f[p*129 + c];
    }
}

// ---------------- launch ----------------
extern "C" void kernel_launch(void* const* d_in, const int* in_sizes, int n_in,
                              void* d_out, int out_size) {
    const float* x        = (const float*)d_in[0];
    const float* norm1_w  = (const float*)d_in[1];
    const float* norm1_b  = (const float*)d_in[2];
    const float* qkv_w    = (const float*)d_in[3];
    const float* qkv_b    = (const float*)d_in[4];
    const float* pos_bias = (const float*)d_in[5];
    const float* out_w    = (const float*)d_in[6];
    const float* out_b    = (const float*)d_in[7];
    const float* convp_w  = (const float*)d_in[8];
    const float* convp_b  = (const float*)d_in[9];
    const float* pw1_w    = (const float*)d_in[10];
    const float* pw1_b    = (const float*)d_in[11];
    const float* dw1_w    = (const float*)d_in[12];
    const float* dw1_b    = (const float*)d_in[13];
    const float* tok_w    = (const float*)d_in[14];
    const float* tok_b    = (const float*)d_in[15];
    const float* norm2_w  = (const float*)d_in[16];
    const float* norm2_b  = (const float*)d_in[17];
    const float* lpw_w    = (const float*)d_in[18];
    const float* ldw_w    = (const float*)d_in[19];
    const float* ldw_b    = (const float*)d_in[20];
    const float* fc1_w    = (const float*)d_in[21];
    const float* fc1_b    = (const float*)d_in[22];
    const float* fc2_w    = (const float*)d_in[23];
    const float* fc2_b    = (const float*)d_in[24];
    float* out = (float*)d_out;

    const int SM_REMSA = 132096 + 17408 + 17408 + 34816;   // 201728
    const int SM_LN2Z  = 33024 + 17408 + 34816;            //  85248
    const int SM_LEFF  = 17408 + 17408 + 34816;            //  69632
    cudaFuncSetAttribute(k_remsa, cudaFuncAttributeMaxDynamicSharedMemorySize, SM_REMSA);
    cudaFuncSetAttribute(k_ln2z,  cudaFuncAttributeMaxDynamicSharedMemorySize, SM_LN2Z);
    cudaFuncSetAttribute(k_leff,  cudaFuncAttributeMaxDynamicSharedMemorySize, SM_LEFF);

    k_fuse <<<64,   256>>>(convp_w, convp_b, pw1_w, pw1_b);
    k_ln1  <<<4096, 256>>>(x, norm1_w, norm1_b);
    k_remsa<<<4096, 256, SM_REMSA>>>(qkv_w, qkv_b, pos_bias, out_w, out_b,
                                     tok_w, tok_b, dw1_w, dw1_b);
    k_ln2z <<<4096, 256, SM_LN2Z>>>(x, norm2_w, norm2_b, lpw_w);
    k_leff <<<4096, 256, SM_LEFF>>>(ldw_w, ldw_b, fc1_w, fc1_b, fc2_w, fc2_b, out);
}

// round 5
// speedup vs baseline: 2.9306x; 1.1957x over previous
#include <cuda_runtime.h>
#include <cuda_bf16.h>
#include <cstdint>
#include <math.h>

#define BATCH 4
#define CCH 128
#define NPIX (BATCH*256*256)     /* 262144 */
#define NWIN (NPIX/64)           /* 4096 */

// ---------------- device scratch ----------------
__device__ float g_Wc[CCH*CCH];
__device__ float g_bc[CCH];
// bf16 weight bank: [0..2]=qkv, [3]=Wc, [4]=out_w, [5]=tok_w, [6]=lpw,
// [7..10]=fc1 chunks, [11..14]=fc2 chunks. Each 128x128 row-major (k contiguous).
__device__ __nv_bfloat16 g_wbf[15*16384];
__device__ __nv_bfloat16 g_y[NPIX*CCH];   // LN1 out, window-token layout
__device__ float g_att[NPIX*CCH];         // remsa out fp32, window-token layout
__device__ float g_x1[NPIX*CCH];          // x + merged attn, channels-last fp32
__device__ __nv_bfloat16 g_z[NPIX*CCH];   // lpw out, channels-last bf16

// ---------------- helpers ----------------
__device__ __forceinline__ uint32_t bf2(float a, float b) {
    __nv_bfloat162 t = __floats2bfloat162_rn(a, b);
    return *reinterpret_cast<uint32_t*>(&t);
}

// exact-GELU via FMA-only erf polynomial (Cephes, |z|<=1); rare tail uses erff
__device__ __forceinline__ float gelu_f(float v) {
    float z = v * 0.7071067811865475f;
    float az = fabsf(z);
    float e;
    if (az <= 1.0f) {
        float s = z*z;
        e = 7.853861595399774e-5f;
        e = e*s - 8.010193625184903e-4f;
        e = e*s + 5.188327685732524e-3f;
        e = e*s - 2.685381193529856e-2f;
        e = e*s + 1.128358514861418e-1f;
        e = e*s - 3.761262582423300e-1f;
        e = e*s + 1.128379165726710f;
        e = e*z;
    } else {
        e = erff(z);   // rare (pre-activations are tiny)
    }
    return v * (0.5f + 0.5f*e);
}

__device__ __forceinline__ void mma16(float* c, const uint32_t* a, const uint32_t* b) {
    asm volatile(
        "mma.sync.aligned.m16n8k16.row.col.f32.bf16.bf16.f32 "
        "{%0,%1,%2,%3},{%4,%5,%6,%7},{%8,%9},{%0,%1,%2,%3};"
        : "+f"(c[0]), "+f"(c[1]), "+f"(c[2]), "+f"(c[3])
        : "r"(a[0]), "r"(a[1]), "r"(a[2]), "r"(a[3]), "r"(b[0]), "r"(b[1]));
}

// Stage prepacked 128x128 bf16 weight (contiguous) -> smem [128][136]
__device__ __forceinline__ void stage_wb(const __nv_bfloat16* __restrict__ Wb,
                                         __nv_bfloat16* __restrict__ sW, int tid) {
    const uint4* src = (const uint4*)Wb;
    #pragma unroll
    for (int i = tid; i < 2048; i += 256) {
        int row = i >> 4, c8 = (i & 15) << 3;
        *(uint4*)(sW + row*136 + c8) = src[i];
    }
}

// 64x128 GEMM tile, K=128, bf16 in, fp32 accum. 8 warps, each 32x32.
__device__ __forceinline__ void mma_gemm_bf(const __nv_bfloat16* __restrict__ sA, int strideA,
                                            const __nv_bfloat16* __restrict__ sW,
                                            float acc[2][4][4], int warp, int lane) {
    int g = lane >> 2, tg = lane & 3;
    int rb = (warp & 1) * 32 + g;
    int cb = (warp >> 1) * 32 + g;
    #pragma unroll
    for (int kt = 0; kt < 8; ++kt) {
        int k0 = kt * 16;
        uint32_t a[2][4];
        #pragma unroll
        for (int mt = 0; mt < 2; ++mt) {
            const __nv_bfloat16* ar = sA + (rb + mt*16)*strideA + k0 + 2*tg;
            a[mt][0] = *(const uint32_t*)(ar);
            a[mt][1] = *(const uint32_t*)(ar + 8*strideA);
            a[mt][2] = *(const uint32_t*)(ar + 8);
            a[mt][3] = *(const uint32_t*)(ar + 8*strideA + 8);
        }
        #pragma unroll
        for (int nt = 0; nt < 4; ++nt) {
            const __nv_bfloat16* wr = sW + (cb + nt*8)*136 + k0 + 2*tg;
            uint32_t b[2];
            b[0] = *(const uint32_t*)(wr);
            b[1] = *(const uint32_t*)(wr + 8);
            #pragma unroll
            for (int mt = 0; mt < 2; ++mt)
                mma16(acc[mt][nt], a[mt], b);
        }
    }
}

// ---------------- K0: fuse convp + pw1 (fp32) ----------------
__global__ void k_fuse(const float* __restrict__ convp_w, const float* __restrict__ convp_b,
                       const float* __restrict__ pw1_w,   const float* __restrict__ pw1_b) {
    int gid = blockIdx.x*256 + threadIdx.x;
    int o = gid >> 7, i = gid & 127;
    float s = 0.f;
    for (int c = 0; c < CCH; ++c) s += pw1_w[o*CCH + c] * convp_w[c*CCH + i];
    g_Wc[o*CCH + i] = s;
    if (gid < CCH) {
        float b = pw1_b[gid];
        for (int c = 0; c < CCH; ++c) b += pw1_w[gid*CCH + c] * convp_b[c];
        g_bc[gid] = b;
    }
}

// ---------------- K0b: pack all GEMM weights to bf16 bank ----------------
__global__ void k_prep(const float* __restrict__ qkv_w, const float* __restrict__ out_w,
                       const float* __restrict__ tok_w, const float* __restrict__ lpw_w,
                       const float* __restrict__ fc1_w, const float* __restrict__ fc2_w) {
    int idx = blockIdx.x*256 + threadIdx.x;       // 960 blocks -> 245760
    int blk = idx >> 14;
    int m = idx & 16383;
    int c = m >> 7, k = m & 127;
    float v;
    if      (blk < 3)  v = qkv_w[blk*16384 + m];
    else if (blk == 3) v = g_Wc[m];
    else if (blk == 4) v = out_w[m];
    else if (blk == 5) v = tok_w[m];
    else if (blk == 6) v = lpw_w[m];
    else if (blk < 11) v = fc1_w[(blk-7)*16384 + m];
    else               v = fc2_w[c*512 + (blk-11)*128 + k];
    g_wbf[idx] = __float2bfloat16(v);
}

// ---------------- LN1: NCHW -> layernorm -> bf16 window-token layout ----------------
__global__ void k_ln1(const float* __restrict__ x, const float* __restrict__ w,
                      const float* __restrict__ b) {
    __shared__ float s[64*129];
    __shared__ float s_mu[64], s_rs[64];
    int tid = threadIdx.x, bid = blockIdx.x;
    int w0 = (bid & 3) * 64;
    int h  = (bid >> 2) & 255;
    int bb = bid >> 10;
    const float* xb = x + (size_t)bb*CCH*65536 + h*256 + w0;
    for (int idx = tid; idx < 8192; idx += 256) {
        int c = idx >> 6, p = idx & 63;
        s[p*129 + c] = xb[c*65536 + p];
    }
    __syncthreads();
    int p = tid >> 2, q = tid & 3;
    float sm = 0.f, sq = 0.f;
    #pragma unroll
    for (int i = 0; i < 32; ++i) { float v = s[p*129 + q*32 + i]; sm += v; sq += v*v; }
    sm += __shfl_xor_sync(0xffffffffu, sm, 1); sq += __shfl_xor_sync(0xffffffffu, sq, 1);
    sm += __shfl_xor_sync(0xffffffffu, sm, 2); sq += __shfl_xor_sync(0xffffffffu, sq, 2);
    if (q == 0) {
        float mu = sm * (1.f/128.f);
        float var = sq * (1.f/128.f) - mu*mu;
        s_mu[p] = mu; s_rs[p] = rsqrtf(var + 1e-5f);
    }
    __syncthreads();
    uint32_t* yw = (uint32_t*)g_y;
    for (int idx = tid; idx < 4096; idx += 256) {
        int pp = idx >> 6, cw = idx & 63;
        int c0 = cw*2;
        int wc = w0 + pp;
        int win = (bb*32 + (h >> 3))*32 + (wc >> 3);
        int n   = (h & 7)*8 + (wc & 7);
        float mu = s_mu[pp], rs = s_rs[pp];
        float v0 = (s[pp*129 + c0]   - mu) * rs * w[c0]   + b[c0];
        float v1 = (s[pp*129 + c0+1] - mu) * rs * w[c0+1] + b[c0+1];
        yw[(size_t)win*4096 + n*64 + cw] = bf2(v0, v1);
    }
}

// ---------------- ReMSA: one CTA per 8x8 window ----------------
__global__ void k_remsa(const float* __restrict__ qkv_b, const float* __restrict__ pos_bias,
                        const float* __restrict__ out_b, const float* __restrict__ tok_b,
                        const float* __restrict__ dw1_w, const float* __restrict__ dw1_b) {
    extern __shared__ __align__(16) char smem[];
    float* s_big = (float*)smem;                                    // 64*516 fp32
    __nv_bfloat16* s_y = (__nv_bfloat16*)(smem + 132096);           // 64*136
    __nv_bfloat16* s_c = (__nv_bfloat16*)(smem + 132096 + 17408);   // 64*136
    __nv_bfloat16* s_W = (__nv_bfloat16*)(smem + 132096 + 34816);   // 128*136
    int tid = threadIdx.x, warp = tid >> 5, lane = tid & 31;
    int win = blockIdx.x;

    const uint32_t* yw = (const uint32_t*)g_y + (size_t)win*4096;
    uint32_t* s_yw = (uint32_t*)s_y;
    for (int idx = tid; idx < 4096; idx += 256) {
        int n = idx >> 6, cw = idx & 63;
        s_yw[n*68 + cw] = yw[idx];
    }

    int g = lane >> 2, tg = lane & 3;
    int rbase = (warp & 1) * 32 + g;
    int cbase = (warp >> 1) * 32;

    // Phase A: [qkv ; Wc] GEMM (64 x 512)
    for (int chunk = 0; chunk < 4; ++chunk) {
        __syncthreads();
        stage_wb(g_wbf + chunk*16384, s_W, tid);
        __syncthreads();
        float acc[2][4][4] = {};
        mma_gemm_bf(s_y, 136, s_W, acc, warp, lane);
        const float* bsrc = (chunk < 3) ? (qkv_b + chunk*128) : g_bc;
        #pragma unroll
        for (int mt = 0; mt < 2; ++mt)
            #pragma unroll
            for (int nt = 0; nt < 4; ++nt) {
                int r0 = rbase + mt*16;
                int c0 = cbase + nt*8 + 2*tg;
                float b0 = bsrc[c0], b1 = bsrc[c0+1];
                *(float2*)&s_big[ r0   *516 + chunk*128 + c0] =
                    make_float2(acc[mt][nt][0] + b0, acc[mt][nt][1] + b1);
                *(float2*)&s_big[(r0+8)*516 + chunk*128 + c0] =
                    make_float2(acc[mt][nt][2] + b0, acc[mt][nt][3] + b1);
            }
    }
    __syncthreads();

    // Phase B: head-mixing attention (4 threads/token, 2 heads each); ao -> s_y (bf16)
    {
        int n = tid >> 2, q4 = tid & 3;
        const float* base = s_big + n*516;
        const float* pb = pos_bias + n*64;
        uint32_t* aw = (uint32_t*)s_y;
        #pragma unroll
        for (int hh = 0; hh < 2; ++hh) {
            int hI = q4*2 + hh;
            const float* qp = base + hI*48;
            float sc[8]; float mx = -1e30f;
            #pragma unroll
            for (int gg = 0; gg < 8; ++gg) {
                const float* kp = base + gg*48 + 16;
                float sd = 0.f;
                #pragma unroll
                for (int d = 0; d < 16; ++d) sd += qp[d]*kp[d];
                sc[gg] = sd*0.25f + pb[hI*8 + gg];
                mx = fmaxf(mx, sc[gg]);
            }
            float ssum = 0.f;
            #pragma unroll
            for (int gg = 0; gg < 8; ++gg) { sc[gg] = __expf(sc[gg] - mx); ssum += sc[gg]; }
            float inv = 1.f / ssum;
            float ao[16];
            #pragma unroll
            for (int d = 0; d < 16; ++d) ao[d] = 0.f;
            #pragma unroll
            for (int gg = 0; gg < 8; ++gg) {
                float a = sc[gg]*inv;
                const float* vp = base + gg*48 + 32;
                #pragma unroll
                for (int d = 0; d < 16; ++d) ao[d] += a*vp[d];
            }
            #pragma unroll
            for (int d = 0; d < 16; d += 2)
                aw[n*68 + hI*8 + (d >> 1)] = bf2(ao[d], ao[d+1]);
        }
    }

    // Phase C: token-dim depthwise conv on xc (s_big cols 384..511) -> s_c (bf16)
    {
        uint32_t* cw32 = (uint32_t*)s_c;
        for (int idx = tid; idx < 4096; idx += 256) {
            int n = idx >> 6, cw = idx & 63;
            int c0 = cw*2;
            const float* col = s_big + 384;
            float a0, a1, a2, b0, b1, b2;
            a1 = col[n*516 + c0];     b1 = col[n*516 + c0 + 1];
            a0 = (n > 0)  ? col[(n-1)*516 + c0]     : 0.f;
            b0 = (n > 0)  ? col[(n-1)*516 + c0 + 1] : 0.f;
            a2 = (n < 63) ? col[(n+1)*516 + c0]     : 0.f;
            b2 = (n < 63) ? col[(n+1)*516 + c0 + 1] : 0.f;
            float d0 = a0*dw1_w[c0*3] + a1*dw1_w[c0*3+1] + a2*dw1_w[c0*3+2] + dw1_b[c0];
            float d1 = b0*dw1_w[c0*3+3] + b1*dw1_w[c0*3+4] + b2*dw1_w[c0*3+5] + dw1_b[c0+1];
            cw32[n*68 + cw] = bf2(d0, d1);
        }
    }
    __syncthreads();

    // Phase D: ao @ out_w^T + d1 @ tok_w^T
    float acc[2][4][4] = {};
    stage_wb(g_wbf + 4*16384, s_W, tid);
    __syncthreads();
    mma_gemm_bf(s_y, 136, s_W, acc, warp, lane);
    __syncthreads();
    stage_wb(g_wbf + 5*16384, s_W, tid);
    __syncthreads();
    mma_gemm_bf(s_c, 136, s_W, acc, warp, lane);
    float* ob = g_att + (size_t)win*8192;
    #pragma unroll
    for (int mt = 0; mt < 2; ++mt)
        #pragma unroll
        for (int nt = 0; nt < 4; ++nt) {
            int r0 = rbase + mt*16;
            int c0 = cbase + nt*8 + 2*tg;
            float b0 = out_b[c0] + tok_b[c0], b1 = out_b[c0+1] + tok_b[c0+1];
            *(float2*)&ob[ r0   *128 + c0] =
                make_float2(acc[mt][nt][0] + b0, acc[mt][nt][1] + b1);
            *(float2*)&ob[(r0+8)*128 + c0] =
                make_float2(acc[mt][nt][2] + b0, acc[mt][nt][3] + b1);
        }
}

// ---------------- LN2 + lpw fused ----------------
__global__ void k_ln2z(const float* __restrict__ x, const float* __restrict__ w,
                       const float* __restrict__ b) {
    extern __shared__ __align__(16) char smem[];
    float* s = (float*)smem;                                      // 64*129 fp32
    __nv_bfloat16* s_A = (__nv_bfloat16*)(smem + 33024);          // 64*136
    __nv_bfloat16* s_W = (__nv_bfloat16*)(smem + 33024 + 17408);  // 128*136
    __shared__ float s_mu[64], s_rs[64];
    int tid = threadIdx.x, bid = blockIdx.x;
    int warp = tid >> 5, lane = tid & 31;
    int w0 = (bid & 3) * 64;
    int h  = (bid >> 2) & 255;
    int bb = bid >> 10;
    const float* xb = x + (size_t)bb*CCH*65536 + h*256 + w0;
    for (int idx = tid; idx < 8192; idx += 256) {
        int c = idx >> 6, p = idx & 63;
        s[p*129 + c] = xb[c*65536 + p];
    }
    stage_wb(g_wbf + 6*16384, s_W, tid);
    __syncthreads();
    for (int idx = tid; idx < 8192; idx += 256) {
        int pp = idx >> 7, c = idx & 127;
        int wc = w0 + pp;
        int win = (bb*32 + (h >> 3))*32 + (wc >> 3);
        int n   = (h & 7)*8 + (wc & 7);
        float v = s[pp*129 + c] + g_att[(size_t)win*8192 + n*128 + c];
        s[pp*129 + c] = v;
        g_x1[((size_t)(bb*65536 + h*256 + wc))*128 + c] = v;
    }
    __syncthreads();
    int p = tid >> 2, q = tid & 3;
    float sm = 0.f, sq = 0.f;
    #pragma unroll
    for (int i = 0; i < 32; ++i) { float v = s[p*129 + q*32 + i]; sm += v; sq += v*v; }
    sm += __shfl_xor_sync(0xffffffffu, sm, 1); sq += __shfl_xor_sync(0xffffffffu, sq, 1);
    sm += __shfl_xor_sync(0xffffffffu, sm, 2); sq += __shfl_xor_sync(0xffffffffu, sq, 2);
    if (q == 0) {
        float mu = sm * (1.f/128.f);
        float var = sq * (1.f/128.f) - mu*mu;
        s_mu[p] = mu; s_rs[p] = rsqrtf(var + 1e-5f);
    }
    __syncthreads();
    uint32_t* aw = (uint32_t*)s_A;
    for (int idx = tid; idx < 4096; idx += 256) {
        int pp = idx >> 6, cw = idx & 63;
        int c0 = cw*2;
        float mu = s_mu[pp], rs = s_rs[pp];
        float v0 = (s[pp*129 + c0]   - mu) * rs * w[c0]   + b[c0];
        float v1 = (s[pp*129 + c0+1] - mu) * rs * w[c0+1] + b[c0+1];
        aw[pp*68 + cw] = bf2(v0, v1);
    }
    __syncthreads();
    float acc[2][4][4] = {};
    mma_gemm_bf(s_A, 136, s_W, acc, warp, lane);
    int g = lane >> 2, tg = lane & 3;
    int rbase = (warp & 1) * 32 + g;
    int cbase = (warp >> 1) * 32;
    size_t pixb = (size_t)(bb*65536 + h*256 + w0);
    uint32_t* zw = (uint32_t*)g_z;
    #pragma unroll
    for (int mt = 0; mt < 2; ++mt)
        #pragma unroll
        for (int nt = 0; nt < 4; ++nt) {
            int r0 = rbase + mt*16;
            int c0 = cbase + nt*8 + 2*tg;
            zw[(pixb + r0)  *64 + (c0 >> 1)] = bf2(acc[mt][nt][0], acc[mt][nt][1]);
            zw[(pixb + r0+8)*64 + (c0 >> 1)] = bf2(acc[mt][nt][2], acc[mt][nt][3]);
        }
}

// ---------------- LeFF ----------------
__global__ void k_leff(const float* __restrict__ ldw_w, const float* __restrict__ ldw_b,
                       const float* __restrict__ fc1_b, const float* __restrict__ fc2_b,
                       float* __restrict__ out) {
    extern __shared__ __align__(16) char smem[];
    __nv_bfloat16* s_d = (__nv_bfloat16*)smem;                   // 64*136
    __nv_bfloat16* s_t = (__nv_bfloat16*)(smem + 17408);         // 64*136
    __nv_bfloat16* s_W = (__nv_bfloat16*)(smem + 34816);         // 128*136
    float* s_f = (float*)(smem + 34816);                         // aliases s_W
    int tid = threadIdx.x, warp = tid >> 5, lane = tid & 31, bid = blockIdx.x;
    int w0 = (bid & 3) * 64;
    int h  = (bid >> 2) & 255;
    int bb = bid >> 10;

    // 3x3 depthwise over g_z (bf16 channels-last), zero padding
    {
        const uint32_t* zw = (const uint32_t*)g_z;
        uint32_t* dw = (uint32_t*)s_d;
        for (int idx = tid; idx < 4096; idx += 256) {
            int p = idx >> 6, cw = idx & 63;
            int c0 = cw*2;
            int xx0 = w0 + p;
            float accA = ldw_b[c0], accB = ldw_b[c0+1];
            #pragma unroll
            for (int dy = 0; dy < 3; ++dy) {
                int yy = h + dy - 1;
                if (yy < 0 || yy > 255) continue;
                #pragma unroll
                for (int dx = 0; dx < 3; ++dx) {
                    int xx = xx0 + dx - 1;
                    if (xx < 0 || xx > 255) continue;
                    uint32_t word = zw[((size_t)(bb*65536 + yy*256 + xx))*64 + cw];
                    __nv_bfloat162 t = *reinterpret_cast<__nv_bfloat162*>(&word);
                    accA += __bfloat162float(t.x) * ldw_w[c0*9     + dy*3 + dx];
                    accB += __bfloat162float(t.y) * ldw_w[(c0+1)*9 + dy*3 + dx];
                }
            }
            dw[p*68 + cw] = bf2(accA, accB);
        }
    }

    int g = lane >> 2, tg = lane & 3;
    int rbase = (warp & 1) * 32 + g;
    int cbase = (warp >> 1) * 32;
    float oacc[2][4][4] = {};
    for (int jc = 0; jc < 4; ++jc) {
        __syncthreads();
        stage_wb(g_wbf + (7+jc)*16384, s_W, tid);
        __syncthreads();
        float tacc[2][4][4] = {};
        mma_gemm_bf(s_d, 136, s_W, tacc, warp, lane);
        uint32_t* tw = (uint32_t*)s_t;
        #pragma unroll
        for (int mt = 0; mt < 2; ++mt)
            #pragma unroll
            for (int nt = 0; nt < 4; ++nt) {
                int r0 = rbase + mt*16;
                int c0 = cbase + nt*8 + 2*tg;
                float b0 = fc1_b[jc*128 + c0], b1 = fc1_b[jc*128 + c0 + 1];
                float v0 = gelu_f(tacc[mt][nt][0] + b0);
                float v1 = gelu_f(tacc[mt][nt][1] + b1);
                float v2 = gelu_f(tacc[mt][nt][2] + b0);
                float v3 = gelu_f(tacc[mt][nt][3] + b1);
                tw[ r0   *68 + (c0 >> 1)] = bf2(v0, v1);
                tw[(r0+8)*68 + (c0 >> 1)] = bf2(v2, v3);
            }
        __syncthreads();
        stage_wb(g_wbf + (11+jc)*16384, s_W, tid);
        __syncthreads();
        mma_gemm_bf(s_t, 136, s_W, oacc, warp, lane);
    }
    __syncthreads();   // done reading s_W before aliasing as s_f

    // epilogue: + fc2_b + residual x1 (fp32), stage fp32, transpose-write NCHW
    size_t pixb = (size_t)(bb*65536 + h*256 + w0);
    #pragma unroll
    for (int mt = 0; mt < 2; ++mt)
        #pragma unroll
        for (int nt = 0; nt < 4; ++nt) {
            int r0 = rbase + mt*16;
            int c0 = cbase + nt*8 + 2*tg;
            float b0 = fc2_b[c0], b1 = fc2_b[c0+1];
            float2 x0 = *(const float2*)&g_x1[(pixb + r0)  *128 + c0];
            float2 x1 = *(const float2*)&g_x1[(pixb + r0+8)*128 + c0];
            s_f[ r0   *129 + c0]     = oacc[mt][nt][0] + b0 + x0.x;
            s_f[ r0   *129 + c0 + 1] = oacc[mt][nt][1] + b1 + x0.y;
            s_f[(r0+8)*129 + c0]     = oacc[mt][nt][2] + b0 + x1.x;
            s_f[(r0+8)*129 + c0 + 1] = oacc[mt][nt][3] + b1 + x1.y;
        }
    __syncthreads();
    for (int idx = tid; idx < 8192; idx += 256) {
        int c = idx >> 6, p = idx & 63;
        out[((size_t)(bb*128 + c)*256 + h)*256 + w0 + p] = s_f[p*129 + c];
    }
}

// ---------------- launch ----------------
extern "C" void kernel_launch(void* const* d_in, const int* in_sizes, int n_in,
                              void* d_out, int out_size) {
    const float* x        = (const float*)d_in[0];
    const float* norm1_w  = (const float*)d_in[1];
    const float* norm1_b  = (const float*)d_in[2];
    const float* qkv_w    = (const float*)d_in[3];
    const float* qkv_b    = (const float*)d_in[4];
    const float* pos_bias = (const float*)d_in[5];
    const float* out_w    = (const float*)d_in[6];
    const float* out_b    = (const float*)d_in[7];
    const float* convp_w  = (const float*)d_in[8];
    const float* convp_b  = (const float*)d_in[9];
    const float* pw1_w    = (const float*)d_in[10];
    const float* pw1_b    = (const float*)d_in[11];
    const float* dw1_w    = (const float*)d_in[12];
    const float* dw1_b    = (const float*)d_in[13];
    const float* tok_w    = (const float*)d_in[14];
    const float* tok_b    = (const float*)d_in[15];
    const float* norm2_w  = (const float*)d_in[16];
    const float* norm2_b  = (const float*)d_in[17];
    const float* lpw_w    = (const float*)d_in[18];
    const float* ldw_w    = (const float*)d_in[19];
    const float* ldw_b    = (const float*)d_in[20];
    const float* fc1_w    = (const float*)d_in[21];
    const float* fc1_b    = (const float*)d_in[22];
    const float* fc2_w    = (const float*)d_in[23];
    const float* fc2_b    = (const float*)d_in[24];
    float* out = (float*)d_out;

    const int SM_REMSA = 132096 + 17408 + 17408 + 34816;   // 201728
    const int SM_LN2Z  = 33024 + 17408 + 34816;            //  85248
    const int SM_LEFF  = 17408 + 17408 + 34816;            //  69632
    cudaFuncSetAttribute(k_remsa, cudaFuncAttributeMaxDynamicSharedMemorySize, SM_REMSA);
    cudaFuncSetAttribute(k_ln2z,  cudaFuncAttributeMaxDynamicSharedMemorySize, SM_LN2Z);
    cudaFuncSetAttribute(k_leff,  cudaFuncAttributeMaxDynamicSharedMemorySize, SM_LEFF);

    k_fuse <<<64,   256>>>(convp_w, convp_b, pw1_w, pw1_b);
    k_prep <<<960,  256>>>(qkv_w, out_w, tok_w, lpw_w, fc1_w, fc2_w);
    k_ln1  <<<4096, 256>>>(x, norm1_w, norm1_b);
    k_remsa<<<4096, 256, SM_REMSA>>>(qkv_b, pos_bias, out_b, tok_b, dw1_w, dw1_b);
    k_ln2z <<<4096, 256, SM_LN2Z>>>(x, norm2_w, norm2_b);
    k_leff <<<4096, 256, SM_LEFF>>>(ldw_w, ldw_b, fc1_b, fc2_b, out);
}

// round 6
// speedup vs baseline: 3.3181x; 1.1322x over previous
#include <cuda_runtime.h>
#include <cuda_bf16.h>
#include <cstdint>
#include <math.h>

#define BATCH 4
#define CCH 128
#define NPIX (BATCH*256*256)     /* 262144 */
#define NWIN (NPIX/64)           /* 4096 */

// ---------------- device scratch ----------------
__device__ float g_Wc[CCH*CCH];
__device__ float g_bc[CCH];
// bf16 weight bank: [0..2]=qkv, [3]=Wc, [4]=out_w, [5]=tok_w, [6]=lpw,
// [7..10]=fc1 chunks, [11..14]=fc2 chunks. Each 128x128 row-major.
__device__ __nv_bfloat16 g_wbf[15*16384];
__device__ __nv_bfloat16 g_y[NPIX*CCH];   // LN1 out, window-token layout
__device__ float g_att[NPIX*CCH];         // remsa out fp32, window-token layout
__device__ float g_x1[NPIX*CCH];          // x + merged attn, channels-last fp32
__device__ __nv_bfloat16 g_z[NPIX*CCH];   // lpw out, channels-last bf16

// ---------------- helpers ----------------
__device__ __forceinline__ uint32_t bf2(float a, float b) {
    __nv_bfloat162 t = __floats2bfloat162_rn(a, b);
    return *reinterpret_cast<uint32_t*>(&t);
}
__device__ __forceinline__ float2 ubf2f(uint32_t w) {
    __nv_bfloat162 t = *reinterpret_cast<__nv_bfloat162*>(&w);
    return make_float2(__bfloat162float(t.x), __bfloat162float(t.y));
}

// exact-GELU via FMA-only erf polynomial (|z|<=1); rare tail uses erff
__device__ __forceinline__ float gelu_f(float v) {
    float z = v * 0.7071067811865475f;
    float e;
    if (fabsf(z) <= 1.0f) {
        float s = z*z;
        e = 7.853861595399774e-5f;
        e = e*s - 8.010193625184903e-4f;
        e = e*s + 5.188327685732524e-3f;
        e = e*s - 2.685381193529856e-2f;
        e = e*s + 1.128358514861418e-1f;
        e = e*s - 3.761262582423300e-1f;
        e = e*s + 1.128379165726710f;
        e = e*z;
    } else {
        e = erff(z);
    }
    return v * (0.5f + 0.5f*e);
}

__device__ __forceinline__ void mma16(float* c, const uint32_t* a, const uint32_t* b) {
    asm volatile(
        "mma.sync.aligned.m16n8k16.row.col.f32.bf16.bf16.f32 "
        "{%0,%1,%2,%3},{%4,%5,%6,%7},{%8,%9},{%0,%1,%2,%3};"
        : "+f"(c[0]), "+f"(c[1]), "+f"(c[2]), "+f"(c[3])
        : "r"(a[0]), "r"(a[1]), "r"(a[2]), "r"(a[3]), "r"(b[0]), "r"(b[1]));
}

// Stage prepacked 128x128 bf16 weight -> smem [128][136]; 512 threads
__device__ __forceinline__ void stage_wb512(const __nv_bfloat16* __restrict__ Wb,
                                            __nv_bfloat16* __restrict__ sW, int tid) {
    const uint4* src = (const uint4*)Wb;
    #pragma unroll
    for (int i = tid; i < 2048; i += 512) {
        int row = i >> 4, c8 = (i & 15) << 3;
        *(uint4*)(sW + row*136 + c8) = src[i];
    }
}

// 128x128 GEMM tile, K=128, bf16 in, fp32 accum. 16 warps, each 32x32.
__device__ __forceinline__ void mma_gemm16(const __nv_bfloat16* __restrict__ sA, int strideA,
                                           const __nv_bfloat16* __restrict__ sW,
                                           float acc[2][4][4], int warp, int lane) {
    int g = lane >> 2, tg = lane & 3;
    int rb = (warp & 3) * 32 + g;
    int cb = (warp >> 2) * 32 + g;
    #pragma unroll
    for (int kt = 0; kt < 8; ++kt) {
        int k0 = kt * 16;
        uint32_t a[2][4];
        #pragma unroll
        for (int mt = 0; mt < 2; ++mt) {
            const __nv_bfloat16* ar = sA + (rb + mt*16)*strideA + k0 + 2*tg;
            a[mt][0] = *(const uint32_t*)(ar);
            a[mt][1] = *(const uint32_t*)(ar + 8*strideA);
            a[mt][2] = *(const uint32_t*)(ar + 8);
            a[mt][3] = *(const uint32_t*)(ar + 8*strideA + 8);
        }
        #pragma unroll
        for (int nt = 0; nt < 4; ++nt) {
            const __nv_bfloat16* wr = sW + (cb + nt*8)*136 + k0 + 2*tg;
            uint32_t b[2];
            b[0] = *(const uint32_t*)(wr);
            b[1] = *(const uint32_t*)(wr + 8);
            #pragma unroll
            for (int mt = 0; mt < 2; ++mt)
                mma16(acc[mt][nt], a[mt], b);
        }
    }
}

// ---------------- K0: fuse convp + pw1 ----------------
__global__ void k_fuse(const float* __restrict__ convp_w, const float* __restrict__ convp_b,
                       const float* __restrict__ pw1_w,   const float* __restrict__ pw1_b) {
    int gid = blockIdx.x*256 + threadIdx.x;
    int o = gid >> 7, i = gid & 127;
    float s = 0.f;
    for (int c = 0; c < CCH; ++c) s += pw1_w[o*CCH + c] * convp_w[c*CCH + i];
    g_Wc[o*CCH + i] = s;
    if (gid < CCH) {
        float b = pw1_b[gid];
        for (int c = 0; c < CCH; ++c) b += pw1_w[gid*CCH + c] * convp_b[c];
        g_bc[gid] = b;
    }
}

// ---------------- K0b: pack weights to bf16 bank ----------------
__global__ void k_prep(const float* __restrict__ qkv_w, const float* __restrict__ out_w,
                       const float* __restrict__ tok_w, const float* __restrict__ lpw_w,
                       const float* __restrict__ fc1_w, const float* __restrict__ fc2_w) {
    int idx = blockIdx.x*256 + threadIdx.x;
    int blk = idx >> 14;
    int m = idx & 16383;
    int c = m >> 7, k = m & 127;
    float v;
    if      (blk < 3)  v = qkv_w[blk*16384 + m];
    else if (blk == 3) v = g_Wc[m];
    else if (blk == 4) v = out_w[m];
    else if (blk == 5) v = tok_w[m];
    else if (blk == 6) v = lpw_w[m];
    else if (blk < 11) v = fc1_w[(blk-7)*16384 + m];
    else               v = fc2_w[c*512 + (blk-11)*128 + k];
    g_wbf[idx] = __float2bfloat16(v);
}

// ---------------- LN1 ----------------
__global__ void k_ln1(const float* __restrict__ x, const float* __restrict__ w,
                      const float* __restrict__ b) {
    __shared__ float s[64*129];
    __shared__ float s_mu[64], s_rs[64];
    int tid = threadIdx.x, bid = blockIdx.x;
    int w0 = (bid & 3) * 64;
    int h  = (bid >> 2) & 255;
    int bb = bid >> 10;
    const float* xb = x + (size_t)bb*CCH*65536 + h*256 + w0;
    for (int idx = tid; idx < 8192; idx += 256) {
        int c = idx >> 6, p = idx & 63;
        s[p*129 + c] = xb[c*65536 + p];
    }
    __syncthreads();
    int p = tid >> 2, q = tid & 3;
    float sm = 0.f, sq = 0.f;
    #pragma unroll
    for (int i = 0; i < 32; ++i) { float v = s[p*129 + q*32 + i]; sm += v; sq += v*v; }
    sm += __shfl_xor_sync(0xffffffffu, sm, 1); sq += __shfl_xor_sync(0xffffffffu, sq, 1);
    sm += __shfl_xor_sync(0xffffffffu, sm, 2); sq += __shfl_xor_sync(0xffffffffu, sq, 2);
    if (q == 0) {
        float mu = sm * (1.f/128.f);
        float var = sq * (1.f/128.f) - mu*mu;
        s_mu[p] = mu; s_rs[p] = rsqrtf(var + 1e-5f);
    }
    __syncthreads();
    uint32_t* yw = (uint32_t*)g_y;
    for (int idx = tid; idx < 4096; idx += 256) {
        int pp = idx >> 6, cw = idx & 63;
        int c0 = cw*2;
        int wc = w0 + pp;
        int win = (bb*32 + (h >> 3))*32 + (wc >> 3);
        int n   = (h & 7)*8 + (wc & 7);
        float mu = s_mu[pp], rs = s_rs[pp];
        float v0 = (s[pp*129 + c0]   - mu) * rs * w[c0]   + b[c0];
        float v1 = (s[pp*129 + c0+1] - mu) * rs * w[c0+1] + b[c0+1];
        yw[(size_t)win*4096 + n*64 + cw] = bf2(v0, v1);
    }
}

// ---------------- ReMSA: 2 windows per CTA, 512 threads ----------------
__global__ void k_remsa(const float* __restrict__ qkv_b, const float* __restrict__ pos_bias,
                        const float* __restrict__ out_b, const float* __restrict__ tok_b,
                        const float* __restrict__ dw1_w, const float* __restrict__ dw1_b) {
    extern __shared__ __align__(16) char smem[];
    __nv_bfloat16* s_qkv = (__nv_bfloat16*)smem;                   // 128*520 bf16
    __nv_bfloat16* s_y   = (__nv_bfloat16*)(smem + 133120);        // 128*136 (LN1 / ao)
    __nv_bfloat16* s_W   = (__nv_bfloat16*)(smem + 133120 + 34816);
    int tid = threadIdx.x, warp = tid >> 5, lane = tid & 31;
    int win0 = blockIdx.x * 2;

    const uint32_t* yw = (const uint32_t*)g_y + (size_t)win0*4096;
    uint32_t* s_yw = (uint32_t*)s_y;
    for (int idx = tid; idx < 8192; idx += 512) {
        int r = idx >> 6, cw = idx & 63;
        s_yw[r*68 + cw] = yw[idx];
    }

    int g = lane >> 2, tg = lane & 3;
    int rbase = (warp & 3) * 32 + g;
    int cbase = (warp >> 2) * 32;
    uint32_t* qw = (uint32_t*)s_qkv;   // stride 260 words per row

    // Phase A: [qkv ; Wc] GEMM (128 x 512) -> s_qkv bf16
    for (int chunk = 0; chunk < 4; ++chunk) {
        __syncthreads();
        stage_wb512(g_wbf + chunk*16384, s_W, tid);
        __syncthreads();
        float acc[2][4][4] = {};
        mma_gemm16(s_y, 136, s_W, acc, warp, lane);
        const float* bsrc = (chunk < 3) ? (qkv_b + chunk*128) : g_bc;
        #pragma unroll
        for (int mt = 0; mt < 2; ++mt)
            #pragma unroll
            for (int nt = 0; nt < 4; ++nt) {
                int r0 = rbase + mt*16;
                int c0 = cbase + nt*8 + 2*tg;
                float b0 = bsrc[c0], b1 = bsrc[c0+1];
                int off = chunk*64 + (c0 >> 1);
                qw[ r0   *260 + off] = bf2(acc[mt][nt][0] + b0, acc[mt][nt][1] + b1);
                qw[(r0+8)*260 + off] = bf2(acc[mt][nt][2] + b0, acc[mt][nt][3] + b1);
            }
    }
    __syncthreads();

    // Phase B: head-mixing attention; 4 threads/token, 2 heads each; ao -> s_y
    {
        int r = tid >> 2, q4 = tid & 3, n = r & 63;
        const uint32_t* base = qw + r*260;   // head hI: words q=hI*24, k=+8, v=+16
        const float* pb = pos_bias + n*64;
        uint32_t* aw = (uint32_t*)s_y;
        #pragma unroll
        for (int hh = 0; hh < 2; ++hh) {
            int hI = q4*2 + hh;
            float qv[16];
            #pragma unroll
            for (int d = 0; d < 8; ++d) {
                float2 f = ubf2f(base[hI*24 + d]);
                qv[2*d] = f.x; qv[2*d+1] = f.y;
            }
            float sc[8]; float mx = -1e30f;
            #pragma unroll
            for (int gg = 0; gg < 8; ++gg) {
                const uint32_t* kp = base + gg*24 + 8;
                float sd = 0.f;
                #pragma unroll
                for (int d = 0; d < 8; ++d) {
                    float2 f = ubf2f(kp[d]);
                    sd += qv[2*d]*f.x + qv[2*d+1]*f.y;
                }
                sc[gg] = sd*0.25f + pb[hI*8 + gg];
                mx = fmaxf(mx, sc[gg]);
            }
            float ssum = 0.f;
            #pragma unroll
            for (int gg = 0; gg < 8; ++gg) { sc[gg] = __expf(sc[gg] - mx); ssum += sc[gg]; }
            float inv = 1.f / ssum;
            float ao[16];
            #pragma unroll
            for (int d = 0; d < 16; ++d) ao[d] = 0.f;
            #pragma unroll
            for (int gg = 0; gg < 8; ++gg) {
                float a = sc[gg]*inv;
                const uint32_t* vp = base + gg*24 + 16;
                #pragma unroll
                for (int d = 0; d < 8; ++d) {
                    float2 f = ubf2f(vp[d]);
                    ao[2*d]   += a*f.x;
                    ao[2*d+1] += a*f.y;
                }
            }
            #pragma unroll
            for (int d = 0; d < 8; ++d)
                aw[r*68 + hI*8 + d] = bf2(ao[2*d], ao[2*d+1]);
        }
    }

    // Phase C: token-dim dwconv on xc (words 192..255 per row); read->regs, sync, write cols 0..63
    uint32_t cres[16];
    #pragma unroll
    for (int it = 0; it < 16; ++it) {
        int idx = tid + it*512;
        int r = idx >> 6, cw = idx & 63, n = r & 63;
        int c0 = cw*2;
        float2 m  = ubf2f(qw[r*260 + 192 + cw]);
        float2 lo = make_float2(0.f, 0.f), hi = make_float2(0.f, 0.f);
        if (n > 0)  lo = ubf2f(qw[(r-1)*260 + 192 + cw]);
        if (n < 63) hi = ubf2f(qw[(r+1)*260 + 192 + cw]);
        float d0 = lo.x*dw1_w[c0*3]   + m.x*dw1_w[c0*3+1] + hi.x*dw1_w[c0*3+2] + dw1_b[c0];
        float d1 = lo.y*dw1_w[c0*3+3] + m.y*dw1_w[c0*3+4] + hi.y*dw1_w[c0*3+5] + dw1_b[c0+1];
        cres[it] = bf2(d0, d1);
    }
    __syncthreads();
    #pragma unroll
    for (int it = 0; it < 16; ++it) {
        int idx = tid + it*512;
        qw[(idx >> 6)*260 + (idx & 63)] = cres[it];
    }
    __syncthreads();

    // Phase D: ao @ out_w^T + dconv @ tok_w^T
    float acc[2][4][4] = {};
    stage_wb512(g_wbf + 4*16384, s_W, tid);
    __syncthreads();
    mma_gemm16(s_y, 136, s_W, acc, warp, lane);
    __syncthreads();
    stage_wb512(g_wbf + 5*16384, s_W, tid);
    __syncthreads();
    mma_gemm16(s_qkv, 520, s_W, acc, warp, lane);
    float* ob = g_att + (size_t)win0*8192;
    #pragma unroll
    for (int mt = 0; mt < 2; ++mt)
        #pragma unroll
        for (int nt = 0; nt < 4; ++nt) {
            int r0 = rbase + mt*16;
            int c0 = cbase + nt*8 + 2*tg;
            float b0 = out_b[c0] + tok_b[c0], b1 = out_b[c0+1] + tok_b[c0+1];
            *(float2*)&ob[ r0   *128 + c0] =
                make_float2(acc[mt][nt][0] + b0, acc[mt][nt][1] + b1);
            *(float2*)&ob[(r0+8)*128 + c0] =
                make_float2(acc[mt][nt][2] + b0, acc[mt][nt][3] + b1);
        }
}

// ---------------- LN2 + lpw fused: 128 pixels per CTA, 512 threads ----------------
__global__ void k_ln2z(const float* __restrict__ x, const float* __restrict__ w,
                       const float* __restrict__ b) {
    extern __shared__ __align__(16) char smem[];
    float* s = (float*)smem;                                      // 128*129 fp32
    __nv_bfloat16* s_A = (__nv_bfloat16*)(smem + 66048);          // 128*136
    __nv_bfloat16* s_W = (__nv_bfloat16*)(smem + 66048 + 34816);  // 128*136
    __shared__ float s_mu[128], s_rs[128];
    int tid = threadIdx.x, bid = blockIdx.x;
    int warp = tid >> 5, lane = tid & 31;
    int w0 = (bid & 1) * 128;
    int h  = (bid >> 1) & 255;
    int bb = bid >> 9;
    const float* xb = x + (size_t)bb*CCH*65536 + h*256 + w0;
    for (int idx = tid; idx < 16384; idx += 512) {
        int c = idx >> 7, p = idx & 127;
        s[p*129 + c] = xb[c*65536 + p];
    }
    stage_wb512(g_wbf + 6*16384, s_W, tid);
    __syncthreads();
    for (int idx = tid; idx < 16384; idx += 512) {
        int pp = idx >> 7, c = idx & 127;
        int wc = w0 + pp;
        int win = (bb*32 + (h >> 3))*32 + (wc >> 3);
        int n   = (h & 7)*8 + (wc & 7);
        float v = s[pp*129 + c] + g_att[(size_t)win*8192 + n*128 + c];
        s[pp*129 + c] = v;
        g_x1[((size_t)(bb*65536 + h*256 + wc))*128 + c] = v;
    }
    __syncthreads();
    int p = tid >> 2, q = tid & 3;
    float sm = 0.f, sq = 0.f;
    #pragma unroll
    for (int i = 0; i < 32; ++i) { float v = s[p*129 + q*32 + i]; sm += v; sq += v*v; }
    sm += __shfl_xor_sync(0xffffffffu, sm, 1); sq += __shfl_xor_sync(0xffffffffu, sq, 1);
    sm += __shfl_xor_sync(0xffffffffu, sm, 2); sq += __shfl_xor_sync(0xffffffffu, sq, 2);
    if (q == 0) {
        float mu = sm * (1.f/128.f);
        float var = sq * (1.f/128.f) - mu*mu;
        s_mu[p] = mu; s_rs[p] = rsqrtf(var + 1e-5f);
    }
    __syncthreads();
    uint32_t* aw = (uint32_t*)s_A;
    for (int idx = tid; idx < 8192; idx += 512) {
        int pp = idx >> 6, cw = idx & 63;
        int c0 = cw*2;
        float mu = s_mu[pp], rs = s_rs[pp];
        float v0 = (s[pp*129 + c0]   - mu) * rs * w[c0]   + b[c0];
        float v1 = (s[pp*129 + c0+1] - mu) * rs * w[c0+1] + b[c0+1];
        aw[pp*68 + cw] = bf2(v0, v1);
    }
    __syncthreads();
    float acc[2][4][4] = {};
    mma_gemm16(s_A, 136, s_W, acc, warp, lane);
    int g = lane >> 2, tg = lane & 3;
    int rbase = (warp & 3) * 32 + g;
    int cbase = (warp >> 2) * 32;
    size_t pixb = (size_t)(bb*65536 + h*256 + w0);
    uint32_t* zw = (uint32_t*)g_z;
    #pragma unroll
    for (int mt = 0; mt < 2; ++mt)
        #pragma unroll
        for (int nt = 0; nt < 4; ++nt) {
            int r0 = rbase + mt*16;
            int c0 = cbase + nt*8 + 2*tg;
            zw[(pixb + r0)  *64 + (c0 >> 1)] = bf2(acc[mt][nt][0], acc[mt][nt][1]);
            zw[(pixb + r0+8)*64 + (c0 >> 1)] = bf2(acc[mt][nt][2], acc[mt][nt][3]);
        }
}

// ---------------- LeFF: 128 pixels per CTA, 512 threads ----------------
__global__ void k_leff(const float* __restrict__ ldw_w, const float* __restrict__ ldw_b,
                       const float* __restrict__ fc1_b, const float* __restrict__ fc2_b,
                       float* __restrict__ out) {
    extern __shared__ __align__(16) char smem[];
    __nv_bfloat16* s_d = (__nv_bfloat16*)smem;                   // 128*136
    __nv_bfloat16* s_t = (__nv_bfloat16*)(smem + 34816);         // 128*136
    __nv_bfloat16* s_W = (__nv_bfloat16*)(smem + 69632);         // 128*136
    float* s_f = (float*)(smem + 34816);                         // aliases s_t+s_W
    int tid = threadIdx.x, warp = tid >> 5, lane = tid & 31, bid = blockIdx.x;
    int w0 = (bid & 1) * 128;
    int h  = (bid >> 1) & 255;
    int bb = bid >> 9;

    // 3x3 depthwise over g_z (bf16 channels-last), zero padding
    {
        const uint32_t* zw = (const uint32_t*)g_z;
        uint32_t* dw = (uint32_t*)s_d;
        for (int idx = tid; idx < 8192; idx += 512) {
            int p = idx >> 6, cw = idx & 63;
            int c0 = cw*2;
            int xx0 = w0 + p;
            float accA = ldw_b[c0], accB = ldw_b[c0+1];
            #pragma unroll
            for (int dy = 0; dy < 3; ++dy) {
                int yy = h + dy - 1;
                if (yy < 0 || yy > 255) continue;
                #pragma unroll
                for (int dx = 0; dx < 3; ++dx) {
                    int xx = xx0 + dx - 1;
                    if (xx < 0 || xx > 255) continue;
                    float2 t = ubf2f(zw[((size_t)(bb*65536 + yy*256 + xx))*64 + cw]);
                    accA += t.x * ldw_w[c0*9     + dy*3 + dx];
                    accB += t.y * ldw_w[(c0+1)*9 + dy*3 + dx];
                }
            }
            dw[p*68 + cw] = bf2(accA, accB);
        }
    }

    int g = lane >> 2, tg = lane & 3;
    int rbase = (warp & 3) * 32 + g;
    int cbase = (warp >> 2) * 32;
    float oacc[2][4][4] = {};
    for (int jc = 0; jc < 4; ++jc) {
        __syncthreads();
        stage_wb512(g_wbf + (7+jc)*16384, s_W, tid);
        __syncthreads();
        float tacc[2][4][4] = {};
        mma_gemm16(s_d, 136, s_W, tacc, warp, lane);
        uint32_t* tw = (uint32_t*)s_t;
        #pragma unroll
        for (int mt = 0; mt < 2; ++mt)
            #pragma unroll
            for (int nt = 0; nt < 4; ++nt) {
                int r0 = rbase + mt*16;
                int c0 = cbase + nt*8 + 2*tg;
                float b0 = fc1_b[jc*128 + c0], b1 = fc1_b[jc*128 + c0 + 1];
                float v0 = gelu_f(tacc[mt][nt][0] + b0);
                float v1 = gelu_f(tacc[mt][nt][1] + b1);
                float v2 = gelu_f(tacc[mt][nt][2] + b0);
                float v3 = gelu_f(tacc[mt][nt][3] + b1);
                tw[ r0   *68 + (c0 >> 1)] = bf2(v0, v1);
                tw[(r0+8)*68 + (c0 >> 1)] = bf2(v2, v3);
            }
        __syncthreads();
        stage_wb512(g_wbf + (11+jc)*16384, s_W, tid);
        __syncthreads();
        mma_gemm16(s_t, 136, s_W, oacc, warp, lane);
    }
    __syncthreads();   // done with s_t/s_W before aliasing as s_f

    // epilogue: + fc2_b + residual x1 (fp32), stage fp32, transpose-write NCHW
    size_t pixb = (size_t)(bb*65536 + h*256 + w0);
    #pragma unroll
    for (int mt = 0; mt < 2; ++mt)
        #pragma unroll
        for (int nt = 0; nt < 4; ++nt) {
            int r0 = rbase + mt*16;
            int c0 = cbase + nt*8 + 2*tg;
            float b0 = fc2_b[c0], b1 = fc2_b[c0+1];
            float2 x0 = *(const float2*)&g_x1[(pixb + r0)  *128 + c0];
            float2 x1 = *(const float2*)&g_x1[(pixb + r0+8)*128 + c0];
            s_f[ r0   *129 + c0]     = oacc[mt][nt][0] + b0 + x0.x;
            s_f[ r0   *129 + c0 + 1] = oacc[mt][nt][1] + b1 + x0.y;
            s_f[(r0+8)*129 + c0]     = oacc[mt][nt][2] + b0 + x1.x;
            s_f[(r0+8)*129 + c0 + 1] = oacc[mt][nt][3] + b1 + x1.y;
        }
    __syncthreads();
    for (int idx = tid; idx < 16384; idx += 512) {
        int c = idx >> 7, p = idx & 127;
        out[((size_t)(bb*128 + c)*256 + h)*256 + w0 + p] = s_f[p*129 + c];
    }
}

// ---------------- launch ----------------
extern "C" void kernel_launch(void* const* d_in, const int* in_sizes, int n_in,
                              void* d_out, int out_size) {
    const float* x        = (const float*)d_in[0];
    const float* norm1_w  = (const float*)d_in[1];
    const float* norm1_b  = (const float*)d_in[2];
    const float* qkv_w    = (const float*)d_in[3];
    const float* qkv_b    = (const float*)d_in[4];
    const float* pos_bias = (const float*)d_in[5];
    const float* out_w    = (const float*)d_in[6];
    const float* out_b    = (const float*)d_in[7];
    const float* convp_w  = (const float*)d_in[8];
    const float* convp_b  = (const float*)d_in[9];
    const float* pw1_w    = (const float*)d_in[10];
    const float* pw1_b    = (const float*)d_in[11];
    const float* dw1_w    = (const float*)d_in[12];
    const float* dw1_b    = (const float*)d_in[13];
    const float* tok_w    = (const float*)d_in[14];
    const float* tok_b    = (const float*)d_in[15];
    const float* norm2_w  = (const float*)d_in[16];
    const float* norm2_b  = (const float*)d_in[17];
    const float* lpw_w    = (const float*)d_in[18];
    const float* ldw_w    = (const float*)d_in[19];
    const float* ldw_b    = (const float*)d_in[20];
    const float* fc1_w    = (const float*)d_in[21];
    const float* fc1_b    = (const float*)d_in[22];
    const float* fc2_w    = (const float*)d_in[23];
    const float* fc2_b    = (const float*)d_in[24];
    float* out = (float*)d_out;

    const int SM_REMSA = 133120 + 34816 + 34816;          // 202752
    const int SM_LN2Z  = 66048 + 34816 + 34816;           // 135680
    const int SM_LEFF  = 34816 + 34816 + 34816;           // 104448
    cudaFuncSetAttribute(k_remsa, cudaFuncAttributeMaxDynamicSharedMemorySize, SM_REMSA);
    cudaFuncSetAttribute(k_ln2z,  cudaFuncAttributeMaxDynamicSharedMemorySize, SM_LN2Z);
    cudaFuncSetAttribute(k_leff,  cudaFuncAttributeMaxDynamicSharedMemorySize, SM_LEFF);

    k_fuse <<<64,   256>>>(convp_w, convp_b, pw1_w, pw1_b);
    k_prep <<<960,  256>>>(qkv_w, out_w, tok_w, lpw_w, fc1_w, fc2_w);
    k_ln1  <<<4096, 256>>>(x, norm1_w, norm1_b);
    k_remsa<<<2048, 512, SM_REMSA>>>(qkv_b, pos_bias, out_b, tok_b, dw1_w, dw1_b);
    k_ln2z <<<2048, 512, SM_LN2Z>>>(x, norm2_w, norm2_b);
    k_leff <<<2048, 512, SM_LEFF>>>(ldw_w, ldw_b, fc1_b, fc2_b, out);
}

// round 7
// speedup vs baseline: 3.3212x; 1.0009x over previous
#include <cuda_runtime.h>
#include <cuda_bf16.h>
#include <cstdint>
#include <math.h>

#define BATCH 4
#define CCH 128
#define NPIX (BATCH*256*256)     /* 262144 */
#define NWIN (NPIX/64)           /* 4096 */

// ---------------- device scratch ----------------
__device__ float g_Wc[CCH*CCH];
__device__ float g_bc[CCH];
// bf16 weight bank: [0..2]=qkv, [3]=Wc, [4]=out_w, [5]=tok_w, [6]=lpw,
// [7..10]=fc1 chunks, [11..14]=fc2 chunks. Each 128x128 row-major.
__device__ __nv_bfloat16 g_wbf[15*16384];
__device__ __nv_bfloat16 g_y[NPIX*CCH];   // LN1 out, window-token layout
__device__ float g_att[NPIX*CCH];         // remsa out fp32, window-token layout
__device__ float g_x1[NPIX*CCH];          // x + merged attn, channels-last fp32
__device__ __nv_bfloat16 g_z[NPIX*CCH];   // lpw out, channels-last bf16

// ---------------- helpers ----------------
__device__ __forceinline__ uint32_t bf2(float a, float b) {
    __nv_bfloat162 t = __floats2bfloat162_rn(a, b);
    return *reinterpret_cast<uint32_t*>(&t);
}
__device__ __forceinline__ float2 ubf2f(uint32_t w) {
    __nv_bfloat162 t = *reinterpret_cast<__nv_bfloat162*>(&w);
    return make_float2(__bfloat162float(t.x), __bfloat162float(t.y));
}

// exact-GELU via FMA-only erf polynomial (|z|<=1); rare tail uses erff
__device__ __forceinline__ float gelu_f(float v) {
    float z = v * 0.7071067811865475f;
    float e;
    if (fabsf(z) <= 1.0f) {
        float s = z*z;
        e = 7.853861595399774e-5f;
        e = e*s - 8.010193625184903e-4f;
        e = e*s + 5.188327685732524e-3f;
        e = e*s - 2.685381193529856e-2f;
        e = e*s + 1.128358514861418e-1f;
        e = e*s - 3.761262582423300e-1f;
        e = e*s + 1.128379165726710f;
        e = e*z;
    } else {
        e = erff(z);
    }
    return v * (0.5f + 0.5f*e);
}

__device__ __forceinline__ void mma16(float* c, const uint32_t* a, const uint32_t* b) {
    asm volatile(
        "mma.sync.aligned.m16n8k16.row.col.f32.bf16.bf16.f32 "
        "{%0,%1,%2,%3},{%4,%5,%6,%7},{%8,%9},{%0,%1,%2,%3};"
        : "+f"(c[0]), "+f"(c[1]), "+f"(c[2]), "+f"(c[3])
        : "r"(a[0]), "r"(a[1]), "r"(a[2]), "r"(a[3]), "r"(b[0]), "r"(b[1]));
}

#define LDSM4(R, addr) \
    asm volatile("ldmatrix.sync.aligned.m8n8.x4.shared.b16 {%0,%1,%2,%3}, [%4];" \
        : "=r"(R[0]), "=r"(R[1]), "=r"(R[2]), "=r"(R[3]) : "r"(addr))

// async stage: prepacked 128x128 bf16 weight -> smem [128][136]
__device__ __forceinline__ void stage_async(const __nv_bfloat16* __restrict__ Wb,
                                            __nv_bfloat16* __restrict__ sW, int tid) {
    uint32_t s = (uint32_t)__cvta_generic_to_shared(sW);
    const char* gp = (const char*)Wb;
    #pragma unroll
    for (int i = tid; i < 2048; i += 512) {
        int row = i >> 4, c8 = (i & 15) << 3;
        asm volatile("cp.async.cg.shared.global [%0], [%1], 16;"
            :: "r"(s + (uint32_t)(row*136 + c8)*2), "l"(gp + i*16));
    }
    asm volatile("cp.async.commit_group;" ::: "memory");
}
__device__ __forceinline__ void stage_wait() {
    asm volatile("cp.async.wait_group 0;" ::: "memory");
}

// 128x128 GEMM tile, K=128, bf16 in, fp32 accum. 16 warps, each 32x32. ldmatrix loads.
__device__ __forceinline__ void mma_gemm16(const __nv_bfloat16* __restrict__ sA, int strideA,
                                           const __nv_bfloat16* __restrict__ sW,
                                           float acc[2][4][4], int warp, int lane) {
    int quad = lane >> 3, r = lane & 7;
    // A: quads -> {rows g klo, rows g+8 klo, rows g khi, rows g+8 khi}
    uint32_t aAddr = (uint32_t)__cvta_generic_to_shared(sA)
        + (uint32_t)((((warp & 3)*32 + (quad & 1)*8 + r) * strideA + (quad >> 1)*8) * 2);
    // B: quads -> {n0-7 klo, n0-7 khi, n8-15 klo, n8-15 khi}
    uint32_t bAddr = (uint32_t)__cvta_generic_to_shared(sW)
        + (uint32_t)((((warp >> 2)*32 + (quad >> 1)*8 + r) * 136 + (quad & 1)*8) * 2);
    uint32_t aStep = (uint32_t)(16 * strideA * 2);
    const uint32_t bStep = 16 * 136 * 2;
    #pragma unroll
    for (int kt = 0; kt < 8; ++kt) {
        uint32_t A0[4], A1[4], B0[4], B1[4];
        LDSM4(A0, aAddr);
        LDSM4(A1, aAddr + aStep);
        LDSM4(B0, bAddr);
        LDSM4(B1, bAddr + bStep);
        aAddr += 32; bAddr += 32;
        mma16(acc[0][0], A0, B0);     mma16(acc[0][1], A0, B0 + 2);
        mma16(acc[0][2], A0, B1);     mma16(acc[0][3], A0, B1 + 2);
        mma16(acc[1][0], A1, B0);     mma16(acc[1][1], A1, B0 + 2);
        mma16(acc[1][2], A1, B1);     mma16(acc[1][3], A1, B1 + 2);
    }
}

// ---------------- K0: fuse convp + pw1 ----------------
__global__ void k_fuse(const float* __restrict__ convp_w, const float* __restrict__ convp_b,
                       const float* __restrict__ pw1_w,   const float* __restrict__ pw1_b) {
    int gid = blockIdx.x*256 + threadIdx.x;
    int o = gid >> 7, i = gid & 127;
    float s = 0.f;
    for (int c = 0; c < CCH; ++c) s += pw1_w[o*CCH + c] * convp_w[c*CCH + i];
    g_Wc[o*CCH + i] = s;
    if (gid < CCH) {
        float b = pw1_b[gid];
        for (int c = 0; c < CCH; ++c) b += pw1_w[gid*CCH + c] * convp_b[c];
        g_bc[gid] = b;
    }
}

// ---------------- K0b: pack weights to bf16 bank ----------------
__global__ void k_prep(const float* __restrict__ qkv_w, const float* __restrict__ out_w,
                       const float* __restrict__ tok_w, const float* __restrict__ lpw_w,
                       const float* __restrict__ fc1_w, const float* __restrict__ fc2_w) {
    int idx = blockIdx.x*256 + threadIdx.x;
    int blk = idx >> 14;
    int m = idx & 16383;
    int c = m >> 7, k = m & 127;
    float v;
    if      (blk < 3)  v = qkv_w[blk*16384 + m];
    else if (blk == 3) v = g_Wc[m];
    else if (blk == 4) v = out_w[m];
    else if (blk == 5) v = tok_w[m];
    else if (blk == 6) v = lpw_w[m];
    else if (blk < 11) v = fc1_w[(blk-7)*16384 + m];
    else               v = fc2_w[c*512 + (blk-11)*128 + k];
    g_wbf[idx] = __float2bfloat16(v);
}

// ---------------- LN1 ----------------
__global__ void k_ln1(const float* __restrict__ x, const float* __restrict__ w,
                      const float* __restrict__ b) {
    __shared__ float s[64*129];
    __shared__ float s_mu[64], s_rs[64];
    int tid = threadIdx.x, bid = blockIdx.x;
    int w0 = (bid & 3) * 64;
    int h  = (bid >> 2) & 255;
    int bb = bid >> 10;
    const float* xb = x + (size_t)bb*CCH*65536 + h*256 + w0;
    for (int idx = tid; idx < 8192; idx += 256) {
        int c = idx >> 6, p = idx & 63;
        s[p*129 + c] = xb[c*65536 + p];
    }
    __syncthreads();
    int p = tid >> 2, q = tid & 3;
    float sm = 0.f, sq = 0.f;
    #pragma unroll
    for (int i = 0; i < 32; ++i) { float v = s[p*129 + q*32 + i]; sm += v; sq += v*v; }
    sm += __shfl_xor_sync(0xffffffffu, sm, 1); sq += __shfl_xor_sync(0xffffffffu, sq, 1);
    sm += __shfl_xor_sync(0xffffffffu, sm, 2); sq += __shfl_xor_sync(0xffffffffu, sq, 2);
    if (q == 0) {
        float mu = sm * (1.f/128.f);
        float var = sq * (1.f/128.f) - mu*mu;
        s_mu[p] = mu; s_rs[p] = rsqrtf(var + 1e-5f);
    }
    __syncthreads();
    uint32_t* yw = (uint32_t*)g_y;
    for (int idx = tid; idx < 4096; idx += 256) {
        int pp = idx >> 6, cw = idx & 63;
        int c0 = cw*2;
        int wc = w0 + pp;
        int win = (bb*32 + (h >> 3))*32 + (wc >> 3);
        int n   = (h & 7)*8 + (wc & 7);
        float mu = s_mu[pp], rs = s_rs[pp];
        float v0 = (s[pp*129 + c0]   - mu) * rs * w[c0]   + b[c0];
        float v1 = (s[pp*129 + c0+1] - mu) * rs * w[c0+1] + b[c0+1];
        yw[(size_t)win*4096 + n*64 + cw] = bf2(v0, v1);
    }
}

// ---------------- ReMSA: 2 windows per CTA, 512 threads ----------------
__global__ void k_remsa(const float* __restrict__ qkv_b, const float* __restrict__ pos_bias,
                        const float* __restrict__ out_b, const float* __restrict__ tok_b,
                        const float* __restrict__ dw1_w, const float* __restrict__ dw1_b) {
    extern __shared__ __align__(16) char smem[];
    __nv_bfloat16* s_qkv = (__nv_bfloat16*)smem;                   // 128*520 bf16
    __nv_bfloat16* s_y   = (__nv_bfloat16*)(smem + 133120);        // 128*136 (LN1 / ao)
    __nv_bfloat16* s_W   = (__nv_bfloat16*)(smem + 133120 + 34816);
    int tid = threadIdx.x, warp = tid >> 5, lane = tid & 31;
    int win0 = blockIdx.x * 2;

    stage_async(g_wbf, s_W, tid);    // prefetch qkv chunk 0 behind the y-tile load

    const uint32_t* yw = (const uint32_t*)g_y + (size_t)win0*4096;
    uint32_t* s_yw = (uint32_t*)s_y;
    for (int idx = tid; idx < 8192; idx += 512) {
        int r = idx >> 6, cw = idx & 63;
        s_yw[r*68 + cw] = yw[idx];
    }

    int g = lane >> 2, tg = lane & 3;
    int rbase = (warp & 3) * 32 + g;
    int cbase = (warp >> 2) * 32;
    uint32_t* qw = (uint32_t*)s_qkv;   // stride 260 words per row

    // Phase A: [qkv ; Wc] GEMM (128 x 512) -> s_qkv bf16
    for (int chunk = 0; chunk < 4; ++chunk) {
        stage_wait();
        __syncthreads();
        float acc[2][4][4] = {};
        mma_gemm16(s_y, 136, s_W, acc, warp, lane);
        __syncthreads();                                 // all reads of s_W done
        if (chunk < 3) stage_async(g_wbf + (chunk+1)*16384, s_W, tid);
        const float* bsrc = (chunk < 3) ? (qkv_b + chunk*128) : g_bc;
        #pragma unroll
        for (int mt = 0; mt < 2; ++mt)
            #pragma unroll
            for (int nt = 0; nt < 4; ++nt) {
                int r0 = rbase + mt*16;
                int c0 = cbase + nt*8 + 2*tg;
                float b0 = bsrc[c0], b1 = bsrc[c0+1];
                int off = chunk*64 + (c0 >> 1);
                qw[ r0   *260 + off] = bf2(acc[mt][nt][0] + b0, acc[mt][nt][1] + b1);
                qw[(r0+8)*260 + off] = bf2(acc[mt][nt][2] + b0, acc[mt][nt][3] + b1);
            }
    }
    __syncthreads();

    // Phase B: head-mixing attention; 4 threads/token, 2 heads each; ao -> s_y
    {
        int r = tid >> 2, q4 = tid & 3, n = r & 63;
        const uint32_t* base = qw + r*260;   // head hI: words q=hI*24, k=+8, v=+16
        const float* pb = pos_bias + n*64;
        uint32_t* aw = (uint32_t*)s_y;
        #pragma unroll
        for (int hh = 0; hh < 2; ++hh) {
            int hI = q4*2 + hh;
            float qv[16];
            #pragma unroll
            for (int d = 0; d < 8; ++d) {
                float2 f = ubf2f(base[hI*24 + d]);
                qv[2*d] = f.x; qv[2*d+1] = f.y;
            }
            float sc[8]; float mx = -1e30f;
            #pragma unroll
            for (int gg = 0; gg < 8; ++gg) {
                const uint32_t* kp = base + gg*24 + 8;
                float sd = 0.f;
                #pragma unroll
                for (int d = 0; d < 8; ++d) {
                    float2 f = ubf2f(kp[d]);
                    sd += qv[2*d]*f.x + qv[2*d+1]*f.y;
                }
                sc[gg] = sd*0.25f + pb[hI*8 + gg];
                mx = fmaxf(mx, sc[gg]);
            }
            float ssum = 0.f;
            #pragma unroll
            for (int gg = 0; gg < 8; ++gg) { sc[gg] = __expf(sc[gg] - mx); ssum += sc[gg]; }
            float inv = 1.f / ssum;
            float ao[16];
            #pragma unroll
            for (int d = 0; d < 16; ++d) ao[d] = 0.f;
            #pragma unroll
            for (int gg = 0; gg < 8; ++gg) {
                float a = sc[gg]*inv;
                const uint32_t* vp = base + gg*24 + 16;
                #pragma unroll
                for (int d = 0; d < 8; ++d) {
                    float2 f = ubf2f(vp[d]);
                    ao[2*d]   += a*f.x;
                    ao[2*d+1] += a*f.y;
                }
            }
            #pragma unroll
            for (int d = 0; d < 8; ++d)
                aw[r*68 + hI*8 + d] = bf2(ao[2*d], ao[2*d+1]);
        }
    }

    // Phase C: token-dim dwconv on xc (words 192..255); read->regs, sync, write cols 0..63
    uint32_t cres[16];
    #pragma unroll
    for (int it = 0; it < 16; ++it) {
        int idx = tid + it*512;
        int r = idx >> 6, cw = idx & 63, n = r & 63;
        int c0 = cw*2;
        float2 m  = ubf2f(qw[r*260 + 192 + cw]);
        float2 lo = make_float2(0.f, 0.f), hi = make_float2(0.f, 0.f);
        if (n > 0)  lo = ubf2f(qw[(r-1)*260 + 192 + cw]);
        if (n < 63) hi = ubf2f(qw[(r+1)*260 + 192 + cw]);
        float d0 = lo.x*dw1_w[c0*3]   + m.x*dw1_w[c0*3+1] + hi.x*dw1_w[c0*3+2] + dw1_b[c0];
        float d1 = lo.y*dw1_w[c0*3+3] + m.y*dw1_w[c0*3+4] + hi.y*dw1_w[c0*3+5] + dw1_b[c0+1];
        cres[it] = bf2(d0, d1);
    }
    __syncthreads();
    stage_async(g_wbf + 4*16384, s_W, tid);   // out_w behind Phase C writes
    #pragma unroll
    for (int it = 0; it < 16; ++it) {
        int idx = tid + it*512;
        qw[(idx >> 6)*260 + (idx & 63)] = cres[it];
    }
    stage_wait();
    __syncthreads();

    // Phase D: ao @ out_w^T + dconv @ tok_w^T
    float acc[2][4][4] = {};
    mma_gemm16(s_y, 136, s_W, acc, warp, lane);
    __syncthreads();
    stage_async(g_wbf + 5*16384, s_W, tid);
    stage_wait();
    __syncthreads();
    mma_gemm16(s_qkv, 520, s_W, acc, warp, lane);
    float* ob = g_att + (size_t)win0*8192;
    #pragma unroll
    for (int mt = 0; mt < 2; ++mt)
        #pragma unroll
        for (int nt = 0; nt < 4; ++nt) {
            int r0 = rbase + mt*16;
            int c0 = cbase + nt*8 + 2*tg;
            float b0 = out_b[c0] + tok_b[c0], b1 = out_b[c0+1] + tok_b[c0+1];
            *(float2*)&ob[ r0   *128 + c0] =
                make_float2(acc[mt][nt][0] + b0, acc[mt][nt][1] + b1);
            *(float2*)&ob[(r0+8)*128 + c0] =
                make_float2(acc[mt][nt][2] + b0, acc[mt][nt][3] + b1);
        }
}

// ---------------- LN2 + lpw fused: 128 pixels per CTA, 512 threads ----------------
__global__ void k_ln2z(const float* __restrict__ x, const float* __restrict__ w,
                       const float* __restrict__ b) {
    extern __shared__ __align__(16) char smem[];
    float* s = (float*)smem;                                      // 128*129 fp32
    __nv_bfloat16* s_A = (__nv_bfloat16*)(smem + 66048);          // 128*136
    __nv_bfloat16* s_W = (__nv_bfloat16*)(smem + 66048 + 34816);  // 128*136
    __shared__ float s_mu[128], s_rs[128];
    int tid = threadIdx.x, bid = blockIdx.x;
    int warp = tid >> 5, lane = tid & 31;
    int w0 = (bid & 1) * 128;
    int h  = (bid >> 1) & 255;
    int bb = bid >> 9;
    stage_async(g_wbf + 6*16384, s_W, tid);
    const float* xb = x + (size_t)bb*CCH*65536 + h*256 + w0;
    for (int idx = tid; idx < 16384; idx += 512) {
        int c = idx >> 7, p = idx & 127;
        s[p*129 + c] = xb[c*65536 + p];
    }
    __syncthreads();
    for (int idx = tid; idx < 16384; idx += 512) {
        int pp = idx >> 7, c = idx & 127;
        int wc = w0 + pp;
        int win = (bb*32 + (h >> 3))*32 + (wc >> 3);
        int n   = (h & 7)*8 + (wc & 7);
        float v = s[pp*129 + c] + g_att[(size_t)win*8192 + n*128 + c];
        s[pp*129 + c] = v;
        g_x1[((size_t)(bb*65536 + h*256 + wc))*128 + c] = v;
    }
    __syncthreads();
    int p = tid >> 2, q = tid & 3;
    float sm = 0.f, sq = 0.f;
    #pragma unroll
    for (int i = 0; i < 32; ++i) { float v = s[p*129 + q*32 + i]; sm += v; sq += v*v; }
    sm += __shfl_xor_sync(0xffffffffu, sm, 1); sq += __shfl_xor_sync(0xffffffffu, sq, 1);
    sm += __shfl_xor_sync(0xffffffffu, sm, 2); sq += __shfl_xor_sync(0xffffffffu, sq, 2);
    if (q == 0) {
        float mu = sm * (1.f/128.f);
        float var = sq * (1.f/128.f) - mu*mu;
        s_mu[p] = mu; s_rs[p] = rsqrtf(var + 1e-5f);
    }
    __syncthreads();
    uint32_t* aw = (uint32_t*)s_A;
    for (int idx = tid; idx < 8192; idx += 512) {
        int pp = idx >> 6, cw = idx & 63;
        int c0 = cw*2;
        float mu = s_mu[pp], rs = s_rs[pp];
        float v0 = (s[pp*129 + c0]   - mu) * rs * w[c0]   + b[c0];
        float v1 = (s[pp*129 + c0+1] - mu) * rs * w[c0+1] + b[c0+1];
        aw[pp*68 + cw] = bf2(v0, v1);
    }
    stage_wait();
    __syncthreads();
    float acc[2][4][4] = {};
    mma_gemm16(s_A, 136, s_W, acc, warp, lane);
    int g = lane >> 2, tg = lane & 3;
    int rbase = (warp & 3) * 32 + g;
    int cbase = (warp >> 2) * 32;
    size_t pixb = (size_t)(bb*65536 + h*256 + w0);
    uint32_t* zw = (uint32_t*)g_z;
    #pragma unroll
    for (int mt = 0; mt < 2; ++mt)
        #pragma unroll
        for (int nt = 0; nt < 4; ++nt) {
            int r0 = rbase + mt*16;
            int c0 = cbase + nt*8 + 2*tg;
            zw[(pixb + r0)  *64 + (c0 >> 1)] = bf2(acc[mt][nt][0], acc[mt][nt][1]);
            zw[(pixb + r0+8)*64 + (c0 >> 1)] = bf2(acc[mt][nt][2], acc[mt][nt][3]);
        }
}

// ---------------- LeFF: 128 pixels per CTA, 512 threads ----------------
__global__ void k_leff(const float* __restrict__ ldw_w, const float* __restrict__ ldw_b,
                       const float* __restrict__ fc1_b, const float* __restrict__ fc2_b,
                       float* __restrict__ out) {
    extern __shared__ __align__(16) char smem[];
    __nv_bfloat16* s_d = (__nv_bfloat16*)smem;                   // 128*136
    __nv_bfloat16* s_t = (__nv_bfloat16*)(smem + 34816);         // 128*136
    __nv_bfloat16* s_W = (__nv_bfloat16*)(smem + 69632);         // 128*136
    float* s_f = (float*)(smem + 34816);                         // aliases s_t+s_W
    int tid = threadIdx.x, warp = tid >> 5, lane = tid & 31, bid = blockIdx.x;
    int w0 = (bid & 1) * 128;
    int h  = (bid >> 1) & 255;
    int bb = bid >> 9;

    stage_async(g_wbf + 7*16384, s_W, tid);   // fc1 chunk 0 behind the dwconv

    // 3x3 depthwise over g_z (bf16 channels-last), zero padding
    {
        const uint32_t* zw = (const uint32_t*)g_z;
        uint32_t* dw = (uint32_t*)s_d;
        for (int idx = tid; idx < 8192; idx += 512) {
            int p = idx >> 6, cw = idx & 63;
            int c0 = cw*2;
            int xx0 = w0 + p;
            float accA = ldw_b[c0], accB = ldw_b[c0+1];
            #pragma unroll
            for (int dy = 0; dy < 3; ++dy) {
                int yy = h + dy - 1;
                if (yy < 0 || yy > 255) continue;
                #pragma unroll
                for (int dx = 0; dx < 3; ++dx) {
                    int xx = xx0 + dx - 1;
                    if (xx < 0 || xx > 255) continue;
                    float2 t = ubf2f(zw[((size_t)(bb*65536 + yy*256 + xx))*64 + cw]);
                    accA += t.x * ldw_w[c0*9     + dy*3 + dx];
                    accB += t.y * ldw_w[(c0+1)*9 + dy*3 + dx];
                }
            }
            dw[p*68 + cw] = bf2(accA, accB);
        }
    }

    int g = lane >> 2, tg = lane & 3;
    int rbase = (warp & 3) * 32 + g;
    int cbase = (warp >> 2) * 32;
    float oacc[2][4][4] = {};
    for (int jc = 0; jc < 4; ++jc) {
        stage_wait();
        __syncthreads();
        float tacc[2][4][4] = {};
        mma_gemm16(s_d, 136, s_W, tacc, warp, lane);
        __syncthreads();                         // fc1 weight reads done
        stage_async(g_wbf + (11+jc)*16384, s_W, tid);
        uint32_t* tw = (uint32_t*)s_t;
        #pragma unroll
        for (int mt = 0; mt < 2; ++mt)
            #pragma unroll
            for (int nt = 0; nt < 4; ++nt) {
                int r0 = rbase + mt*16;
                int c0 = cbase + nt*8 + 2*tg;
                float b0 = fc1_b[jc*128 + c0], b1 = fc1_b[jc*128 + c0 + 1];
                float v0 = gelu_f(tacc[mt][nt][0] + b0);
                float v1 = gelu_f(tacc[mt][nt][1] + b1);
                float v2 = gelu_f(tacc[mt][nt][2] + b0);
                float v3 = gelu_f(tacc[mt][nt][3] + b1);
                tw[ r0   *68 + (c0 >> 1)] = bf2(v0, v1);
                tw[(r0+8)*68 + (c0 >> 1)] = bf2(v2, v3);
            }
        stage_wait();
        __syncthreads();
        mma_gemm16(s_t, 136, s_W, oacc, warp, lane);
        __syncthreads();                         // fc2 weight reads done
        if (jc < 3) stage_async(g_wbf + (8+jc)*16384, s_W, tid);
    }

    // epilogue: + fc2_b + residual x1 (fp32), stage fp32, transpose-write NCHW
    size_t pixb = (size_t)(bb*65536 + h*256 + w0);
    #pragma unroll
    for (int mt = 0; mt < 2; ++mt)
        #pragma unroll
        for (int nt = 0; nt < 4; ++nt) {
            int r0 = rbase + mt*16;
            int c0 = cbase + nt*8 + 2*tg;
            float b0 = fc2_b[c0], b1 = fc2_b[c0+1];
            float2 x0 = *(const float2*)&g_x1[(pixb + r0)  *128 + c0];
            float2 x1 = *(const float2*)&g_x1[(pixb + r0+8)*128 + c0];
            s_f[ r0   *129 + c0]     = oacc[mt][nt][0] + b0 + x0.x;
            s_f[ r0   *129 + c0 + 1] = oacc[mt][nt][1] + b1 + x0.y;
            s_f[(r0+8)*129 + c0]     = oacc[mt][nt][2] + b0 + x1.x;
            s_f[(r0+8)*129 + c0 + 1] = oacc[mt][nt][3] + b1 + x1.y;
        }
    __syncthreads();
    for (int idx = tid; idx < 16384; idx += 512) {
        int c = idx >> 7, p = idx & 127;
        out[((size_t)(bb*128 + c)*256 + h)*256 + w0 + p] = s_f[p*129 + c];
    }
}

// ---------------- launch ----------------
extern "C" void kernel_launch(void* const* d_in, const int* in_sizes, int n_in,
                              void* d_out, int out_size) {
    const float* x        = (const float*)d_in[0];
    const float* norm1_w  = (const float*)d_in[1];
    const float* norm1_b  = (const float*)d_in[2];
    const float* qkv_w    = (const float*)d_in[3];
    const float* qkv_b    = (const float*)d_in[4];
    const float* pos_bias = (const float*)d_in[5];
    const float* out_w    = (const float*)d_in[6];
    const float* out_b    = (const float*)d_in[7];
    const float* convp_w  = (const float*)d_in[8];
    const float* convp_b  = (const float*)d_in[9];
    const float* pw1_w    = (const float*)d_in[10];
    const float* pw1_b    = (const float*)d_in[11];
    const float* dw1_w    = (const float*)d_in[12];
    const float* dw1_b    = (const float*)d_in[13];
    const float* tok_w    = (const float*)d_in[14];
    const float* tok_b    = (const float*)d_in[15];
    const float* norm2_w  = (const float*)d_in[16];
    const float* norm2_b  = (const float*)d_in[17];
    const float* lpw_w    = (const float*)d_in[18];
    const float* ldw_w    = (const float*)d_in[19];
    const float* ldw_b    = (const float*)d_in[20];
    const float* fc1_w    = (const float*)d_in[21];
    const float* fc1_b    = (const float*)d_in[22];
    const float* fc2_w    = (const float*)d_in[23];
    const float* fc2_b    = (const float*)d_in[24];
    float* out = (float*)d_out;

    const int SM_REMSA = 133120 + 34816 + 34816;          // 202752
    const int SM_LN2Z  = 66048 + 34816 + 34816;           // 135680
    const int SM_LEFF  = 34816 + 34816 + 34816;           // 104448
    cudaFuncSetAttribute(k_remsa, cudaFuncAttributeMaxDynamicSharedMemorySize, SM_REMSA);
    cudaFuncSetAttribute(k_ln2z,  cudaFuncAttributeMaxDynamicSharedMemorySize, SM_LN2Z);
    cudaFuncSetAttribute(k_leff,  cudaFuncAttributeMaxDynamicSharedMemorySize, SM_LEFF);

    k_fuse <<<64,   256>>>(convp_w, convp_b, pw1_w, pw1_b);
    k_prep <<<960,  256>>>(qkv_w, out_w, tok_w, lpw_w, fc1_w, fc2_w);
    k_ln1  <<<4096, 256>>>(x, norm1_w, norm1_b);
    k_remsa<<<2048, 512, SM_REMSA>>>(qkv_b, pos_bias, out_b, tok_b, dw1_w, dw1_b);
    k_ln2z <<<2048, 512, SM_LN2Z>>>(x, norm2_w, norm2_b);
    k_leff <<<2048, 512, SM_LEFF>>>(ldw_w, ldw_b, fc1_b, fc2_b, out);
}

// round 8
// speedup vs baseline: 3.9468x; 1.1884x over previous
#include <cuda_runtime.h>
#include <cuda_bf16.h>
#include <cstdint>
#include <math.h>

#define BATCH 4
#define CCH 128
#define NPIX (BATCH*256*256)     /* 262144 */
#define NWIN (NPIX/64)           /* 4096 */

// ---------------- device scratch ----------------
__device__ float g_Wc[CCH*CCH];
__device__ float g_bc[CCH];
// bf16 weight bank: [0..2]=qkv, [3]=Wc, [4]=out_w, [5]=tok_w, [6]=lpw,
// [7..10]=fc1 chunks, [11..14]=fc2 chunks. Each 128x128 row-major.
__device__ __nv_bfloat16 g_wbf[15*16384];
__device__ __nv_bfloat16 g_att[NPIX*CCH]; // remsa out bf16, window-token layout
__device__ float g_x1[NPIX*CCH];          // x + merged attn, channels-last fp32
__device__ __nv_bfloat16 g_z[NPIX*CCH];   // lpw out, channels-last bf16

// ---------------- helpers ----------------
__device__ __forceinline__ uint32_t bf2(float a, float b) {
    __nv_bfloat162 t = __floats2bfloat162_rn(a, b);
    return *reinterpret_cast<uint32_t*>(&t);
}
__device__ __forceinline__ float2 ubf2f(uint32_t w) {
    __nv_bfloat162 t = *reinterpret_cast<__nv_bfloat162*>(&w);
    return make_float2(__bfloat162float(t.x), __bfloat162float(t.y));
}

// exact-GELU via FMA-only erf polynomial (|z|<=1); rare tail uses erff
__device__ __forceinline__ float gelu_f(float v) {
    float z = v * 0.7071067811865475f;
    float e;
    if (fabsf(z) <= 1.0f) {
        float s = z*z;
        e = 7.853861595399774e-5f;
        e = e*s - 8.010193625184903e-4f;
        e = e*s + 5.188327685732524e-3f;
        e = e*s - 2.685381193529856e-2f;
        e = e*s + 1.128358514861418e-1f;
        e = e*s - 3.761262582423300e-1f;
        e = e*s + 1.128379165726710f;
        e = e*z;
    } else {
        e = erff(z);
    }
    return v * (0.5f + 0.5f*e);
}

__device__ __forceinline__ void mma16(float* c, const uint32_t* a, const uint32_t* b) {
    asm volatile(
        "mma.sync.aligned.m16n8k16.row.col.f32.bf16.bf16.f32 "
        "{%0,%1,%2,%3},{%4,%5,%6,%7},{%8,%9},{%0,%1,%2,%3};"
        : "+f"(c[0]), "+f"(c[1]), "+f"(c[2]), "+f"(c[3])
        : "r"(a[0]), "r"(a[1]), "r"(a[2]), "r"(a[3]), "r"(b[0]), "r"(b[1]));
}

#define LDSM4(R, addr) \
    asm volatile("ldmatrix.sync.aligned.m8n8.x4.shared.b16 {%0,%1,%2,%3}, [%4];" \
        : "=r"(R[0]), "=r"(R[1]), "=r"(R[2]), "=r"(R[3]) : "r"(addr))

// async stage: prepacked 128x128 bf16 weight -> smem [128][136]
__device__ __forceinline__ void stage_async(const __nv_bfloat16* __restrict__ Wb,
                                            __nv_bfloat16* __restrict__ sW, int tid) {
    uint32_t s = (uint32_t)__cvta_generic_to_shared(sW);
    const char* gp = (const char*)Wb;
    #pragma unroll
    for (int i = tid; i < 2048; i += 512) {
        int row = i >> 4, c8 = (i & 15) << 3;
        asm volatile("cp.async.cg.shared.global [%0], [%1], 16;"
            :: "r"(s + (uint32_t)(row*136 + c8)*2), "l"(gp + i*16));
    }
    asm volatile("cp.async.commit_group;" ::: "memory");
}
__device__ __forceinline__ void stage_wait0() {
    asm volatile("cp.async.wait_group 0;" ::: "memory");
}
__device__ __forceinline__ void stage_wait1() {
    asm volatile("cp.async.wait_group 1;" ::: "memory");
}

// 128x128 GEMM tile, K=128, bf16 in, fp32 accum. 16 warps, each 32x32. ldmatrix loads.
__device__ __forceinline__ void mma_gemm16(const __nv_bfloat16* __restrict__ sA, int strideA,
                                           const __nv_bfloat16* __restrict__ sW,
                                           float acc[2][4][4], int warp, int lane) {
    int quad = lane >> 3, r = lane & 7;
    uint32_t aAddr = (uint32_t)__cvta_generic_to_shared(sA)
        + (uint32_t)((((warp & 3)*32 + (quad & 1)*8 + r) * strideA + (quad >> 1)*8) * 2);
    uint32_t bAddr = (uint32_t)__cvta_generic_to_shared(sW)
        + (uint32_t)((((warp >> 2)*32 + (quad >> 1)*8 + r) * 136 + (quad & 1)*8) * 2);
    uint32_t aStep = (uint32_t)(16 * strideA * 2);
    const uint32_t bStep = 16 * 136 * 2;
    #pragma unroll
    for (int kt = 0; kt < 8; ++kt) {
        uint32_t A0[4], A1[4], B0[4], B1[4];
        LDSM4(A0, aAddr);
        LDSM4(A1, aAddr + aStep);
        LDSM4(B0, bAddr);
        LDSM4(B1, bAddr + bStep);
        aAddr += 32; bAddr += 32;
        mma16(acc[0][0], A0, B0);     mma16(acc[0][1], A0, B0 + 2);
        mma16(acc[0][2], A0, B1);     mma16(acc[0][3], A0, B1 + 2);
        mma16(acc[1][0], A1, B0);     mma16(acc[1][1], A1, B0 + 2);
        mma16(acc[1][2], A1, B1);     mma16(acc[1][3], A1, B1 + 2);
    }
}

// ---------------- K0: fuse convp + pw1 ----------------
__global__ void k_fuse(const float* __restrict__ convp_w, const float* __restrict__ convp_b,
                       const float* __restrict__ pw1_w,   const float* __restrict__ pw1_b) {
    int gid = blockIdx.x*256 + threadIdx.x;
    int o = gid >> 7, i = gid & 127;
    float s = 0.f;
    for (int c = 0; c < CCH; ++c) s += pw1_w[o*CCH + c] * convp_w[c*CCH + i];
    g_Wc[o*CCH + i] = s;
    if (gid < CCH) {
        float b = pw1_b[gid];
        for (int c = 0; c < CCH; ++c) b += pw1_w[gid*CCH + c] * convp_b[c];
        g_bc[gid] = b;
    }
}

// ---------------- K0b: pack weights to bf16 bank ----------------
__global__ void k_prep(const float* __restrict__ qkv_w, const float* __restrict__ out_w,
                       const float* __restrict__ tok_w, const float* __restrict__ lpw_w,
                       const float* __restrict__ fc1_w, const float* __restrict__ fc2_w) {
    int idx = blockIdx.x*256 + threadIdx.x;
    int blk = idx >> 14;
    int m = idx & 16383;
    int c = m >> 7, k = m & 127;
    float v;
    if      (blk < 3)  v = qkv_w[blk*16384 + m];
    else if (blk == 3) v = g_Wc[m];
    else if (blk == 4) v = out_w[m];
    else if (blk == 5) v = tok_w[m];
    else if (blk == 6) v = lpw_w[m];
    else if (blk < 11) v = fc1_w[(blk-7)*16384 + m];
    else               v = fc2_w[c*512 + (blk-11)*128 + k];
    g_wbf[idx] = __float2bfloat16(v);
}

// ---------------- ReMSA (LN1 fused): 2 windows per CTA, 512 threads ----------------
__global__ void k_remsa(const float* __restrict__ x,
                        const float* __restrict__ n1w, const float* __restrict__ n1b,
                        const float* __restrict__ qkv_b, const float* __restrict__ pos_bias,
                        const float* __restrict__ out_b, const float* __restrict__ tok_b,
                        const float* __restrict__ dw1_w, const float* __restrict__ dw1_b) {
    extern __shared__ __align__(16) char smem[];
    __nv_bfloat16* s_qkv = (__nv_bfloat16*)smem;                   // 128*520 bf16 (also s_x fp32)
    __nv_bfloat16* s_y   = (__nv_bfloat16*)(smem + 133120);        // 128*136 (LN1 / ao)
    __nv_bfloat16* s_W   = (__nv_bfloat16*)(smem + 133120 + 34816);
    __shared__ float s_mu[128], s_rs[128];
    int tid = threadIdx.x, warp = tid >> 5, lane = tid & 31;
    int win0 = blockIdx.x * 2;
    int bb   = win0 >> 10;
    int rem  = win0 & 1023;
    int h0   = (rem >> 5) * 8;
    int w0c  = (rem & 31) * 8;   // 16 columns wide (2 windows)

    stage_async(g_wbf, s_W, tid);    // prefetch qkv chunk 0

    // ---- LN1 fused: load x tile (128 ch x 8 rows x 16 cols) into s_x fp32 ----
    float* s_x = (float*)s_qkv;      // [128 tokens][129]
    const float* xb = x + (size_t)bb*CCH*65536 + h0*256 + w0c;
    #pragma unroll
    for (int it = 0; it < 8; ++it) {
        int idx = tid + it*512;                 // 4096 float4
        int c = idx >> 5, r = (idx >> 2) & 7, w4 = idx & 3;
        float4 v = *(const float4*)(xb + c*65536 + r*256 + w4*4);
        int wb = w4*4;
        int row0 = (wb >> 3)*64 + r*8 + (wb & 7);
        s_x[(row0  )*129 + c] = v.x;
        s_x[(row0+1)*129 + c] = v.y;
        s_x[(row0+2)*129 + c] = v.z;
        s_x[(row0+3)*129 + c] = v.w;
    }
    __syncthreads();
    {
        int p = tid >> 2, q = tid & 3;
        float sm = 0.f, sq = 0.f;
        #pragma unroll
        for (int i = 0; i < 32; ++i) { float v = s_x[p*129 + q*32 + i]; sm += v; sq += v*v; }
        sm += __shfl_xor_sync(0xffffffffu, sm, 1); sq += __shfl_xor_sync(0xffffffffu, sq, 1);
        sm += __shfl_xor_sync(0xffffffffu, sm, 2); sq += __shfl_xor_sync(0xffffffffu, sq, 2);
        if (q == 0) {
            float mu = sm * (1.f/128.f);
            float var = sq * (1.f/128.f) - mu*mu;
            s_mu[p] = mu; s_rs[p] = rsqrtf(var + 1e-5f);
        }
    }
    __syncthreads();
    uint32_t* s_yw = (uint32_t*)s_y;
    for (int idx = tid; idx < 8192; idx += 512) {
        int pp = idx >> 6, cw = idx & 63, c0 = cw*2;
        float mu = s_mu[pp], rs = s_rs[pp];
        float v0 = (s_x[pp*129 + c0]   - mu) * rs * n1w[c0]   + n1b[c0];
        float v1 = (s_x[pp*129 + c0+1] - mu) * rs * n1w[c0+1] + n1b[c0+1];
        s_yw[pp*68 + cw] = bf2(v0, v1);
    }

    int g = lane >> 2, tg = lane & 3;
    int rbase = (warp & 3) * 32 + g;
    int cbase = (warp >> 2) * 32;
    uint32_t* qw = (uint32_t*)s_qkv;   // stride 260 words per row (overwrites s_x)

    // Phase A: [qkv ; Wc] GEMM (128 x 512) -> s_qkv bf16
    for (int chunk = 0; chunk < 4; ++chunk) {
        stage_wait0();
        __syncthreads();
        float acc[2][4][4] = {};
        mma_gemm16(s_y, 136, s_W, acc, warp, lane);
        __syncthreads();
        if (chunk < 3) stage_async(g_wbf + (chunk+1)*16384, s_W, tid);
        const float* bsrc = (chunk < 3) ? (qkv_b + chunk*128) : g_bc;
        #pragma unroll
        for (int mt = 0; mt < 2; ++mt)
            #pragma unroll
            for (int nt = 0; nt < 4; ++nt) {
                int r0 = rbase + mt*16;
                int c0 = cbase + nt*8 + 2*tg;
                float b0 = bsrc[c0], b1 = bsrc[c0+1];
                int off = chunk*64 + (c0 >> 1);
                qw[ r0   *260 + off] = bf2(acc[mt][nt][0] + b0, acc[mt][nt][1] + b1);
                qw[(r0+8)*260 + off] = bf2(acc[mt][nt][2] + b0, acc[mt][nt][3] + b1);
            }
    }
    __syncthreads();

    // Phase B: head-mixing attention; 4 threads/token, 2 heads each; ao -> s_y
    {
        int r = tid >> 2, q4 = tid & 3, n = r & 63;
        const uint32_t* base = qw + r*260;
        const float* pb = pos_bias + n*64;
        uint32_t* aw = (uint32_t*)s_y;
        #pragma unroll
        for (int hh = 0; hh < 2; ++hh) {
            int hI = q4*2 + hh;
            float qv[16];
            #pragma unroll
            for (int d = 0; d < 8; ++d) {
                float2 f = ubf2f(base[hI*24 + d]);
                qv[2*d] = f.x; qv[2*d+1] = f.y;
            }
            float sc[8]; float mx = -1e30f;
            #pragma unroll
            for (int gg = 0; gg < 8; ++gg) {
                const uint32_t* kp = base + gg*24 + 8;
                float sd = 0.f;
                #pragma unroll
                for (int d = 0; d < 8; ++d) {
                    float2 f = ubf2f(kp[d]);
                    sd += qv[2*d]*f.x + qv[2*d+1]*f.y;
                }
                sc[gg] = sd*0.25f + pb[hI*8 + gg];
                mx = fmaxf(mx, sc[gg]);
            }
            float ssum = 0.f;
            #pragma unroll
            for (int gg = 0; gg < 8; ++gg) { sc[gg] = __expf(sc[gg] - mx); ssum += sc[gg]; }
            float inv = 1.f / ssum;
            float ao[16];
            #pragma unroll
            for (int d = 0; d < 16; ++d) ao[d] = 0.f;
            #pragma unroll
            for (int gg = 0; gg < 8; ++gg) {
                float a = sc[gg]*inv;
                const uint32_t* vp = base + gg*24 + 16;
                #pragma unroll
                for (int d = 0; d < 8; ++d) {
                    float2 f = ubf2f(vp[d]);
                    ao[2*d]   += a*f.x;
                    ao[2*d+1] += a*f.y;
                }
            }
            #pragma unroll
            for (int d = 0; d < 8; ++d)
                aw[r*68 + hI*8 + d] = bf2(ao[2*d], ao[2*d+1]);
        }
    }

    // Phase C: token-dim dwconv on xc; read->regs, sync, write cols 0..63
    uint32_t cres[16];
    #pragma unroll
    for (int it = 0; it < 16; ++it) {
        int idx = tid + it*512;
        int r = idx >> 6, cw = idx & 63, n = r & 63;
        int c0 = cw*2;
        float2 m  = ubf2f(qw[r*260 + 192 + cw]);
        float2 lo = make_float2(0.f, 0.f), hi = make_float2(0.f, 0.f);
        if (n > 0)  lo = ubf2f(qw[(r-1)*260 + 192 + cw]);
        if (n < 63) hi = ubf2f(qw[(r+1)*260 + 192 + cw]);
        float d0 = lo.x*dw1_w[c0*3]   + m.x*dw1_w[c0*3+1] + hi.x*dw1_w[c0*3+2] + dw1_b[c0];
        float d1 = lo.y*dw1_w[c0*3+3] + m.y*dw1_w[c0*3+4] + hi.y*dw1_w[c0*3+5] + dw1_b[c0+1];
        cres[it] = bf2(d0, d1);
    }
    __syncthreads();
    stage_async(g_wbf + 4*16384, s_W, tid);
    #pragma unroll
    for (int it = 0; it < 16; ++it) {
        int idx = tid + it*512;
        qw[(idx >> 6)*260 + (idx & 63)] = cres[it];
    }
    stage_wait0();
    __syncthreads();

    // Phase D: ao @ out_w^T + dconv @ tok_w^T -> g_att (bf16)
    float acc[2][4][4] = {};
    mma_gemm16(s_y, 136, s_W, acc, warp, lane);
    __syncthreads();
    stage_async(g_wbf + 5*16384, s_W, tid);
    stage_wait0();
    __syncthreads();
    mma_gemm16(s_qkv, 520, s_W, acc, warp, lane);
    uint32_t* ow = (uint32_t*)g_att + (size_t)win0*4096;
    #pragma unroll
    for (int mt = 0; mt < 2; ++mt)
        #pragma unroll
        for (int nt = 0; nt < 4; ++nt) {
            int r0 = rbase + mt*16;
            int c0 = cbase + nt*8 + 2*tg;
            float b0 = out_b[c0] + tok_b[c0], b1 = out_b[c0+1] + tok_b[c0+1];
            ow[ r0   *64 + (c0 >> 1)] = bf2(acc[mt][nt][0] + b0, acc[mt][nt][1] + b1);
            ow[(r0+8)*64 + (c0 >> 1)] = bf2(acc[mt][nt][2] + b0, acc[mt][nt][3] + b1);
        }
}

// ---------------- LN2 + lpw fused: 128 pixels per CTA, 512 threads ----------------
__global__ void k_ln2z(const float* __restrict__ x, const float* __restrict__ w,
                       const float* __restrict__ b) {
    extern __shared__ __align__(16) char smem[];
    float* s = (float*)smem;                                      // 128*129 fp32
    __nv_bfloat16* s_A = (__nv_bfloat16*)(smem + 66048);          // 128*136
    __nv_bfloat16* s_W = (__nv_bfloat16*)(smem + 66048 + 34816);  // 128*136
    __shared__ float s_mu[128], s_rs[128];
    int tid = threadIdx.x, bid = blockIdx.x;
    int warp = tid >> 5, lane = tid & 31;
    int w0 = (bid & 1) * 128;
    int h  = (bid >> 1) & 255;
    int bb = bid >> 9;
    stage_async(g_wbf + 6*16384, s_W, tid);
    const float* xb = x + (size_t)bb*CCH*65536 + h*256 + w0;
    for (int idx = tid; idx < 16384; idx += 512) {
        int c = idx >> 7, p = idx & 127;
        s[p*129 + c] = xb[c*65536 + p];
    }
    __syncthreads();
    const uint32_t* attw = (const uint32_t*)g_att;
    for (int idx = tid; idx < 8192; idx += 512) {
        int pp = idx >> 6, cw = idx & 63, c0 = cw*2;
        int wc = w0 + pp;
        int win = (bb*32 + (h >> 3))*32 + (wc >> 3);
        int n   = (h & 7)*8 + (wc & 7);
        float2 a = ubf2f(attw[(size_t)win*4096 + n*64 + cw]);
        float v0 = s[pp*129 + c0]     + a.x;
        float v1 = s[pp*129 + c0 + 1] + a.y;
        s[pp*129 + c0]     = v0;
        s[pp*129 + c0 + 1] = v1;
        *(float2*)&g_x1[((size_t)(bb*65536 + h*256 + wc))*128 + c0] = make_float2(v0, v1);
    }
    __syncthreads();
    int p = tid >> 2, q = tid & 3;
    float sm = 0.f, sq = 0.f;
    #pragma unroll
    for (int i = 0; i < 32; ++i) { float v = s[p*129 + q*32 + i]; sm += v; sq += v*v; }
    sm += __shfl_xor_sync(0xffffffffu, sm, 1); sq += __shfl_xor_sync(0xffffffffu, sq, 1);
    sm += __shfl_xor_sync(0xffffffffu, sm, 2); sq += __shfl_xor_sync(0xffffffffu, sq, 2);
    if (q == 0) {
        float mu = sm * (1.f/128.f);
        float var = sq * (1.f/128.f) - mu*mu;
        s_mu[p] = mu; s_rs[p] = rsqrtf(var + 1e-5f);
    }
    __syncthreads();
    uint32_t* aw = (uint32_t*)s_A;
    for (int idx = tid; idx < 8192; idx += 512) {
        int pp = idx >> 6, cw = idx & 63;
        int c0 = cw*2;
        float mu = s_mu[pp], rs = s_rs[pp];
        float v0 = (s[pp*129 + c0]   - mu) * rs * w[c0]   + b[c0];
        float v1 = (s[pp*129 + c0+1] - mu) * rs * w[c0+1] + b[c0+1];
        aw[pp*68 + cw] = bf2(v0, v1);
    }
    stage_wait0();
    __syncthreads();
    float acc[2][4][4] = {};
    mma_gemm16(s_A, 136, s_W, acc, warp, lane);
    int g = lane >> 2, tg = lane & 3;
    int rbase = (warp & 3) * 32 + g;
    int cbase = (warp >> 2) * 32;
    size_t pixb = (size_t)(bb*65536 + h*256 + w0);
    uint32_t* zw = (uint32_t*)g_z;
    #pragma unroll
    for (int mt = 0; mt < 2; ++mt)
        #pragma unroll
        for (int nt = 0; nt < 4; ++nt) {
            int r0 = rbase + mt*16;
            int c0 = cbase + nt*8 + 2*tg;
            zw[(pixb + r0)  *64 + (c0 >> 1)] = bf2(acc[mt][nt][0], acc[mt][nt][1]);
            zw[(pixb + r0+8)*64 + (c0 >> 1)] = bf2(acc[mt][nt][2], acc[mt][nt][3]);
        }
}

// ---------------- LeFF: 128 pixels per CTA, 512 threads, double-buffered weights ----------------
__global__ void k_leff(const float* __restrict__ ldw_w, const float* __restrict__ ldw_b,
                       const float* __restrict__ fc1_b, const float* __restrict__ fc2_b,
                       float* __restrict__ out) {
    extern __shared__ __align__(16) char smem[];
    __nv_bfloat16* s_d  = (__nv_bfloat16*)smem;                   // 128*136
    __nv_bfloat16* s_t  = (__nv_bfloat16*)(smem + 34816);         // 128*136
    __nv_bfloat16* s_W0 = (__nv_bfloat16*)(smem + 69632);         // fc1 buffer
    __nv_bfloat16* s_W1 = (__nv_bfloat16*)(smem + 104448);        // fc2 buffer
    float* s_f = (float*)(smem + 34816);                          // aliases s_t + s_W0
    int tid = threadIdx.x, warp = tid >> 5, lane = tid & 31, bid = blockIdx.x;
    int w0 = (bid & 1) * 128;
    int h  = (bid >> 1) & 255;
    int bb = bid >> 9;

    stage_async(g_wbf + 7*16384, s_W0, tid);    // fc1[0]

    // 3x3 depthwise over g_z (bf16 channels-last), zero padding
    {
        const uint32_t* zw = (const uint32_t*)g_z;
        uint32_t* dw = (uint32_t*)s_d;
        for (int idx = tid; idx < 8192; idx += 512) {
            int p = idx >> 6, cw = idx & 63;
            int c0 = cw*2;
            int xx0 = w0 + p;
            float accA = ldw_b[c0], accB = ldw_b[c0+1];
            #pragma unroll
            for (int dy = 0; dy < 3; ++dy) {
                int yy = h + dy - 1;
                if (yy < 0 || yy > 255) continue;
                #pragma unroll
                for (int dx = 0; dx < 3; ++dx) {
                    int xx = xx0 + dx - 1;
                    if (xx < 0 || xx > 255) continue;
                    float2 t = ubf2f(zw[((size_t)(bb*65536 + yy*256 + xx))*64 + cw]);
                    accA += t.x * ldw_w[c0*9     + dy*3 + dx];
                    accB += t.y * ldw_w[(c0+1)*9 + dy*3 + dx];
                }
            }
            dw[p*68 + cw] = bf2(accA, accB);
        }
    }
    stage_async(g_wbf + 11*16384, s_W1, tid);   // fc2[0]

    int g = lane >> 2, tg = lane & 3;
    int rbase = (warp & 3) * 32 + g;
    int cbase = (warp >> 2) * 32;
    float oacc[2][4][4] = {};
    for (int jc = 0; jc < 4; ++jc) {
        stage_wait1();                 // fc1[jc] landed (fc2[jc] may still fly)
        __syncthreads();
        float tacc[2][4][4] = {};
        mma_gemm16(s_d, 136, s_W0, tacc, warp, lane);
        __syncthreads();               // fc1 buffer reads done
        if (jc < 3) stage_async(g_wbf + (8+jc)*16384, s_W0, tid);
        uint32_t* tw = (uint32_t*)s_t;
        #pragma unroll
        for (int mt = 0; mt < 2; ++mt)
            #pragma unroll
            for (int nt = 0; nt < 4; ++nt) {
                int r0 = rbase + mt*16;
                int c0 = cbase + nt*8 + 2*tg;
                float b0 = fc1_b[jc*128 + c0], b1 = fc1_b[jc*128 + c0 + 1];
                float v0 = gelu_f(tacc[mt][nt][0] + b0);
                float v1 = gelu_f(tacc[mt][nt][1] + b1);
                float v2 = gelu_f(tacc[mt][nt][2] + b0);
                float v3 = gelu_f(tacc[mt][nt][3] + b1);
                tw[ r0   *68 + (c0 >> 1)] = bf2(v0, v1);
                tw[(r0+8)*68 + (c0 >> 1)] = bf2(v2, v3);
            }
        if (jc < 3) stage_wait1(); else stage_wait0();   // fc2[jc] landed
        __syncthreads();
        mma_gemm16(s_t, 136, s_W1, oacc, warp, lane);
        __syncthreads();               // fc2 buffer + s_t reads done
        if (jc < 3) stage_async(g_wbf + (12+jc)*16384, s_W1, tid);
    }

    // epilogue: + fc2_b + residual x1 (fp32), stage fp32, transpose-write NCHW
    size_t pixb = (size_t)(bb*65536 + h*256 + w0);
    #pragma unroll
    for (int mt = 0; mt < 2; ++mt)
        #pragma unroll
        for (int nt = 0; nt < 4; ++nt) {
            int r0 = rbase + mt*16;
            int c0 = cbase + nt*8 + 2*tg;
            float b0 = fc2_b[c0], b1 = fc2_b[c0+1];
            float2 x0 = *(const float2*)&g_x1[(pixb + r0)  *128 + c0];
            float2 x1 = *(const float2*)&g_x1[(pixb + r0+8)*128 + c0];
            s_f[ r0   *129 + c0]     = oacc[mt][nt][0] + b0 + x0.x;
            s_f[ r0   *129 + c0 + 1] = oacc[mt][nt][1] + b1 + x0.y;
            s_f[(r0+8)*129 + c0]     = oacc[mt][nt][2] + b0 + x1.x;
            s_f[(r0+8)*129 + c0 + 1] = oacc[mt][nt][3] + b1 + x1.y;
        }
    __syncthreads();
    for (int idx = tid; idx < 16384; idx += 512) {
        int c = idx >> 7, p = idx & 127;
        out[((size_t)(bb*128 + c)*256 + h)*256 + w0 + p] = s_f[p*129 + c];
    }
}

// ---------------- launch ----------------
extern "C" void kernel_launch(void* const* d_in, const int* in_sizes, int n_in,
                              void* d_out, int out_size) {
    const float* x        = (const float*)d_in[0];
    const float* norm1_w  = (const float*)d_in[1];
    const float* norm1_b  = (const float*)d_in[2];
    const float* qkv_w    = (const float*)d_in[3];
    const float* qkv_b    = (const float*)d_in[4];
    const float* pos_bias = (const float*)d_in[5];
    const float* out_w    = (const float*)d_in[6];
    const float* out_b    = (const float*)d_in[7];
    const float* convp_w  = (const float*)d_in[8];
    const float* convp_b  = (const float*)d_in[9];
    const float* pw1_w    = (const float*)d_in[10];
    const float* pw1_b    = (const float*)d_in[11];
    const float* dw1_w    = (const float*)d_in[12];
    const float* dw1_b    = (const float*)d_in[13];
    const float* tok_w    = (const float*)d_in[14];
    const float* tok_b    = (const float*)d_in[15];
    const float* norm2_w  = (const float*)d_in[16];
    const float* norm2_b  = (const float*)d_in[17];
    const float* lpw_w    = (const float*)d_in[18];
    const float* ldw_w    = (const float*)d_in[19];
    const float* ldw_b    = (const float*)d_in[20];
    const float* fc1_w    = (const float*)d_in[21];
    const float* fc1_b    = (const float*)d_in[22];
    const float* fc2_w    = (const float*)d_in[23];
    const float* fc2_b    = (const float*)d_in[24];
    float* out = (float*)d_out;

    const int SM_REMSA = 133120 + 34816 + 34816;          // 202752
    const int SM_LN2Z  = 66048 + 34816 + 34816;           // 135680
    const int SM_LEFF  = 34816*4;                         // 139264
    cudaFuncSetAttribute(k_remsa, cudaFuncAttributeMaxDynamicSharedMemorySize, SM_REMSA);
    cudaFuncSetAttribute(k_ln2z,  cudaFuncAttributeMaxDynamicSharedMemorySize, SM_LN2Z);
    cudaFuncSetAttribute(k_leff,  cudaFuncAttributeMaxDynamicSharedMemorySize, SM_LEFF);

    k_fuse <<<64,   256>>>(convp_w, convp_b, pw1_w, pw1_b);
    k_prep <<<960,  256>>>(qkv_w, out_w, tok_w, lpw_w, fc1_w, fc2_w);
    k_remsa<<<2048, 512, SM_REMSA>>>(x, norm1_w, norm1_b, qkv_b, pos_bias,
                                     out_b, tok_b, dw1_w, dw1_b);
    k_ln2z <<<2048, 512, SM_LN2Z>>>(x, norm2_w, norm2_b);
    k_leff <<<2048, 512, SM_LEFF>>>(ldw_w, ldw_b, fc1_b, fc2_b, out);
}

// round 9
// speedup vs baseline: 4.8735x; 1.2348x over previous
#include <cuda_runtime.h>
#include <cuda_bf16.h>
#include <cstdint>
#include <math.h>

#define BATCH 4
#define CCH 128
#define NPIX (BATCH*256*256)     /* 262144 */
#define NWIN (NPIX/64)           /* 4096 */

// ---------------- device scratch ----------------
__device__ float g_bc[CCH];
// bf16 weight bank: [0..2]=qkv, [3]=Wc, [4]=out_w, [5]=tok_w, [6]=lpw,
// [7..10]=fc1 chunks, [11..14]=fc2 chunks. Each 128x128 row-major.
__device__ __nv_bfloat16 g_wbf[15*16384];
__device__ __nv_bfloat16 g_att[NPIX*CCH]; // remsa out bf16, window-token layout
__device__ float g_x1[NPIX*CCH];          // x + merged attn, channels-last fp32
__device__ __nv_bfloat16 g_z[NPIX*CCH];   // lpw out, channels-last bf16

// ---------------- helpers ----------------
__device__ __forceinline__ uint32_t bf2(float a, float b) {
    __nv_bfloat162 t = __floats2bfloat162_rn(a, b);
    return *reinterpret_cast<uint32_t*>(&t);
}
__device__ __forceinline__ float2 ubf2f(uint32_t w) {
    __nv_bfloat162 t = *reinterpret_cast<__nv_bfloat162*>(&w);
    return make_float2(__bfloat162float(t.x), __bfloat162float(t.y));
}

// exact-GELU via FMA-only erf polynomial (|z|<=1); rare tail uses erff
__device__ __forceinline__ float gelu_f(float v) {
    float z = v * 0.7071067811865475f;
    float e;
    if (fabsf(z) <= 1.0f) {
        float s = z*z;
        e = 7.853861595399774e-5f;
        e = e*s - 8.010193625184903e-4f;
        e = e*s + 5.188327685732524e-3f;
        e = e*s - 2.685381193529856e-2f;
        e = e*s + 1.128358514861418e-1f;
        e = e*s - 3.761262582423300e-1f;
        e = e*s + 1.128379165726710f;
        e = e*z;
    } else {
        e = erff(z);
    }
    return v * (0.5f + 0.5f*e);
}

__device__ __forceinline__ void mma16(float* c, const uint32_t* a, const uint32_t* b) {
    asm volatile(
        "mma.sync.aligned.m16n8k16.row.col.f32.bf16.bf16.f32 "
        "{%0,%1,%2,%3},{%4,%5,%6,%7},{%8,%9},{%0,%1,%2,%3};"
        : "+f"(c[0]), "+f"(c[1]), "+f"(c[2]), "+f"(c[3])
        : "r"(a[0]), "r"(a[1]), "r"(a[2]), "r"(a[3]), "r"(b[0]), "r"(b[1]));
}

#define LDSM4(R, addr) \
    asm volatile("ldmatrix.sync.aligned.m8n8.x4.shared.b16 {%0,%1,%2,%3}, [%4];" \
        : "=r"(R[0]), "=r"(R[1]), "=r"(R[2]), "=r"(R[3]) : "r"(addr))

// async stage: prepacked 128x128 bf16 weight -> smem [128][136]
__device__ __forceinline__ void stage_async(const __nv_bfloat16* __restrict__ Wb,
                                            __nv_bfloat16* __restrict__ sW, int tid) {
    uint32_t s = (uint32_t)__cvta_generic_to_shared(sW);
    const char* gp = (const char*)Wb;
    #pragma unroll
    for (int i = tid; i < 2048; i += 512) {
        int row = i >> 4, c8 = (i & 15) << 3;
        asm volatile("cp.async.cg.shared.global [%0], [%1], 16;"
            :: "r"(s + (uint32_t)(row*136 + c8)*2), "l"(gp + i*16));
    }
    asm volatile("cp.async.commit_group;" ::: "memory");
}
__device__ __forceinline__ void stage_wait0() {
    asm volatile("cp.async.wait_group 0;" ::: "memory");
}

// 128x128 GEMM tile, K=128, bf16 in, fp32 accum. 16 warps, each 32x32. ldmatrix loads.
__device__ __forceinline__ void mma_gemm16(const __nv_bfloat16* __restrict__ sA, int strideA,
                                           const __nv_bfloat16* __restrict__ sW,
                                           float acc[2][4][4], int warp, int lane) {
    int quad = lane >> 3, r = lane & 7;
    uint32_t aAddr = (uint32_t)__cvta_generic_to_shared(sA)
        + (uint32_t)((((warp & 3)*32 + (quad & 1)*8 + r) * strideA + (quad >> 1)*8) * 2);
    uint32_t bAddr = (uint32_t)__cvta_generic_to_shared(sW)
        + (uint32_t)((((warp >> 2)*32 + (quad >> 1)*8 + r) * 136 + (quad & 1)*8) * 2);
    uint32_t aStep = (uint32_t)(16 * strideA * 2);
    const uint32_t bStep = 16 * 136 * 2;
    #pragma unroll
    for (int kt = 0; kt < 8; ++kt) {
        uint32_t A0[4], A1[4], B0[4], B1[4];
        LDSM4(A0, aAddr);
        LDSM4(A1, aAddr + aStep);
        LDSM4(B0, bAddr);
        LDSM4(B1, bAddr + bStep);
        aAddr += 32; bAddr += 32;
        mma16(acc[0][0], A0, B0);     mma16(acc[0][1], A0, B0 + 2);
        mma16(acc[0][2], A0, B1);     mma16(acc[0][3], A0, B1 + 2);
        mma16(acc[1][0], A1, B0);     mma16(acc[1][1], A1, B0 + 2);
        mma16(acc[1][2], A1, B1);     mma16(acc[1][3], A1, B1 + 2);
    }
}

// ---------------- K0: pack weights to bf16 bank (Wc fused inline) ----------------
__global__ void k_prep(const float* __restrict__ qkv_w, const float* __restrict__ out_w,
                       const float* __restrict__ tok_w, const float* __restrict__ lpw_w,
                       const float* __restrict__ fc1_w, const float* __restrict__ fc2_w,
                       const float* __restrict__ convp_w, const float* __restrict__ convp_b,
                       const float* __restrict__ pw1_w,   const float* __restrict__ pw1_b) {
    int idx = blockIdx.x*256 + threadIdx.x;
    int blk = idx >> 14;
    int m = idx & 16383;
    int c = m >> 7, k = m & 127;
    float v;
    if      (blk < 3)  v = qkv_w[blk*16384 + m];
    else if (blk == 3) {
        v = 0.f;
        for (int i = 0; i < CCH; ++i) v += pw1_w[c*CCH + i] * convp_w[i*CCH + k];
    }
    else if (blk == 4) v = out_w[m];
    else if (blk == 5) v = tok_w[m];
    else if (blk == 6) v = lpw_w[m];
    else if (blk < 11) v = fc1_w[(blk-7)*16384 + m];
    else               v = fc2_w[c*512 + (blk-11)*128 + k];
    g_wbf[idx] = __float2bfloat16(v);
    if (idx < CCH) {
        float b = pw1_b[idx];
        for (int i = 0; i < CCH; ++i) b += pw1_w[idx*CCH + i] * convp_b[i];
        g_bc[idx] = b;
    }
}

// ---------------- ReMSA (LN1 fused): 2 windows per CTA, 512 threads ----------------
__global__ void k_remsa(const float* __restrict__ x,
                        const float* __restrict__ n1w, const float* __restrict__ n1b,
                        const float* __restrict__ qkv_b, const float* __restrict__ pos_bias,
                        const float* __restrict__ out_b, const float* __restrict__ tok_b,
                        const float* __restrict__ dw1_w, const float* __restrict__ dw1_b) {
    extern __shared__ __align__(16) char smem[];
    __nv_bfloat16* s_qkv = (__nv_bfloat16*)smem;                   // 128*520 bf16 (also s_x fp32)
    __nv_bfloat16* s_y   = (__nv_bfloat16*)(smem + 133120);        // 128*136 (LN1 / ao)
    __nv_bfloat16* s_W   = (__nv_bfloat16*)(smem + 133120 + 34816);
    __shared__ float s_mu[128], s_rs[128];
    int tid = threadIdx.x, warp = tid >> 5, lane = tid & 31;
    int win0 = blockIdx.x * 2;
    int bb   = win0 >> 10;
    int rem  = win0 & 1023;
    int h0   = (rem >> 5) * 8;
    int w0c  = (rem & 31) * 8;   // 16 columns wide (2 windows)

    stage_async(g_wbf, s_W, tid);    // prefetch qkv chunk 0

    // ---- LN1 fused: load x tile (128 ch x 8 rows x 16 cols) into s_x fp32 ----
    float* s_x = (float*)s_qkv;      // [128 tokens][129]
    const float* xb = x + (size_t)bb*CCH*65536 + h0*256 + w0c;
    #pragma unroll
    for (int it = 0; it < 8; ++it) {
        int idx = tid + it*512;                 // 4096 float4
        int c = idx >> 5, r = (idx >> 2) & 7, w4 = idx & 3;
        float4 v = *(const float4*)(xb + c*65536 + r*256 + w4*4);
        int wb = w4*4;
        int row0 = (wb >> 3)*64 + r*8 + (wb & 7);
        s_x[(row0  )*129 + c] = v.x;
        s_x[(row0+1)*129 + c] = v.y;
        s_x[(row0+2)*129 + c] = v.z;
        s_x[(row0+3)*129 + c] = v.w;
    }
    __syncthreads();
    {
        int p = tid >> 2, q = tid & 3;
        float sm = 0.f, sq = 0.f;
        #pragma unroll
        for (int i = 0; i < 32; ++i) { float v = s_x[p*129 + q*32 + i]; sm += v; sq += v*v; }
        sm += __shfl_xor_sync(0xffffffffu, sm, 1); sq += __shfl_xor_sync(0xffffffffu, sq, 1);
        sm += __shfl_xor_sync(0xffffffffu, sm, 2); sq += __shfl_xor_sync(0xffffffffu, sq, 2);
        if (q == 0) {
            float mu = sm * (1.f/128.f);
            float var = sq * (1.f/128.f) - mu*mu;
            s_mu[p] = mu; s_rs[p] = rsqrtf(var + 1e-5f);
        }
    }
    __syncthreads();
    uint32_t* s_yw = (uint32_t*)s_y;
    for (int idx = tid; idx < 8192; idx += 512) {
        int pp = idx >> 6, cw = idx & 63, c0 = cw*2;
        float mu = s_mu[pp], rs = s_rs[pp];
        float v0 = (s_x[pp*129 + c0]   - mu) * rs * n1w[c0]   + n1b[c0];
        float v1 = (s_x[pp*129 + c0+1] - mu) * rs * n1w[c0+1] + n1b[c0+1];
        s_yw[pp*68 + cw] = bf2(v0, v1);
    }

    int g = lane >> 2, tg = lane & 3;
    int rbase = (warp & 3) * 32 + g;
    int cbase = (warp >> 2) * 32;
    uint32_t* qw = (uint32_t*)s_qkv;   // stride 260 words per row (overwrites s_x)

    // Phase A: [qkv ; Wc] GEMM (128 x 512) -> s_qkv bf16
    for (int chunk = 0; chunk < 4; ++chunk) {
        stage_wait0();
        __syncthreads();
        float acc[2][4][4] = {};
        mma_gemm16(s_y, 136, s_W, acc, warp, lane);
        __syncthreads();
        if (chunk < 3) stage_async(g_wbf + (chunk+1)*16384, s_W, tid);
        const float* bsrc = (chunk < 3) ? (qkv_b + chunk*128) : g_bc;
        #pragma unroll
        for (int mt = 0; mt < 2; ++mt)
            #pragma unroll
            for (int nt = 0; nt < 4; ++nt) {
                int r0 = rbase + mt*16;
                int c0 = cbase + nt*8 + 2*tg;
                float b0 = bsrc[c0], b1 = bsrc[c0+1];
                int off = chunk*64 + (c0 >> 1);
                qw[ r0   *260 + off] = bf2(acc[mt][nt][0] + b0, acc[mt][nt][1] + b1);
                qw[(r0+8)*260 + off] = bf2(acc[mt][nt][2] + b0, acc[mt][nt][3] + b1);
            }
    }
    __syncthreads();

    // Phase B: head-mixing attention; 4 threads/token, 2 heads each; ao -> s_y
    {
        int r = tid >> 2, q4 = tid & 3, n = r & 63;
        const uint32_t* base = qw + r*260;
        const float* pb = pos_bias + n*64;
        uint32_t* aw = (uint32_t*)s_y;
        #pragma unroll
        for (int hh = 0; hh < 2; ++hh) {
            int hI = q4*2 + hh;
            float qv[16];
            #pragma unroll
            for (int d = 0; d < 8; ++d) {
                float2 f = ubf2f(base[hI*24 + d]);
                qv[2*d] = f.x; qv[2*d+1] = f.y;
            }
            float sc[8]; float mx = -1e30f;
            #pragma unroll
            for (int gg = 0; gg < 8; ++gg) {
                const uint32_t* kp = base + gg*24 + 8;
                float sd = 0.f;
                #pragma unroll
                for (int d = 0; d < 8; ++d) {
                    float2 f = ubf2f(kp[d]);
                    sd += qv[2*d]*f.x + qv[2*d+1]*f.y;
                }
                sc[gg] = sd*0.25f + pb[hI*8 + gg];
                mx = fmaxf(mx, sc[gg]);
            }
            float ssum = 0.f;
            #pragma unroll
            for (int gg = 0; gg < 8; ++gg) { sc[gg] = __expf(sc[gg] - mx); ssum += sc[gg]; }
            float inv = 1.f / ssum;
            float ao[16];
            #pragma unroll
            for (int d = 0; d < 16; ++d) ao[d] = 0.f;
            #pragma unroll
            for (int gg = 0; gg < 8; ++gg) {
                float a = sc[gg]*inv;
                const uint32_t* vp = base + gg*24 + 16;
                #pragma unroll
                for (int d = 0; d < 8; ++d) {
                    float2 f = ubf2f(vp[d]);
                    ao[2*d]   += a*f.x;
                    ao[2*d+1] += a*f.y;
                }
            }
            #pragma unroll
            for (int d = 0; d < 8; ++d)
                aw[r*68 + hI*8 + d] = bf2(ao[2*d], ao[2*d+1]);
        }
    }

    // Phase C: token-dim dwconv on xc; read->regs, sync, write cols 0..63
    uint32_t cres[16];
    #pragma unroll
    for (int it = 0; it < 16; ++it) {
        int idx = tid + it*512;
        int r = idx >> 6, cw = idx & 63, n = r & 63;
        int c0 = cw*2;
        float2 m  = ubf2f(qw[r*260 + 192 + cw]);
        float2 lo = make_float2(0.f, 0.f), hi = make_float2(0.f, 0.f);
        if (n > 0)  lo = ubf2f(qw[(r-1)*260 + 192 + cw]);
        if (n < 63) hi = ubf2f(qw[(r+1)*260 + 192 + cw]);
        float d0 = lo.x*dw1_w[c0*3]   + m.x*dw1_w[c0*3+1] + hi.x*dw1_w[c0*3+2] + dw1_b[c0];
        float d1 = lo.y*dw1_w[c0*3+3] + m.y*dw1_w[c0*3+4] + hi.y*dw1_w[c0*3+5] + dw1_b[c0+1];
        cres[it] = bf2(d0, d1);
    }
    __syncthreads();
    stage_async(g_wbf + 4*16384, s_W, tid);
    #pragma unroll
    for (int it = 0; it < 16; ++it) {
        int idx = tid + it*512;
        qw[(idx >> 6)*260 + (idx & 63)] = cres[it];
    }
    stage_wait0();
    __syncthreads();

    // Phase D: ao @ out_w^T + dconv @ tok_w^T -> g_att (bf16)
    float acc[2][4][4] = {};
    mma_gemm16(s_y, 136, s_W, acc, warp, lane);
    __syncthreads();
    stage_async(g_wbf + 5*16384, s_W, tid);
    stage_wait0();
    __syncthreads();
    mma_gemm16(s_qkv, 520, s_W, acc, warp, lane);
    uint32_t* ow = (uint32_t*)g_att + (size_t)win0*4096;
    #pragma unroll
    for (int mt = 0; mt < 2; ++mt)
        #pragma unroll
        for (int nt = 0; nt < 4; ++nt) {
            int r0 = rbase + mt*16;
            int c0 = cbase + nt*8 + 2*tg;
            float b0 = out_b[c0] + tok_b[c0], b1 = out_b[c0+1] + tok_b[c0+1];
            ow[ r0   *64 + (c0 >> 1)] = bf2(acc[mt][nt][0] + b0, acc[mt][nt][1] + b1);
            ow[(r0+8)*64 + (c0 >> 1)] = bf2(acc[mt][nt][2] + b0, acc[mt][nt][3] + b1);
        }
}

// ---------------- LN2 + lpw fused: register-resident, 2 CTAs/SM ----------------
__global__ void __launch_bounds__(512, 2) k_ln2z(const float* __restrict__ x,
                                                 const float* __restrict__ w,
                                                 const float* __restrict__ b) {
    extern __shared__ __align__(16) char smem[];
    __nv_bfloat16* s_A = (__nv_bfloat16*)smem;            // 128*136
    __nv_bfloat16* s_W = (__nv_bfloat16*)(smem + 34816);  // 128*136
    int tid = threadIdx.x, bid = blockIdx.x;
    int warp = tid >> 5, lane = tid & 31;
    int w0 = (bid & 1) * 128;
    int h  = (bid >> 1) & 255;
    int bb = bid >> 9;
    stage_async(g_wbf + 6*16384, s_W, tid);

    int p = tid >> 2, q = tid & 3;
    int wc = w0 + p;
    // load x (32 channels of one pixel)
    const float* xp = x + (size_t)bb*CCH*65536 + h*256 + wc + (size_t)q*32*65536;
    float x1[32];
    #pragma unroll
    for (int i = 0; i < 32; ++i) x1[i] = xp[(size_t)i*65536];
    // add attention branch (bf16)
    int win = (bb*32 + (h >> 3))*32 + (wc >> 3);
    int n   = (h & 7)*8 + (wc & 7);
    const uint4* ap = (const uint4*)((const uint32_t*)g_att + (size_t)win*4096 + n*64 + q*16);
    #pragma unroll
    for (int j4 = 0; j4 < 4; ++j4) {
        uint4 u = ap[j4];
        float2 f;
        f = ubf2f(u.x); x1[j4*8+0] += f.x; x1[j4*8+1] += f.y;
        f = ubf2f(u.y); x1[j4*8+2] += f.x; x1[j4*8+3] += f.y;
        f = ubf2f(u.z); x1[j4*8+4] += f.x; x1[j4*8+5] += f.y;
        f = ubf2f(u.w); x1[j4*8+6] += f.x; x1[j4*8+7] += f.y;
    }
    // write x1 fp32 (residual for leff)
    float* xo = g_x1 + ((size_t)(bb*65536 + h*256 + wc))*128 + q*32;
    #pragma unroll
    for (int i = 0; i < 8; ++i)
        *(float4*)(xo + i*4) = make_float4(x1[4*i], x1[4*i+1], x1[4*i+2], x1[4*i+3]);
    // LN stats across the 4 threads of this pixel
    float sm = 0.f, sq = 0.f;
    #pragma unroll
    for (int i = 0; i < 32; ++i) { sm += x1[i]; sq += x1[i]*x1[i]; }
    sm += __shfl_xor_sync(0xffffffffu, sm, 1); sq += __shfl_xor_sync(0xffffffffu, sq, 1);
    sm += __shfl_xor_sync(0xffffffffu, sm, 2); sq += __shfl_xor_sync(0xffffffffu, sq, 2);
    float mu = sm * (1.f/128.f);
    float rs = rsqrtf(sq * (1.f/128.f) - mu*mu + 1e-5f);
    // normalize -> bf16 smem
    uint32_t* aw = (uint32_t*)s_A;
    #pragma unroll
    for (int j = 0; j < 16; ++j) {
        int c0 = q*32 + 2*j;
        float v0 = (x1[2*j]   - mu) * rs * w[c0]   + b[c0];
        float v1 = (x1[2*j+1] - mu) * rs * w[c0+1] + b[c0+1];
        aw[p*68 + q*16 + j] = bf2(v0, v1);
    }
    stage_wait0();
    __syncthreads();
    float acc[2][4][4] = {};
    mma_gemm16(s_A, 136, s_W, acc, warp, lane);
    int g = lane >> 2, tg = lane & 3;
    int rbase = (warp & 3) * 32 + g;
    int cbase = (warp >> 2) * 32;
    size_t pixb = (size_t)(bb*65536 + h*256 + w0);
    uint32_t* zw = (uint32_t*)g_z;
    #pragma unroll
    for (int mt = 0; mt < 2; ++mt)
        #pragma unroll
        for (int nt = 0; nt < 4; ++nt) {
            int r0 = rbase + mt*16;
            int c0 = cbase + nt*8 + 2*tg;
            zw[(pixb + r0)  *64 + (c0 >> 1)] = bf2(acc[mt][nt][0], acc[mt][nt][1]);
            zw[(pixb + r0+8)*64 + (c0 >> 1)] = bf2(acc[mt][nt][2], acc[mt][nt][3]);
        }
}

// ---------------- LeFF: 128 pixels per CTA, 512 threads, 2 CTAs/SM ----------------
__global__ void __launch_bounds__(512, 2) k_leff(const float* __restrict__ ldw_w,
                                                 const float* __restrict__ ldw_b,
                                                 const float* __restrict__ fc1_b,
                                                 const float* __restrict__ fc2_b,
                                                 float* __restrict__ out) {
    extern __shared__ __align__(16) char smem[];
    __nv_bfloat16* s_d = (__nv_bfloat16*)smem;                   // 128*136
    __nv_bfloat16* s_t = (__nv_bfloat16*)(smem + 34816);         // 128*136
    __nv_bfloat16* s_W = (__nv_bfloat16*)(smem + 69632);         // 128*136
    float* s_f = (float*)(smem + 34816);                         // aliases s_t + s_W
    int tid = threadIdx.x, warp = tid >> 5, lane = tid & 31, bid = blockIdx.x;
    int w0 = (bid & 1) * 128;
    int h  = (bid >> 1) & 255;
    int bb = bid >> 9;

    stage_async(g_wbf + 7*16384, s_W, tid);    // fc1[0]

    // 3x3 depthwise over g_z (bf16 channels-last), zero padding
    {
        const uint32_t* zw = (const uint32_t*)g_z;
        uint32_t* dw = (uint32_t*)s_d;
        for (int idx = tid; idx < 8192; idx += 512) {
            int p = idx >> 6, cw = idx & 63;
            int c0 = cw*2;
            int xx0 = w0 + p;
            float accA = ldw_b[c0], accB = ldw_b[c0+1];
            #pragma unroll
            for (int dy = 0; dy < 3; ++dy) {
                int yy = h + dy - 1;
                if (yy < 0 || yy > 255) continue;
                #pragma unroll
                for (int dx = 0; dx < 3; ++dx) {
                    int xx = xx0 + dx - 1;
                    if (xx < 0 || xx > 255) continue;
                    float2 t = ubf2f(zw[((size_t)(bb*65536 + yy*256 + xx))*64 + cw]);
                    accA += t.x * ldw_w[c0*9     + dy*3 + dx];
                    accB += t.y * ldw_w[(c0+1)*9 + dy*3 + dx];
                }
            }
            dw[p*68 + cw] = bf2(accA, accB);
        }
    }

    int g = lane >> 2, tg = lane & 3;
    int rbase = (warp & 3) * 32 + g;
    int cbase = (warp >> 2) * 32;
    float oacc[2][4][4] = {};
    for (int jc = 0; jc < 4; ++jc) {
        stage_wait0();
        __syncthreads();
        float tacc[2][4][4] = {};
        mma_gemm16(s_d, 136, s_W, tacc, warp, lane);
        __syncthreads();
        stage_async(g_wbf + (11+jc)*16384, s_W, tid);   // fc2[jc]
        uint32_t* tw = (uint32_t*)s_t;
        #pragma unroll
        for (int mt = 0; mt < 2; ++mt)
            #pragma unroll
            for (int nt = 0; nt < 4; ++nt) {
                int r0 = rbase + mt*16;
                int c0 = cbase + nt*8 + 2*tg;
                float b0 = fc1_b[jc*128 + c0], b1 = fc1_b[jc*128 + c0 + 1];
                float v0 = gelu_f(tacc[mt][nt][0] + b0);
                float v1 = gelu_f(tacc[mt][nt][1] + b1);
                float v2 = gelu_f(tacc[mt][nt][2] + b0);
                float v3 = gelu_f(tacc[mt][nt][3] + b1);
                tw[ r0   *68 + (c0 >> 1)] = bf2(v0, v1);
                tw[(r0+8)*68 + (c0 >> 1)] = bf2(v2, v3);
            }
        stage_wait0();
        __syncthreads();
        mma_gemm16(s_t, 136, s_W, oacc, warp, lane);
        __syncthreads();
        if (jc < 3) stage_async(g_wbf + (8+jc)*16384, s_W, tid);   // fc1[jc+1]
    }

    // epilogue: + fc2_b + residual x1 (fp32), stage fp32, transpose-write NCHW
    size_t pixb = (size_t)(bb*65536 + h*256 + w0);
    #pragma unroll
    for (int mt = 0; mt < 2; ++mt)
        #pragma unroll
        for (int nt = 0; nt < 4; ++nt) {
            int r0 = rbase + mt*16;
            int c0 = cbase + nt*8 + 2*tg;
            float b0 = fc2_b[c0], b1 = fc2_b[c0+1];
            float2 x0 = *(const float2*)&g_x1[(pixb + r0)  *128 + c0];
            float2 x1 = *(const float2*)&g_x1[(pixb + r0+8)*128 + c0];
            s_f[ r0   *129 + c0]     = oacc[mt][nt][0] + b0 + x0.x;
            s_f[ r0   *129 + c0 + 1] = oacc[mt][nt][1] + b1 + x0.y;
            s_f[(r0+8)*129 + c0]     = oacc[mt][nt][2] + b0 + x1.x;
            s_f[(r0+8)*129 + c0 + 1] = oacc[mt][nt][3] + b1 + x1.y;
        }
    __syncthreads();
    for (int idx = tid; idx < 16384; idx += 512) {
        int c = idx >> 7, p = idx & 127;
        out[((size_t)(bb*128 + c)*256 + h)*256 + w0 + p] = s_f[p*129 + c];
    }
}

// ---------------- launch ----------------
extern "C" void kernel_launch(void* const* d_in, const int* in_sizes, int n_in,
                              void* d_out, int out_size) {
    const float* x        = (const float*)d_in[0];
    const float* norm1_w  = (const float*)d_in[1];
    const float* norm1_b  = (const float*)d_in[2];
    const float* qkv_w    = (const float*)d_in[3];
    const float* qkv_b    = (const float*)d_in[4];
    const float* pos_bias = (const float*)d_in[5];
    const float* out_w    = (const float*)d_in[6];
    const float* out_b    = (const float*)d_in[7];
    const float* convp_w  = (const float*)d_in[8];
    const float* convp_b  = (const float*)d_in[9];
    const float* pw1_w    = (const float*)d_in[10];
    const float* pw1_b    = (const float*)d_in[11];
    const float* dw1_w    = (const float*)d_in[12];
    const float* dw1_b    = (const float*)d_in[13];
    const float* tok_w    = (const float*)d_in[14];
    const float* tok_b    = (const float*)d_in[15];
    const float* norm2_w  = (const float*)d_in[16];
    const float* norm2_b  = (const float*)d_in[17];
    const float* lpw_w    = (const float*)d_in[18];
    const float* ldw_w    = (const float*)d_in[19];
    const float* ldw_b    = (const float*)d_in[20];
    const float* fc1_w    = (const float*)d_in[21];
    const float* fc1_b    = (const float*)d_in[22];
    const float* fc2_w    = (const float*)d_in[23];
    const float* fc2_b    = (const float*)d_in[24];
    float* out = (float*)d_out;

    const int SM_REMSA = 133120 + 34816 + 34816;          // 202752
    const int SM_LN2Z  = 34816 + 34816;                   //  69632
    const int SM_LEFF  = 34816*3;                         // 104448
    cudaFuncSetAttribute(k_remsa, cudaFuncAttributeMaxDynamicSharedMemorySize, SM_REMSA);
    cudaFuncSetAttribute(k_ln2z,  cudaFuncAttributeMaxDynamicSharedMemorySize, SM_LN2Z);
    cudaFuncSetAttribute(k_leff,  cudaFuncAttributeMaxDynamicSharedMemorySize, SM_LEFF);

    k_prep <<<960,  256>>>(qkv_w, out_w, tok_w, lpw_w, fc1_w, fc2_w,
                           convp_w, convp_b, pw1_w, pw1_b);
    k_remsa<<<2048, 512, SM_REMSA>>>(x, norm1_w, norm1_b, qkv_b, pos_bias,
                                     out_b, tok_b, dw1_w, dw1_b);
    k_ln2z <<<2048, 512, SM_LN2Z>>>(x, norm2_w, norm2_b);
    k_leff <<<2048, 512, SM_LEFF>>>(ldw_w, ldw_b, fc1_b, fc2_b, out);
}

// round 10
// speedup vs baseline: 4.9894x; 1.0238x over previous
#include <cuda_runtime.h>
#include <cuda_bf16.h>
#include <cstdint>
#include <math.h>

#define BATCH 4
#define CCH 128
#define NPIX (BATCH*256*256)     /* 262144 */
#define NWIN (NPIX/64)           /* 4096 */

// ---------------- device scratch ----------------
__device__ float g_bc[CCH];
// bf16 weight bank: [0..2]=qkv, [3]=Wc, [4]=out_w, [5]=tok_w, [6]=lpw,
// [7..10]=fc1 chunks, [11..14]=fc2 chunks. Each 128x128 row-major.
__device__ __nv_bfloat16 g_wbf[15*16384];
__device__ __nv_bfloat16 g_att[NPIX*CCH]; // remsa out bf16, window-token layout
__device__ float g_x1[NPIX*CCH];          // x + merged attn, channels-last fp32
__device__ __nv_bfloat16 g_z[NPIX*CCH];   // lpw out, channels-last bf16

// ---------------- helpers ----------------
__device__ __forceinline__ uint32_t bf2(float a, float b) {
    __nv_bfloat162 t = __floats2bfloat162_rn(a, b);
    return *reinterpret_cast<uint32_t*>(&t);
}
__device__ __forceinline__ float2 ubf2f(uint32_t w) {
    __nv_bfloat162 t = *reinterpret_cast<__nv_bfloat162*>(&w);
    return make_float2(__bfloat162float(t.x), __bfloat162float(t.y));
}

// exact-GELU via FMA-only erf polynomial (|z|<=1); rare tail uses erff
__device__ __forceinline__ float gelu_f(float v) {
    float z = v * 0.7071067811865475f;
    float e;
    if (fabsf(z) <= 1.0f) {
        float s = z*z;
        e = 7.853861595399774e-5f;
        e = e*s - 8.010193625184903e-4f;
        e = e*s + 5.188327685732524e-3f;
        e = e*s - 2.685381193529856e-2f;
        e = e*s + 1.128358514861418e-1f;
        e = e*s - 3.761262582423300e-1f;
        e = e*s + 1.128379165726710f;
        e = e*z;
    } else {
        e = erff(z);
    }
    return v * (0.5f + 0.5f*e);
}

__device__ __forceinline__ void mma16(float* c, const uint32_t* a, const uint32_t* b) {
    asm volatile(
        "mma.sync.aligned.m16n8k16.row.col.f32.bf16.bf16.f32 "
        "{%0,%1,%2,%3},{%4,%5,%6,%7},{%8,%9},{%0,%1,%2,%3};"
        : "+f"(c[0]), "+f"(c[1]), "+f"(c[2]), "+f"(c[3])
        : "r"(a[0]), "r"(a[1]), "r"(a[2]), "r"(a[3]), "r"(b[0]), "r"(b[1]));
}

#define LDSM4(R, addr) \
    asm volatile("ldmatrix.sync.aligned.m8n8.x4.shared.b16 {%0,%1,%2,%3}, [%4];" \
        : "=r"(R[0]), "=r"(R[1]), "=r"(R[2]), "=r"(R[3]) : "r"(addr))

// async stage: prepacked 128x128 bf16 weight -> smem [128][136]
__device__ __forceinline__ void stage_async(const __nv_bfloat16* __restrict__ Wb,
                                            __nv_bfloat16* __restrict__ sW, int tid) {
    uint32_t s = (uint32_t)__cvta_generic_to_shared(sW);
    const char* gp = (const char*)Wb;
    #pragma unroll
    for (int i = tid; i < 2048; i += 512) {
        int row = i >> 4, c8 = (i & 15) << 3;
        asm volatile("cp.async.cg.shared.global [%0], [%1], 16;"
            :: "r"(s + (uint32_t)(row*136 + c8)*2), "l"(gp + i*16));
    }
    asm volatile("cp.async.commit_group;" ::: "memory");
}
__device__ __forceinline__ void stage_wait0() {
    asm volatile("cp.async.wait_group 0;" ::: "memory");
}

// 128x128 GEMM tile, K=128, bf16 in, fp32 accum. 16 warps, each 32x32. ldmatrix loads.
__device__ __forceinline__ void mma_gemm16(const __nv_bfloat16* __restrict__ sA, int strideA,
                                           const __nv_bfloat16* __restrict__ sW,
                                           float acc[2][4][4], int warp, int lane) {
    int quad = lane >> 3, r = lane & 7;
    uint32_t aAddr = (uint32_t)__cvta_generic_to_shared(sA)
        + (uint32_t)((((warp & 3)*32 + (quad & 1)*8 + r) * strideA + (quad >> 1)*8) * 2);
    uint32_t bAddr = (uint32_t)__cvta_generic_to_shared(sW)
        + (uint32_t)((((warp >> 2)*32 + (quad >> 1)*8 + r) * 136 + (quad & 1)*8) * 2);
    uint32_t aStep = (uint32_t)(16 * strideA * 2);
    const uint32_t bStep = 16 * 136 * 2;
    #pragma unroll
    for (int kt = 0; kt < 8; ++kt) {
        uint32_t A0[4], A1[4], B0[4], B1[4];
        LDSM4(A0, aAddr);
        LDSM4(A1, aAddr + aStep);
        LDSM4(B0, bAddr);
        LDSM4(B1, bAddr + bStep);
        aAddr += 32; bAddr += 32;
        mma16(acc[0][0], A0, B0);     mma16(acc[0][1], A0, B0 + 2);
        mma16(acc[0][2], A0, B1);     mma16(acc[0][3], A0, B1 + 2);
        mma16(acc[1][0], A1, B0);     mma16(acc[1][1], A1, B0 + 2);
        mma16(acc[1][2], A1, B1);     mma16(acc[1][3], A1, B1 + 2);
    }
}

// Half-N variant: 128x(16-per-warp) columns — tacc is 16 regs, kills spills in leff.
__device__ __forceinline__ void mma_gemm16_n2(const __nv_bfloat16* __restrict__ sA, int strideA,
                                              const __nv_bfloat16* __restrict__ sW,
                                              float acc[2][2][4], int warp, int lane, int nhalf) {
    int quad = lane >> 3, r = lane & 7;
    uint32_t aAddr = (uint32_t)__cvta_generic_to_shared(sA)
        + (uint32_t)((((warp & 3)*32 + (quad & 1)*8 + r) * strideA + (quad >> 1)*8) * 2);
    uint32_t bAddr = (uint32_t)__cvta_generic_to_shared(sW)
        + (uint32_t)((((warp >> 2)*32 + nhalf*16 + (quad >> 1)*8 + r) * 136 + (quad & 1)*8) * 2);
    uint32_t aStep = (uint32_t)(16 * strideA * 2);
    #pragma unroll
    for (int kt = 0; kt < 8; ++kt) {
        uint32_t A0[4], A1[4], B0[4];
        LDSM4(A0, aAddr);
        LDSM4(A1, aAddr + aStep);
        LDSM4(B0, bAddr);
        aAddr += 32; bAddr += 32;
        mma16(acc[0][0], A0, B0);     mma16(acc[0][1], A0, B0 + 2);
        mma16(acc[1][0], A1, B0);     mma16(acc[1][1], A1, B0 + 2);
    }
}

// ---------------- K0: pack weights to bf16 bank (Wc fused inline) ----------------
__global__ void k_prep(const float* __restrict__ qkv_w, const float* __restrict__ out_w,
                       const float* __restrict__ tok_w, const float* __restrict__ lpw_w,
                       const float* __restrict__ fc1_w, const float* __restrict__ fc2_w,
                       const float* __restrict__ convp_w, const float* __restrict__ convp_b,
                       const float* __restrict__ pw1_w,   const float* __restrict__ pw1_b) {
    int idx = blockIdx.x*256 + threadIdx.x;
    int blk = idx >> 14;
    int m = idx & 16383;
    int c = m >> 7, k = m & 127;
    float v;
    if      (blk < 3)  v = qkv_w[blk*16384 + m];
    else if (blk == 3) {
        v = 0.f;
        for (int i = 0; i < CCH; ++i) v += pw1_w[c*CCH + i] * convp_w[i*CCH + k];
    }
    else if (blk == 4) v = out_w[m];
    else if (blk == 5) v = tok_w[m];
    else if (blk == 6) v = lpw_w[m];
    else if (blk < 11) v = fc1_w[(blk-7)*16384 + m];
    else               v = fc2_w[c*512 + (blk-11)*128 + k];
    g_wbf[idx] = __float2bfloat16(v);
    if (idx < CCH) {
        float b = pw1_b[idx];
        for (int i = 0; i < CCH; ++i) b += pw1_w[idx*CCH + i] * convp_b[i];
        g_bc[idx] = b;
    }
}

// ---------------- ReMSA (LN1 fused): 2 windows per CTA, 512 threads ----------------
__global__ void k_remsa(const float* __restrict__ x,
                        const float* __restrict__ n1w, const float* __restrict__ n1b,
                        const float* __restrict__ qkv_b, const float* __restrict__ pos_bias,
                        const float* __restrict__ out_b, const float* __restrict__ tok_b,
                        const float* __restrict__ dw1_w, const float* __restrict__ dw1_b) {
    extern __shared__ __align__(16) char smem[];
    __nv_bfloat16* s_qkv = (__nv_bfloat16*)smem;                   // 128*520 bf16 (also s_x fp32)
    __nv_bfloat16* s_y   = (__nv_bfloat16*)(smem + 133120);        // 128*136 (LN1 / ao)
    __nv_bfloat16* s_W   = (__nv_bfloat16*)(smem + 133120 + 34816);
    __shared__ float s_mu[128], s_rs[128];
    int tid = threadIdx.x, warp = tid >> 5, lane = tid & 31;
    int win0 = blockIdx.x * 2;
    int bb   = win0 >> 10;
    int rem  = win0 & 1023;
    int h0   = (rem >> 5) * 8;
    int w0c  = (rem & 31) * 8;   // 16 columns wide (2 windows)

    stage_async(g_wbf, s_W, tid);    // prefetch qkv chunk 0

    // ---- LN1 fused: load x tile (128 ch x 8 rows x 16 cols) into s_x fp32 ----
    float* s_x = (float*)s_qkv;      // [128 tokens][129]
    const float* xb = x + (size_t)bb*CCH*65536 + h0*256 + w0c;
    #pragma unroll
    for (int it = 0; it < 8; ++it) {
        int idx = tid + it*512;                 // 4096 float4
        int c = idx >> 5, r = (idx >> 2) & 7, w4 = idx & 3;
        float4 v = *(const float4*)(xb + c*65536 + r*256 + w4*4);
        int wb = w4*4;
        int row0 = (wb >> 3)*64 + r*8 + (wb & 7);
        s_x[(row0  )*129 + c] = v.x;
        s_x[(row0+1)*129 + c] = v.y;
        s_x[(row0+2)*129 + c] = v.z;
        s_x[(row0+3)*129 + c] = v.w;
    }
    __syncthreads();
    {
        int p = tid >> 2, q = tid & 3;
        float sm = 0.f, sq = 0.f;
        #pragma unroll
        for (int i = 0; i < 32; ++i) { float v = s_x[p*129 + q*32 + i]; sm += v; sq += v*v; }
        sm += __shfl_xor_sync(0xffffffffu, sm, 1); sq += __shfl_xor_sync(0xffffffffu, sq, 1);
        sm += __shfl_xor_sync(0xffffffffu, sm, 2); sq += __shfl_xor_sync(0xffffffffu, sq, 2);
        if (q == 0) {
            float mu = sm * (1.f/128.f);
            float var = sq * (1.f/128.f) - mu*mu;
            s_mu[p] = mu; s_rs[p] = rsqrtf(var + 1e-5f);
        }
    }
    __syncthreads();
    uint32_t* s_yw = (uint32_t*)s_y;
    for (int idx = tid; idx < 8192; idx += 512) {
        int pp = idx >> 6, cw = idx & 63, c0 = cw*2;
        float mu = s_mu[pp], rs = s_rs[pp];
        float v0 = (s_x[pp*129 + c0]   - mu) * rs * n1w[c0]   + n1b[c0];
        float v1 = (s_x[pp*129 + c0+1] - mu) * rs * n1w[c0+1] + n1b[c0+1];
        s_yw[pp*68 + cw] = bf2(v0, v1);
    }

    int g = lane >> 2, tg = lane & 3;
    int rbase = (warp & 3) * 32 + g;
    int cbase = (warp >> 2) * 32;
    uint32_t* qw = (uint32_t*)s_qkv;   // stride 260 words per row (overwrites s_x)

    // Phase A: [qkv ; Wc] GEMM (128 x 512) -> s_qkv bf16
    for (int chunk = 0; chunk < 4; ++chunk) {
        stage_wait0();
        __syncthreads();
        float acc[2][4][4] = {};
        mma_gemm16(s_y, 136, s_W, acc, warp, lane);
        __syncthreads();
        if (chunk < 3) stage_async(g_wbf + (chunk+1)*16384, s_W, tid);
        const float* bsrc = (chunk < 3) ? (qkv_b + chunk*128) : g_bc;
        #pragma unroll
        for (int mt = 0; mt < 2; ++mt)
            #pragma unroll
            for (int nt = 0; nt < 4; ++nt) {
                int r0 = rbase + mt*16;
                int c0 = cbase + nt*8 + 2*tg;
                float b0 = bsrc[c0], b1 = bsrc[c0+1];
                int off = chunk*64 + (c0 >> 1);
                qw[ r0   *260 + off] = bf2(acc[mt][nt][0] + b0, acc[mt][nt][1] + b1);
                qw[(r0+8)*260 + off] = bf2(acc[mt][nt][2] + b0, acc[mt][nt][3] + b1);
            }
    }
    __syncthreads();

    // Phase B: head-mixing attention; 4 threads/token, 2 heads each; ao -> s_y
    {
        int r = tid >> 2, q4 = tid & 3, n = r & 63;
        const uint32_t* base = qw + r*260;
        const float* pb = pos_bias + n*64;
        uint32_t* aw = (uint32_t*)s_y;
        #pragma unroll
        for (int hh = 0; hh < 2; ++hh) {
            int hI = q4*2 + hh;
            float qv[16];
            #pragma unroll
            for (int d = 0; d < 8; ++d) {
                float2 f = ubf2f(base[hI*24 + d]);
                qv[2*d] = f.x; qv[2*d+1] = f.y;
            }
            float sc[8]; float mx = -1e30f;
            #pragma unroll
            for (int gg = 0; gg < 8; ++gg) {
                const uint32_t* kp = base + gg*24 + 8;
                float sd = 0.f;
                #pragma unroll
                for (int d = 0; d < 8; ++d) {
                    float2 f = ubf2f(kp[d]);
                    sd += qv[2*d]*f.x + qv[2*d+1]*f.y;
                }
                sc[gg] = sd*0.25f + pb[hI*8 + gg];
                mx = fmaxf(mx, sc[gg]);
            }
            float ssum = 0.f;
            #pragma unroll
            for (int gg = 0; gg < 8; ++gg) { sc[gg] = __expf(sc[gg] - mx); ssum += sc[gg]; }
            float inv = 1.f / ssum;
            float ao[16];
            #pragma unroll
            for (int d = 0; d < 16; ++d) ao[d] = 0.f;
            #pragma unroll
            for (int gg = 0; gg < 8; ++gg) {
                float a = sc[gg]*inv;
                const uint32_t* vp = base + gg*24 + 16;
                #pragma unroll
                for (int d = 0; d < 8; ++d) {
                    float2 f = ubf2f(vp[d]);
                    ao[2*d]   += a*f.x;
                    ao[2*d+1] += a*f.y;
                }
            }
            #pragma unroll
            for (int d = 0; d < 8; ++d)
                aw[r*68 + hI*8 + d] = bf2(ao[2*d], ao[2*d+1]);
        }
    }

    // Phase C: token-dim dwconv on xc; read->regs, sync, write cols 0..63
    uint32_t cres[16];
    #pragma unroll
    for (int it = 0; it < 16; ++it) {
        int idx = tid + it*512;
        int r = idx >> 6, cw = idx & 63, n = r & 63;
        int c0 = cw*2;
        float2 m  = ubf2f(qw[r*260 + 192 + cw]);
        float2 lo = make_float2(0.f, 0.f), hi = make_float2(0.f, 0.f);
        if (n > 0)  lo = ubf2f(qw[(r-1)*260 + 192 + cw]);
        if (n < 63) hi = ubf2f(qw[(r+1)*260 + 192 + cw]);
        float d0 = lo.x*dw1_w[c0*3]   + m.x*dw1_w[c0*3+1] + hi.x*dw1_w[c0*3+2] + dw1_b[c0];
        float d1 = lo.y*dw1_w[c0*3+3] + m.y*dw1_w[c0*3+4] + hi.y*dw1_w[c0*3+5] + dw1_b[c0+1];
        cres[it] = bf2(d0, d1);
    }
    __syncthreads();
    stage_async(g_wbf + 4*16384, s_W, tid);
    #pragma unroll
    for (int it = 0; it < 16; ++it) {
        int idx = tid + it*512;
        qw[(idx >> 6)*260 + (idx & 63)] = cres[it];
    }
    stage_wait0();
    __syncthreads();

    // Phase D: ao @ out_w^T + dconv @ tok_w^T -> g_att (bf16)
    float acc[2][4][4] = {};
    mma_gemm16(s_y, 136, s_W, acc, warp, lane);
    __syncthreads();
    stage_async(g_wbf + 5*16384, s_W, tid);
    stage_wait0();
    __syncthreads();
    mma_gemm16(s_qkv, 520, s_W, acc, warp, lane);
    uint32_t* ow = (uint32_t*)g_att + (size_t)win0*4096;
    #pragma unroll
    for (int mt = 0; mt < 2; ++mt)
        #pragma unroll
        for (int nt = 0; nt < 4; ++nt) {
            int r0 = rbase + mt*16;
            int c0 = cbase + nt*8 + 2*tg;
            float b0 = out_b[c0] + tok_b[c0], b1 = out_b[c0+1] + tok_b[c0+1];
            ow[ r0   *64 + (c0 >> 1)] = bf2(acc[mt][nt][0] + b0, acc[mt][nt][1] + b1);
            ow[(r0+8)*64 + (c0 >> 1)] = bf2(acc[mt][nt][2] + b0, acc[mt][nt][3] + b1);
        }
}

// ---------------- LN2 + lpw fused: register-resident, 2 CTAs/SM ----------------
__global__ void __launch_bounds__(512, 2) k_ln2z(const float* __restrict__ x,
                                                 const float* __restrict__ w,
                                                 const float* __restrict__ b) {
    extern __shared__ __align__(16) char smem[];
    __nv_bfloat16* s_A = (__nv_bfloat16*)smem;            // 128*136
    __nv_bfloat16* s_W = (__nv_bfloat16*)(smem + 34816);  // 128*136
    int tid = threadIdx.x, bid = blockIdx.x;
    int warp = tid >> 5, lane = tid & 31;
    int w0 = (bid & 1) * 128;
    int h  = (bid >> 1) & 255;
    int bb = bid >> 9;
    stage_async(g_wbf + 6*16384, s_W, tid);

    int p = tid >> 2, q = tid & 3;
    int wc = w0 + p;
    const float* xp = x + (size_t)bb*CCH*65536 + h*256 + wc + (size_t)q*32*65536;
    float x1[32];
    #pragma unroll
    for (int i = 0; i < 32; ++i) x1[i] = xp[(size_t)i*65536];
    int win = (bb*32 + (h >> 3))*32 + (wc >> 3);
    int n   = (h & 7)*8 + (wc & 7);
    const uint4* ap = (const uint4*)((const uint32_t*)g_att + (size_t)win*4096 + n*64 + q*16);
    #pragma unroll
    for (int j4 = 0; j4 < 4; ++j4) {
        uint4 u = ap[j4];
        float2 f;
        f = ubf2f(u.x); x1[j4*8+0] += f.x; x1[j4*8+1] += f.y;
        f = ubf2f(u.y); x1[j4*8+2] += f.x; x1[j4*8+3] += f.y;
        f = ubf2f(u.z); x1[j4*8+4] += f.x; x1[j4*8+5] += f.y;
        f = ubf2f(u.w); x1[j4*8+6] += f.x; x1[j4*8+7] += f.y;
    }
    float* xo = g_x1 + ((size_t)(bb*65536 + h*256 + wc))*128 + q*32;
    #pragma unroll
    for (int i = 0; i < 8; ++i)
        *(float4*)(xo + i*4) = make_float4(x1[4*i], x1[4*i+1], x1[4*i+2], x1[4*i+3]);
    float sm = 0.f, sq = 0.f;
    #pragma unroll
    for (int i = 0; i < 32; ++i) { sm += x1[i]; sq += x1[i]*x1[i]; }
    sm += __shfl_xor_sync(0xffffffffu, sm, 1); sq += __shfl_xor_sync(0xffffffffu, sq, 1);
    sm += __shfl_xor_sync(0xffffffffu, sm, 2); sq += __shfl_xor_sync(0xffffffffu, sq, 2);
    float mu = sm * (1.f/128.f);
    float rs = rsqrtf(sq * (1.f/128.f) - mu*mu + 1e-5f);
    uint32_t* aw = (uint32_t*)s_A;
    #pragma unroll
    for (int j = 0; j < 16; ++j) {
        int c0 = q*32 + 2*j;
        float v0 = (x1[2*j]   - mu) * rs * w[c0]   + b[c0];
        float v1 = (x1[2*j+1] - mu) * rs * w[c0+1] + b[c0+1];
        aw[p*68 + q*16 + j] = bf2(v0, v1);
    }
    stage_wait0();
    __syncthreads();
    float acc[2][4][4] = {};
    mma_gemm16(s_A, 136, s_W, acc, warp, lane);
    int g = lane >> 2, tg = lane & 3;
    int rbase = (warp & 3) * 32 + g;
    int cbase = (warp >> 2) * 32;
    size_t pixb = (size_t)(bb*65536 + h*256 + w0);
    uint32_t* zw = (uint32_t*)g_z;
    #pragma unroll
    for (int mt = 0; mt < 2; ++mt)
        #pragma unroll
        for (int nt = 0; nt < 4; ++nt) {
            int r0 = rbase + mt*16;
            int c0 = cbase + nt*8 + 2*tg;
            zw[(pixb + r0)  *64 + (c0 >> 1)] = bf2(acc[mt][nt][0], acc[mt][nt][1]);
            zw[(pixb + r0+8)*64 + (c0 >> 1)] = bf2(acc[mt][nt][2], acc[mt][nt][3]);
        }
}

// ---------------- LeFF: 128 pixels per CTA, 512 threads, 2 CTAs/SM, no spills ----------------
__global__ void __launch_bounds__(512, 2) k_leff(const float* __restrict__ ldw_w,
                                                 const float* __restrict__ ldw_b,
                                                 const float* __restrict__ fc1_b,
                                                 const float* __restrict__ fc2_b,
                                                 float* __restrict__ out) {
    extern __shared__ __align__(16) char smem[];
    __nv_bfloat16* s_d = (__nv_bfloat16*)smem;                   // 128*136
    __nv_bfloat16* s_t = (__nv_bfloat16*)(smem + 34816);         // 128*136
    __nv_bfloat16* s_W = (__nv_bfloat16*)(smem + 69632);         // 128*136
    float* s_f = (float*)(smem + 34816);                         // aliases s_t + s_W
    int tid = threadIdx.x, warp = tid >> 5, lane = tid & 31, bid = blockIdx.x;
    int w0 = (bid & 1) * 128;
    int h  = (bid >> 1) & 255;
    int bb = bid >> 9;

    stage_async(g_wbf + 7*16384, s_W, tid);    // fc1[0]

    // 3x3 depthwise over g_z (bf16 channels-last), uint4-vectorized (8 channels/thread)
    {
        const uint4* zw4 = (const uint4*)g_z;
        #pragma unroll
        for (int it = 0; it < 4; ++it) {
            int idx = tid + it*512;              // 2048 uint4
            int p = idx >> 4, c16 = idx & 15;
            int c0 = c16*8;
            int xx0 = w0 + p;
            float acc[8];
            #pragma unroll
            for (int j = 0; j < 8; ++j) acc[j] = ldw_b[c0 + j];
            #pragma unroll
            for (int dy = 0; dy < 3; ++dy) {
                int yy = h + dy - 1;
                if (yy < 0 || yy > 255) continue;
                #pragma unroll
                for (int dx = 0; dx < 3; ++dx) {
                    int xx = xx0 + dx - 1;
                    if (xx < 0 || xx > 255) continue;
                    uint4 u = zw4[((size_t)(bb*65536 + yy*256 + xx))*16 + c16];
                    float2 f;
                    f = ubf2f(u.x); acc[0] += f.x*ldw_w[(c0  )*9 + dy*3 + dx];
                                    acc[1] += f.y*ldw_w[(c0+1)*9 + dy*3 + dx];
                    f = ubf2f(u.y); acc[2] += f.x*ldw_w[(c0+2)*9 + dy*3 + dx];
                                    acc[3] += f.y*ldw_w[(c0+3)*9 + dy*3 + dx];
                    f = ubf2f(u.z); acc[4] += f.x*ldw_w[(c0+4)*9 + dy*3 + dx];
                                    acc[5] += f.y*ldw_w[(c0+5)*9 + dy*3 + dx];
                    f = ubf2f(u.w); acc[6] += f.x*ldw_w[(c0+6)*9 + dy*3 + dx];
                                    acc[7] += f.y*ldw_w[(c0+7)*9 + dy*3 + dx];
                }
            }
            uint4 o;
            o.x = bf2(acc[0], acc[1]); o.y = bf2(acc[2], acc[3]);
            o.z = bf2(acc[4], acc[5]); o.w = bf2(acc[6], acc[7]);
            *(uint4*)((uint32_t*)s_d + p*68 + c16*4) = o;
        }
    }

    int g = lane >> 2, tg = lane & 3;
    int rbase = (warp & 3) * 32 + g;
    int cbase = (warp >> 2) * 32;
    float oacc[2][4][4] = {};
    for (int jc = 0; jc < 4; ++jc) {
        stage_wait0();
        __syncthreads();
        // fc1 in two 16-col halves (tacc = 16 regs -> no spills), gelu+store per half
        uint32_t* tw = (uint32_t*)s_t;
        #pragma unroll
        for (int half = 0; half < 2; ++half) {
            float tacc[2][2][4] = {};
            mma_gemm16_n2(s_d, 136, s_W, tacc, warp, lane, half);
            #pragma unroll
            for (int mt = 0; mt < 2; ++mt)
                #pragma unroll
                for (int nt = 0; nt < 2; ++nt) {
                    int r0 = rbase + mt*16;
                    int c0 = cbase + half*16 + nt*8 + 2*tg;
                    float b0 = fc1_b[jc*128 + c0], b1 = fc1_b[jc*128 + c0 + 1];
                    float v0 = gelu_f(tacc[mt][nt][0] + b0);
                    float v1 = gelu_f(tacc[mt][nt][1] + b1);
                    float v2 = gelu_f(tacc[mt][nt][2] + b0);
                    float v3 = gelu_f(tacc[mt][nt][3] + b1);
                    tw[ r0   *68 + (c0 >> 1)] = bf2(v0, v1);
                    tw[(r0+8)*68 + (c0 >> 1)] = bf2(v2, v3);
                }
        }
        __syncthreads();                        // s_W reads + s_t writes done
        stage_async(g_wbf + (11+jc)*16384, s_W, tid);   // fc2[jc]
        stage_wait0();
        __syncthreads();
        mma_gemm16(s_t, 136, s_W, oacc, warp, lane);
        __syncthreads();                        // fc2 weight + s_t reads done
        if (jc < 3) stage_async(g_wbf + (8+jc)*16384, s_W, tid);   // fc1[jc+1]
    }

    // epilogue: + fc2_b + residual x1 (fp32), stage fp32, transpose-write NCHW
    size_t pixb = (size_t)(bb*65536 + h*256 + w0);
    #pragma unroll
    for (int mt = 0; mt < 2; ++mt)
        #pragma unroll
        for (int nt = 0; nt < 4; ++nt) {
            int r0 = rbase + mt*16;
            int c0 = cbase + nt*8 + 2*tg;
            float b0 = fc2_b[c0], b1 = fc2_b[c0+1];
            float2 x0 = *(const float2*)&g_x1[(pixb + r0)  *128 + c0];
            float2 x1 = *(const float2*)&g_x1[(pixb + r0+8)*128 + c0];
            s_f[ r0   *129 + c0]     = oacc[mt][nt][0] + b0 + x0.x;
            s_f[ r0   *129 + c0 + 1] = oacc[mt][nt][1] + b1 + x0.y;
            s_f[(r0+8)*129 + c0]     = oacc[mt][nt][2] + b0 + x1.x;
            s_f[(r0+8)*129 + c0 + 1] = oacc[mt][nt][3] + b1 + x1.y;
        }
    __syncthreads();
    for (int idx = tid; idx < 16384; idx += 512) {
        int c = idx >> 7, p = idx & 127;
        out[((size_t)(bb*128 + c)*256 + h)*256 + w0 + p] = s_f[p*129 + c];
    }
}

// ---------------- launch ----------------
extern "C" void kernel_launch(void* const* d_in, const int* in_sizes, int n_in,
                              void* d_out, int out_size) {
    const float* x        = (const float*)d_in[0];
    const float* norm1_w  = (const float*)d_in[1];
    const float* norm1_b  = (const float*)d_in[2];
    const float* qkv_w    = (const float*)d_in[3];
    const float* qkv_b    = (const float*)d_in[4];
    const float* pos_bias = (const float*)d_in[5];
    const float* out_w    = (const float*)d_in[6];
    const float* out_b    = (const float*)d_in[7];
    const float* convp_w  = (const float*)d_in[8];
    const float* convp_b  = (const float*)d_in[9];
    const float* pw1_w    = (const float*)d_in[10];
    const float* pw1_b    = (const float*)d_in[11];
    const float* dw1_w    = (const float*)d_in[12];
    const float* dw1_b    = (const float*)d_in[13];
    const float* tok_w    = (const float*)d_in[14];
    const float* tok_b    = (const float*)d_in[15];
    const float* norm2_w  = (const float*)d_in[16];
    const float* norm2_b  = (const float*)d_in[17];
    const float* lpw_w    = (const float*)d_in[18];
    const float* ldw_w    = (const float*)d_in[19];
    const float* ldw_b    = (const float*)d_in[20];
    const float* fc1_w    = (const float*)d_in[21];
    const float* fc1_b    = (const float*)d_in[22];
    const float* fc2_w    = (const float*)d_in[23];
    const float* fc2_b    = (const float*)d_in[24];
    float* out = (float*)d_out;

    const int SM_REMSA = 133120 + 34816 + 34816;          // 202752
    const int SM_LN2Z  = 34816 + 34816;                   //  69632
    const int SM_LEFF  = 34816*3;                         // 104448
    cudaFuncSetAttribute(k_remsa, cudaFuncAttributeMaxDynamicSharedMemorySize, SM_REMSA);
    cudaFuncSetAttribute(k_ln2z,  cudaFuncAttributeMaxDynamicSharedMemorySize, SM_LN2Z);
    cudaFuncSetAttribute(k_leff,  cudaFuncAttributeMaxDynamicSharedMemorySize, SM_LEFF);

    k_prep <<<960,  256>>>(qkv_w, out_w, tok_w, lpw_w, fc1_w, fc2_w,
                           convp_w, convp_b, pw1_w, pw1_b);
    k_remsa<<<2048, 512, SM_REMSA>>>(x, norm1_w, norm1_b, qkv_b, pos_bias,
                                     out_b, tok_b, dw1_w, dw1_b);
    k_ln2z <<<2048, 512, SM_LN2Z>>>(x, norm2_w, norm2_b);
    k_leff <<<2048, 512, SM_LEFF>>>(ldw_w, ldw_b, fc1_b, fc2_b, out);
}